// round 1
// baseline (speedup 1.0000x reference)
#include <cuda_runtime.h>
#include <math.h>
#include <stdint.h>

#define BB   2
#define TT   2048
#define CC   2048
#define HH   32
#define KVHN 8
#define DD   64
#define GG   4

// Scratch (allocation-free rule: __device__ globals)
__device__ float g_q[(size_t)BB * TT * CC];            // 33.5 MB
__device__ float g_k[(size_t)BB * TT * KVHN * DD];     //  8.4 MB
__device__ float g_v[(size_t)BB * TT * KVHN * DD];     //  8.4 MB
__device__ float g_attn[(size_t)BB * TT * CC];         // 33.5 MB

// ---------------------------------------------------------------------------
// NT GEMM: C[M,N] = A[M,K] @ B[N,K]^T   (A, B row-major)
// 128x128 block, BK=16, 256 threads, 8x8 per thread.
// ---------------------------------------------------------------------------
template<int BM, int BN, int BK, int TM, int TN>
__global__ void gemm_nt(const float* __restrict__ A, const float* __restrict__ B,
                        float* __restrict__ C, int M, int N, int K)
{
    __shared__ float As[BK][BM + 4];
    __shared__ float Bs[BK][BN + 4];

    const int tid = threadIdx.x;               // 256
    const int tx  = tid % (BN / TN);           // 0..15
    const int ty  = tid / (BN / TN);           // 0..15
    const int bm  = blockIdx.y * BM;
    const int bn  = blockIdx.x * BN;

    float acc[TM][TN];
#pragma unroll
    for (int i = 0; i < TM; ++i)
#pragma unroll
        for (int j = 0; j < TN; ++j) acc[i][j] = 0.f;

    for (int k0 = 0; k0 < K; k0 += BK) {
        // Load A tile (BM x BK) transposed into As[k][m]
#pragma unroll
        for (int i = 0; i < (BM * BK) / (256 * 4); ++i) {
            int lin = tid + i * 256;           // float4 index
            int row = lin / (BK / 4);
            int c4  = lin % (BK / 4);
            float4 v = *(const float4*)(A + (size_t)(bm + row) * K + k0 + c4 * 4);
            As[c4 * 4 + 0][row] = v.x;
            As[c4 * 4 + 1][row] = v.y;
            As[c4 * 4 + 2][row] = v.z;
            As[c4 * 4 + 3][row] = v.w;
        }
        // Load B tile (BN x BK) transposed into Bs[k][n]
#pragma unroll
        for (int i = 0; i < (BN * BK) / (256 * 4); ++i) {
            int lin = tid + i * 256;
            int row = lin / (BK / 4);
            int c4  = lin % (BK / 4);
            float4 v = *(const float4*)(B + (size_t)(bn + row) * K + k0 + c4 * 4);
            Bs[c4 * 4 + 0][row] = v.x;
            Bs[c4 * 4 + 1][row] = v.y;
            Bs[c4 * 4 + 2][row] = v.z;
            Bs[c4 * 4 + 3][row] = v.w;
        }
        __syncthreads();

#pragma unroll
        for (int k = 0; k < BK; ++k) {
            float ar[TM], br[TN];
#pragma unroll
            for (int i = 0; i < TM; ++i) ar[i] = As[k][ty * TM + i];
#pragma unroll
            for (int j = 0; j < TN; ++j) br[j] = Bs[k][tx * TN + j];
#pragma unroll
            for (int i = 0; i < TM; ++i)
#pragma unroll
                for (int j = 0; j < TN; ++j)
                    acc[i][j] += ar[i] * br[j];
        }
        __syncthreads();
    }

#pragma unroll
    for (int i = 0; i < TM; ++i) {
        float* crow = C + (size_t)(bm + ty * TM + i) * N + bn + tx * TN;
#pragma unroll
        for (int j4 = 0; j4 < TN / 4; ++j4) {
            float4 v = make_float4(acc[i][j4 * 4 + 0], acc[i][j4 * 4 + 1],
                                   acc[i][j4 * 4 + 2], acc[i][j4 * 4 + 3]);
            *(float4*)(crow + j4 * 4) = v;
        }
    }
}

// ---------------------------------------------------------------------------
// RoPE in place on q (B*T x H*D) and k (B*T x KVH*D).
// Element pair (d, d+32) per thread.
// ---------------------------------------------------------------------------
__global__ void rope_kernel(float* __restrict__ q, float* __restrict__ k,
                            const float* __restrict__ cosb, const float* __restrict__ sinb)
{
    const int halfs_q = BB * TT * HH * (DD / 2);
    const int halfs_k = BB * TT * KVHN * (DD / 2);
    int idx = blockIdx.x * blockDim.x + threadIdx.x;
    if (idx < halfs_q) {
        int d   = idx & 31;
        int h   = (idx >> 5) & (HH - 1);
        int row = idx >> 10;               // 5 bits d + 5 bits h
        int t   = row & (TT - 1);
        float* p = q + (size_t)row * CC + h * DD;
        float c1 = cosb[t * DD + d],      s1 = sinb[t * DD + d];
        float c2 = cosb[t * DD + d + 32], s2 = sinb[t * DD + d + 32];
        float a = p[d], b2 = p[d + 32];
        p[d]      = a * c1 - b2 * s1;
        p[d + 32] = b2 * c2 + a * s2;
    } else if (idx < halfs_q + halfs_k) {
        int j   = idx - halfs_q;
        int d   = j & 31;
        int h   = (j >> 5) & (KVHN - 1);
        int row = j >> 8;                  // 5 bits d + 3 bits h
        int t   = row & (TT - 1);
        float* p = k + (size_t)row * (KVHN * DD) + h * DD;
        float c1 = cosb[t * DD + d],      s1 = sinb[t * DD + d];
        float c2 = cosb[t * DD + d + 32], s2 = sinb[t * DD + d + 32];
        float a = p[d], b2 = p[d + 32];
        p[d]      = a * c1 - b2 * s1;
        p[d + 32] = b2 * c2 + a * s2;
    }
}

// ---------------------------------------------------------------------------
// Fused causal flash attention, fp32, GQA (G=4), D=64.
// Block: one (b, h, 64-query tile). 256 threads; thread = (ty 0..15, tx 0..15).
// Thread owns rows ty*4..+3.  S cols strided: tx + 16*j.  O cols: tx*4..+3.
// KP buffer holds K, then is reused for P (exp scores).
// ---------------------------------------------------------------------------
#define FPAD 68   // floats per row = 17 float4 (odd stride -> conflict-friendly)

__global__ void flash_kernel(const float* __restrict__ Qg, const float* __restrict__ Kg,
                             const float* __restrict__ Vg, float* __restrict__ Og)
{
    extern __shared__ float sm[];
    float* Qs = sm;                        // [64][68]
    float* KP = sm + 64 * FPAD;            // [64][68]  K tile, reused as P
    float* Vs = sm + 2 * 64 * FPAD;        // [64][64]

    const int qt  = blockIdx.x;
    const int h   = blockIdx.y;
    const int b   = blockIdx.z;
    const int kvh = h >> 2;                // G = 4
    const int tid = threadIdx.x;
    const int tx  = tid & 15;
    const int ty  = tid >> 4;
    const int rr  = ty * 4;

    // Load Q tile scaled by 1/sqrt(D)
    const float* Qb = Qg + ((size_t)(b * TT + qt * 64)) * CC + h * DD;
#pragma unroll
    for (int i = 0; i < 4; ++i) {
        int lin = tid + i * 256;           // 1024 float4s
        int row = lin >> 4, c4 = lin & 15;
        float4 v = *(const float4*)(Qb + (size_t)row * CC + c4 * 4);
        float4 w = make_float4(v.x * 0.125f, v.y * 0.125f, v.z * 0.125f, v.w * 0.125f);
        *(float4*)(Qs + row * FPAD + c4 * 4) = w;
    }

    float o[4][4];
    float m_i[4], l_i[4];
#pragma unroll
    for (int i = 0; i < 4; ++i) {
        m_i[i] = -1e30f; l_i[i] = 0.f;
#pragma unroll
        for (int j = 0; j < 4; ++j) o[i][j] = 0.f;
    }

    for (int kt = 0; kt <= qt; ++kt) {
        __syncthreads();   // prior PV reads done (and Q load on first iter ordering below)
        const float* Kb = Kg + ((size_t)(b * TT + kt * 64)) * (KVHN * DD) + kvh * DD;
        const float* Vb = Vg + ((size_t)(b * TT + kt * 64)) * (KVHN * DD) + kvh * DD;
#pragma unroll
        for (int i = 0; i < 4; ++i) {
            int lin = tid + i * 256;
            int row = lin >> 4, c4 = lin & 15;
            float4 kv = *(const float4*)(Kb + (size_t)row * (KVHN * DD) + c4 * 4);
            *(float4*)(KP + row * FPAD + c4 * 4) = kv;
            float4 vv = *(const float4*)(Vb + (size_t)row * (KVHN * DD) + c4 * 4);
            *(float4*)(Vs + row * 64 + c4 * 4) = vv;
        }
        __syncthreads();

        // S = Q K^T  (4 rows x 4 strided cols per thread)
        float s[4][4];
#pragma unroll
        for (int i = 0; i < 4; ++i)
#pragma unroll
            for (int j = 0; j < 4; ++j) s[i][j] = 0.f;

#pragma unroll
        for (int d4 = 0; d4 < 16; ++d4) {
            float4 qv[4], kv[4];
#pragma unroll
            for (int i = 0; i < 4; ++i) qv[i] = *(const float4*)(Qs + (rr + i) * FPAD + d4 * 4);
#pragma unroll
            for (int j = 0; j < 4; ++j) kv[j] = *(const float4*)(KP + (tx + 16 * j) * FPAD + d4 * 4);
#pragma unroll
            for (int i = 0; i < 4; ++i)
#pragma unroll
                for (int j = 0; j < 4; ++j)
                    s[i][j] += qv[i].x * kv[j].x + qv[i].y * kv[j].y
                             + qv[i].z * kv[j].z + qv[i].w * kv[j].w;
        }

        if (kt == qt) {
#pragma unroll
            for (int i = 0; i < 4; ++i)
#pragma unroll
                for (int j = 0; j < 4; ++j)
                    if (tx + 16 * j > rr + i) s[i][j] = -1e30f;
        }

        __syncthreads();   // all KP (K) reads complete before overwrite with P

        // Online softmax (row stats shared by the 16 tx threads via shfl)
#pragma unroll
        for (int i = 0; i < 4; ++i) {
            float mx = fmaxf(fmaxf(s[i][0], s[i][1]), fmaxf(s[i][2], s[i][3]));
#pragma unroll
            for (int off = 8; off > 0; off >>= 1)
                mx = fmaxf(mx, __shfl_xor_sync(0xffffffffu, mx, off));
            float mnew = fmaxf(m_i[i], mx);
            float corr = __expf(m_i[i] - mnew);
            float ssum = 0.f;
#pragma unroll
            for (int j = 0; j < 4; ++j) { s[i][j] = __expf(s[i][j] - mnew); ssum += s[i][j]; }
#pragma unroll
            for (int off = 8; off > 0; off >>= 1)
                ssum += __shfl_xor_sync(0xffffffffu, ssum, off);
            l_i[i] = l_i[i] * corr + ssum;
            m_i[i] = mnew;
#pragma unroll
            for (int j = 0; j < 4; ++j) o[i][j] *= corr;
#pragma unroll
            for (int j = 0; j < 4; ++j) KP[(rr + i) * FPAD + tx + 16 * j] = s[i][j];
        }
        __syncthreads();

        // O += P @ V  (output cols tx*4..+3)
#pragma unroll
        for (int c4 = 0; c4 < 16; ++c4) {
            float4 pv[4];
#pragma unroll
            for (int i = 0; i < 4; ++i) pv[i] = *(const float4*)(KP + (rr + i) * FPAD + c4 * 4);
            float4 vv[4];
#pragma unroll
            for (int kk = 0; kk < 4; ++kk) vv[kk] = *(const float4*)(Vs + (c4 * 4 + kk) * 64 + tx * 4);
#pragma unroll
            for (int i = 0; i < 4; ++i) {
                o[i][0] += pv[i].x * vv[0].x + pv[i].y * vv[1].x + pv[i].z * vv[2].x + pv[i].w * vv[3].x;
                o[i][1] += pv[i].x * vv[0].y + pv[i].y * vv[1].y + pv[i].z * vv[2].y + pv[i].w * vv[3].y;
                o[i][2] += pv[i].x * vv[0].z + pv[i].y * vv[1].z + pv[i].z * vv[2].z + pv[i].w * vv[3].z;
                o[i][3] += pv[i].x * vv[0].w + pv[i].y * vv[1].w + pv[i].z * vv[2].w + pv[i].w * vv[3].w;
            }
        }
    }

    // Epilogue: normalize and store (layout already (b, t, h*D+d))
    float* Ob = Og + ((size_t)(b * TT + qt * 64)) * CC + h * DD;
#pragma unroll
    for (int i = 0; i < 4; ++i) {
        float inv = 1.0f / l_i[i];
        float4 v = make_float4(o[i][0] * inv, o[i][1] * inv, o[i][2] * inv, o[i][3] * inv);
        *(float4*)(Ob + (size_t)(rr + i) * CC + tx * 4) = v;
    }
}

// ---------------------------------------------------------------------------
extern "C" void kernel_launch(void* const* d_in, const int* in_sizes, int n_in,
                              void* d_out, int out_size)
{
    const float* x    = (const float*)d_in[0];
    const float* Wq   = (const float*)d_in[1];
    const float* Wk   = (const float*)d_in[2];
    const float* Wv   = (const float*)d_in[3];
    const float* Wo   = (const float*)d_in[4];
    const float* cosb = (const float*)d_in[5];
    const float* sinb = (const float*)d_in[6];
    float* out = (float*)d_out;

    float *q, *k, *v, *attn;
    cudaGetSymbolAddress((void**)&q,    g_q);
    cudaGetSymbolAddress((void**)&k,    g_k);
    cudaGetSymbolAddress((void**)&v,    g_v);
    cudaGetSymbolAddress((void**)&attn, g_attn);

    const int M = BB * TT;   // 4096

    // Projections
    gemm_nt<128, 128, 16, 8, 8><<<dim3(CC / 128, M / 128), 256>>>(x, Wq, q, M, CC, CC);
    gemm_nt<128, 128, 16, 8, 8><<<dim3((KVHN * DD) / 128, M / 128), 256>>>(x, Wk, k, M, KVHN * DD, CC);
    gemm_nt<128, 128, 16, 8, 8><<<dim3((KVHN * DD) / 128, M / 128), 256>>>(x, Wv, v, M, KVHN * DD, CC);

    // RoPE (in place on q, k)
    {
        int total = BB * TT * (HH + KVHN) * (DD / 2);
        rope_kernel<<<(total + 255) / 256, 256>>>(q, k, cosb, sinb);
    }

    // Flash attention
    {
        int smem = (2 * 64 * FPAD + 64 * 64) * (int)sizeof(float);  // 51200 B
        cudaFuncSetAttribute(flash_kernel, cudaFuncAttributeMaxDynamicSharedMemorySize, smem);
        flash_kernel<<<dim3(TT / 64, HH, BB), 256, smem>>>(q, k, v, attn);
    }

    // Output projection
    gemm_nt<128, 128, 16, 8, 8><<<dim3(CC / 128, M / 128), 256>>>(attn, Wo, out, M, CC, CC);
}

// round 3
// speedup vs baseline: 1.9126x; 1.9126x over previous
#include <cuda_runtime.h>
#include <math.h>
#include <stdint.h>

#define BB   2
#define TT   2048
#define CC   2048
#define HH   32
#define KVHN 8
#define DD   64
#define KDIM 2048

// GEMM tile config
#define GBM  128
#define GBN  128
#define GBK  32
#define NCHUNK (KDIM / GBK)       // 64
#define SSTRIDE 36                // padded word stride (conflict-free, 16B aligned)
#define TILE_W (128 * SSTRIDE)    // words per tile
#define GEMM_SMEM (4 * TILE_W * 4)  // As0,Bs0,As1,Bs1 = 73728 B

// Scratch (allocation-free rule: __device__ globals)
__device__ float g_q[(size_t)BB * TT * CC];
__device__ float g_k[(size_t)BB * TT * KVHN * DD];
__device__ float g_v[(size_t)BB * TT * KVHN * DD];
__device__ float g_attn[(size_t)BB * TT * CC];

// ---------------------------------------------------------------------------
// helpers
// ---------------------------------------------------------------------------
__device__ __forceinline__ uint32_t smem_u32(const void* p) {
    uint32_t r;
    asm("{ .reg .u64 t; cvta.to.shared.u64 t, %1; cvt.u32.u64 %0, t; }" : "=r"(r) : "l"(p));
    return r;
}
__device__ __forceinline__ uint32_t f2tf(float f) {
    uint32_t r;
    asm("cvt.rna.tf32.f32 %0, %1;" : "=r"(r) : "f"(f));
    return r;
}
#define CP16(dst, src) \
    asm volatile("cp.async.cg.shared.global [%0], [%1], 16;" :: "r"(dst), "l"(src))
#define CP_COMMIT() asm volatile("cp.async.commit_group;" ::: "memory")
#define CP_WAIT1()  asm volatile("cp.async.wait_group 1;" ::: "memory")
#define CP_WAIT0()  asm volatile("cp.async.wait_group 0;" ::: "memory")

__device__ __forceinline__ void mma_tf32(float* d, const uint32_t* a, const uint32_t* b) {
    asm volatile(
        "mma.sync.aligned.m16n8k8.row.col.f32.tf32.tf32.f32 "
        "{%0,%1,%2,%3}, {%4,%5,%6,%7}, {%8,%9}, {%0,%1,%2,%3};"
        : "+f"(d[0]), "+f"(d[1]), "+f"(d[2]), "+f"(d[3])
        : "r"(a[0]), "r"(a[1]), "r"(a[2]), "r"(a[3]), "r"(b[0]), "r"(b[1]));
}

// ---------------------------------------------------------------------------
// mma.sync tf32 NT GEMM tile: C[128,128] = A[128,K] @ W[128,K]^T (fp32 acc)
// 256 threads (8 warps 2x4), warp tile 64x32, cp.async double-buffered.
// ---------------------------------------------------------------------------
__device__ __forceinline__ void gemm_mma_tile(const float* __restrict__ A,
                                              const float* __restrict__ W,
                                              float* __restrict__ Cp, int ldc)
{
    extern __shared__ float smf[];
    const uint32_t sbase = smem_u32(smf);

    const int tid  = threadIdx.x;
    const int wid  = tid >> 5, lane = tid & 31;
    const int wm   = wid & 1,  wn   = wid >> 1;     // 2 x 4 warp grid
    const int g    = lane >> 2, tig = lane & 3;

    float acc[4][4][4];
#pragma unroll
    for (int i = 0; i < 4; ++i)
#pragma unroll
        for (int j = 0; j < 4; ++j)
#pragma unroll
            for (int e = 0; e < 4; ++e) acc[i][j][e] = 0.f;

    // async loader: A tile (128x32) + W tile (128x32), each 1024 float4
    auto load_chunk = [&](int c, int buf) {
        const float* Ab = A + c * GBK;
        const float* Wb = W + c * GBK;
        const uint32_t da = sbase + (buf ? 2u * TILE_W * 4u : 0u);
        const uint32_t db = da + TILE_W * 4u;
#pragma unroll
        for (int i = 0; i < 4; ++i) {
            int lin = tid + i * 256;
            int r = lin >> 3, c4 = lin & 7;
            CP16(da + (uint32_t)(r * SSTRIDE + c4 * 4) * 4u,
                 Ab + (size_t)r * KDIM + c4 * 4);
        }
#pragma unroll
        for (int i = 0; i < 4; ++i) {
            int lin = tid + i * 256;
            int r = lin >> 3, c4 = lin & 7;
            CP16(db + (uint32_t)(r * SSTRIDE + c4 * 4) * 4u,
                 Wb + (size_t)r * KDIM + c4 * 4);
        }
        CP_COMMIT();
    };

    auto compute = [&](int buf) {
        const float* As = smf + buf * 2 * TILE_W;
        const float* Bs = As + TILE_W;
#pragma unroll
        for (int ks = 0; ks < 4; ++ks) {
            uint32_t a[4][4], b[4][2];
            const int kc = ks * 8 + tig;
#pragma unroll
            for (int mf = 0; mf < 4; ++mf) {
                const int row = wm * 64 + mf * 16 + g;
                a[mf][0] = f2tf(As[row * SSTRIDE + kc]);
                a[mf][1] = f2tf(As[(row + 8) * SSTRIDE + kc]);
                a[mf][2] = f2tf(As[row * SSTRIDE + kc + 4]);
                a[mf][3] = f2tf(As[(row + 8) * SSTRIDE + kc + 4]);
            }
#pragma unroll
            for (int nf = 0; nf < 4; ++nf) {
                const int col = wn * 32 + nf * 8 + g;
                b[nf][0] = f2tf(Bs[col * SSTRIDE + kc]);
                b[nf][1] = f2tf(Bs[col * SSTRIDE + kc + 4]);
            }
#pragma unroll
            for (int mf = 0; mf < 4; ++mf)
#pragma unroll
                for (int nf = 0; nf < 4; ++nf)
                    mma_tf32(acc[mf][nf], a[mf], b[nf]);
        }
    };

    load_chunk(0, 0);
    int buf = 0;
    for (int c = 0; c < NCHUNK; ++c) {
        if (c + 1 < NCHUNK) { load_chunk(c + 1, buf ^ 1); CP_WAIT1(); }
        else                { CP_WAIT0(); }
        __syncthreads();
        compute(buf);
        __syncthreads();
        buf ^= 1;
    }

    // epilogue
#pragma unroll
    for (int mf = 0; mf < 4; ++mf) {
        const int r0 = wm * 64 + mf * 16 + g;
#pragma unroll
        for (int nf = 0; nf < 4; ++nf) {
            const int c0 = wn * 32 + nf * 8 + tig * 2;
            *(float2*)(Cp + (size_t)r0 * ldc + c0)       = make_float2(acc[mf][nf][0], acc[mf][nf][1]);
            *(float2*)(Cp + (size_t)(r0 + 8) * ldc + c0) = make_float2(acc[mf][nf][2], acc[mf][nf][3]);
        }
    }
}

// QKV fused: blockIdx.x in [0,24): 0-15 -> Q, 16-19 -> K, 20-23 -> V
__global__ void __launch_bounds__(256, 2)
gemm_qkv(const float* __restrict__ x,
         const float* __restrict__ Wq, const float* __restrict__ Wk, const float* __restrict__ Wv,
         float* __restrict__ q, float* __restrict__ k, float* __restrict__ v)
{
    const int nt = blockIdx.x;
    const int bm = blockIdx.y * GBM;
    const float* W; float* C; int ldc, cn;
    if (nt < 16)      { W = Wq; C = q; ldc = CC;        cn = nt * GBN; }
    else if (nt < 20) { W = Wk; C = k; ldc = KVHN * DD; cn = (nt - 16) * GBN; }
    else              { W = Wv; C = v; ldc = KVHN * DD; cn = (nt - 20) * GBN; }
    gemm_mma_tile(x + (size_t)bm * KDIM, W + (size_t)cn * KDIM,
                  C + (size_t)bm * ldc + cn, ldc);
}

__global__ void __launch_bounds__(256, 2)
gemm_oproj(const float* __restrict__ A, const float* __restrict__ W, float* __restrict__ C)
{
    const int bm = blockIdx.y * GBM;
    const int bn = blockIdx.x * GBN;
    gemm_mma_tile(A + (size_t)bm * KDIM, W + (size_t)bn * KDIM,
                  C + (size_t)bm * CC + bn, CC);
}

// ---------------------------------------------------------------------------
// RoPE in place on q (B*T x H*D) and k (B*T x KVH*D).
// ---------------------------------------------------------------------------
__global__ void rope_kernel(float* __restrict__ q, float* __restrict__ k,
                            const float* __restrict__ cosb, const float* __restrict__ sinb)
{
    const int halfs_q = BB * TT * HH * (DD / 2);
    const int halfs_k = BB * TT * KVHN * (DD / 2);
    int idx = blockIdx.x * blockDim.x + threadIdx.x;
    if (idx < halfs_q) {
        int d   = idx & 31;
        int h   = (idx >> 5) & (HH - 1);
        int row = idx >> 10;
        int t   = row & (TT - 1);
        float* p = q + (size_t)row * CC + h * DD;
        float c1 = cosb[t * DD + d],      s1 = sinb[t * DD + d];
        float c2 = cosb[t * DD + d + 32], s2 = sinb[t * DD + d + 32];
        float a = p[d], b2 = p[d + 32];
        p[d]      = a * c1 - b2 * s1;
        p[d + 32] = b2 * c2 + a * s2;
    } else if (idx < halfs_q + halfs_k) {
        int j   = idx - halfs_q;
        int d   = j & 31;
        int h   = (j >> 5) & (KVHN - 1);
        int row = j >> 8;
        int t   = row & (TT - 1);
        float* p = k + (size_t)row * (KVHN * DD) + h * DD;
        float c1 = cosb[t * DD + d],      s1 = sinb[t * DD + d];
        float c2 = cosb[t * DD + d + 32], s2 = sinb[t * DD + d + 32];
        float a = p[d], b2 = p[d + 32];
        p[d]      = a * c1 - b2 * s1;
        p[d + 32] = b2 * c2 + a * s2;
    }
}

// ---------------------------------------------------------------------------
// Fused causal flash attention, fp32, GQA (G=4), D=64. (unchanged; proven)
// ---------------------------------------------------------------------------
#define FPAD 68

__global__ void flash_kernel(const float* __restrict__ Qg, const float* __restrict__ Kg,
                             const float* __restrict__ Vg, float* __restrict__ Og)
{
    extern __shared__ float sm[];
    float* Qs = sm;
    float* KP = sm + 64 * FPAD;
    float* Vs = sm + 2 * 64 * FPAD;

    const int qt  = blockIdx.x;
    const int h   = blockIdx.y;
    const int b   = blockIdx.z;
    const int kvh = h >> 2;
    const int tid = threadIdx.x;
    const int tx  = tid & 15;
    const int ty  = tid >> 4;
    const int rr  = ty * 4;

    const float* Qb = Qg + ((size_t)(b * TT + qt * 64)) * CC + h * DD;
#pragma unroll
    for (int i = 0; i < 4; ++i) {
        int lin = tid + i * 256;
        int row = lin >> 4, c4 = lin & 15;
        float4 v = *(const float4*)(Qb + (size_t)row * CC + c4 * 4);
        float4 w = make_float4(v.x * 0.125f, v.y * 0.125f, v.z * 0.125f, v.w * 0.125f);
        *(float4*)(Qs + row * FPAD + c4 * 4) = w;
    }

    float o[4][4];
    float m_i[4], l_i[4];
#pragma unroll
    for (int i = 0; i < 4; ++i) {
        m_i[i] = -1e30f; l_i[i] = 0.f;
#pragma unroll
        for (int j = 0; j < 4; ++j) o[i][j] = 0.f;
    }

    for (int kt = 0; kt <= qt; ++kt) {
        __syncthreads();
        const float* Kb = Kg + ((size_t)(b * TT + kt * 64)) * (KVHN * DD) + kvh * DD;
        const float* Vb = Vg + ((size_t)(b * TT + kt * 64)) * (KVHN * DD) + kvh * DD;
#pragma unroll
        for (int i = 0; i < 4; ++i) {
            int lin = tid + i * 256;
            int row = lin >> 4, c4 = lin & 15;
            float4 kv = *(const float4*)(Kb + (size_t)row * (KVHN * DD) + c4 * 4);
            *(float4*)(KP + row * FPAD + c4 * 4) = kv;
            float4 vv = *(const float4*)(Vb + (size_t)row * (KVHN * DD) + c4 * 4);
            *(float4*)(Vs + row * 64 + c4 * 4) = vv;
        }
        __syncthreads();

        float s[4][4];
#pragma unroll
        for (int i = 0; i < 4; ++i)
#pragma unroll
            for (int j = 0; j < 4; ++j) s[i][j] = 0.f;

#pragma unroll
        for (int d4 = 0; d4 < 16; ++d4) {
            float4 qv[4], kv[4];
#pragma unroll
            for (int i = 0; i < 4; ++i) qv[i] = *(const float4*)(Qs + (rr + i) * FPAD + d4 * 4);
#pragma unroll
            for (int j = 0; j < 4; ++j) kv[j] = *(const float4*)(KP + (tx + 16 * j) * FPAD + d4 * 4);
#pragma unroll
            for (int i = 0; i < 4; ++i)
#pragma unroll
                for (int j = 0; j < 4; ++j)
                    s[i][j] += qv[i].x * kv[j].x + qv[i].y * kv[j].y
                             + qv[i].z * kv[j].z + qv[i].w * kv[j].w;
        }

        if (kt == qt) {
#pragma unroll
            for (int i = 0; i < 4; ++i)
#pragma unroll
                for (int j = 0; j < 4; ++j)
                    if (tx + 16 * j > rr + i) s[i][j] = -1e30f;
        }

        __syncthreads();

#pragma unroll
        for (int i = 0; i < 4; ++i) {
            float mx = fmaxf(fmaxf(s[i][0], s[i][1]), fmaxf(s[i][2], s[i][3]));
#pragma unroll
            for (int off = 8; off > 0; off >>= 1)
                mx = fmaxf(mx, __shfl_xor_sync(0xffffffffu, mx, off));
            float mnew = fmaxf(m_i[i], mx);
            float corr = __expf(m_i[i] - mnew);
            float ssum = 0.f;
#pragma unroll
            for (int j = 0; j < 4; ++j) { s[i][j] = __expf(s[i][j] - mnew); ssum += s[i][j]; }
#pragma unroll
            for (int off = 8; off > 0; off >>= 1)
                ssum += __shfl_xor_sync(0xffffffffu, ssum, off);
            l_i[i] = l_i[i] * corr + ssum;
            m_i[i] = mnew;
#pragma unroll
            for (int j = 0; j < 4; ++j) o[i][j] *= corr;
#pragma unroll
            for (int j = 0; j < 4; ++j) KP[(rr + i) * FPAD + tx + 16 * j] = s[i][j];
        }
        __syncthreads();

#pragma unroll
        for (int c4 = 0; c4 < 16; ++c4) {
            float4 pv[4];
#pragma unroll
            for (int i = 0; i < 4; ++i) pv[i] = *(const float4*)(KP + (rr + i) * FPAD + c4 * 4);
            float4 vv[4];
#pragma unroll
            for (int kk = 0; kk < 4; ++kk) vv[kk] = *(const float4*)(Vs + (c4 * 4 + kk) * 64 + tx * 4);
#pragma unroll
            for (int i = 0; i < 4; ++i) {
                o[i][0] += pv[i].x * vv[0].x + pv[i].y * vv[1].x + pv[i].z * vv[2].x + pv[i].w * vv[3].x;
                o[i][1] += pv[i].x * vv[0].y + pv[i].y * vv[1].y + pv[i].z * vv[2].y + pv[i].w * vv[3].y;
                o[i][2] += pv[i].x * vv[0].z + pv[i].y * vv[1].z + pv[i].z * vv[2].z + pv[i].w * vv[3].z;
                o[i][3] += pv[i].x * vv[0].w + pv[i].y * vv[1].w + pv[i].z * vv[2].w + pv[i].w * vv[3].w;
            }
        }
    }

    float* Ob = Og + ((size_t)(b * TT + qt * 64)) * CC + h * DD;
#pragma unroll
    for (int i = 0; i < 4; ++i) {
        float inv = 1.0f / l_i[i];
        float4 v = make_float4(o[i][0] * inv, o[i][1] * inv, o[i][2] * inv, o[i][3] * inv);
        *(float4*)(Ob + (size_t)(rr + i) * CC + tx * 4) = v;
    }
}

// ---------------------------------------------------------------------------
extern "C" void kernel_launch(void* const* d_in, const int* in_sizes, int n_in,
                              void* d_out, int out_size)
{
    const float* x    = (const float*)d_in[0];
    const float* Wq   = (const float*)d_in[1];
    const float* Wk   = (const float*)d_in[2];
    const float* Wv   = (const float*)d_in[3];
    const float* Wo   = (const float*)d_in[4];
    const float* cosb = (const float*)d_in[5];
    const float* sinb = (const float*)d_in[6];
    float* out = (float*)d_out;

    float *q, *k, *v, *attn;
    cudaGetSymbolAddress((void**)&q,    g_q);
    cudaGetSymbolAddress((void**)&k,    g_k);
    cudaGetSymbolAddress((void**)&v,    g_v);
    cudaGetSymbolAddress((void**)&attn, g_attn);

    cudaFuncSetAttribute(gemm_qkv,   cudaFuncAttributeMaxDynamicSharedMemorySize, GEMM_SMEM);
    cudaFuncSetAttribute(gemm_oproj, cudaFuncAttributeMaxDynamicSharedMemorySize, GEMM_SMEM);

    // QKV projections (mma.sync tf32): 24 n-tiles x 32 m-tiles
    gemm_qkv<<<dim3(24, 32), 256, GEMM_SMEM>>>(x, Wq, Wk, Wv, q, k, v);

    // RoPE (in place on q, k)
    {
        int total = BB * TT * (HH + KVHN) * (DD / 2);
        rope_kernel<<<(total + 255) / 256, 256>>>(q, k, cosb, sinb);
    }

    // Flash attention (fp32)
    {
        int smem = (2 * 64 * FPAD + 64 * 64) * (int)sizeof(float);
        cudaFuncSetAttribute(flash_kernel, cudaFuncAttributeMaxDynamicSharedMemorySize, smem);
        flash_kernel<<<dim3(TT / 64, HH, BB), 256, smem>>>(q, k, v, attn);
    }

    // Output projection (mma.sync tf32): 16 n-tiles x 32 m-tiles
    gemm_oproj<<<dim3(16, 32), 256, GEMM_SMEM>>>(attn, Wo, out);
}

// round 5
// speedup vs baseline: 3.0422x; 1.5906x over previous
#include <cuda_runtime.h>
#include <math.h>
#include <stdint.h>

#define BB   2
#define TT   2048
#define CC   2048
#define HH   32
#define KVHN 8
#define DD   64
#define KDIM 2048

// GEMM tile config
#define GBM  128
#define GBN  128
#define GBK  32
#define NCHUNK (KDIM / GBK)       // 64
#define SSTRIDE 36
#define TILE_W (128 * SSTRIDE)
#define GEMM_SMEM (4 * TILE_W * 4)  // 73728 B

// Scratch (allocation-free rule: __device__ globals)
__device__ float g_q[(size_t)BB * TT * CC];
__device__ float g_k[(size_t)BB * TT * KVHN * DD];
__device__ float g_v[(size_t)BB * TT * KVHN * DD];
__device__ float g_attn[(size_t)BB * TT * CC];

// ---------------------------------------------------------------------------
// helpers
// ---------------------------------------------------------------------------
__device__ __forceinline__ uint32_t smem_u32(const void* p) {
    uint32_t r;
    asm("{ .reg .u64 t; cvta.to.shared.u64 t, %1; cvt.u32.u64 %0, t; }" : "=r"(r) : "l"(p));
    return r;
}
__device__ __forceinline__ uint32_t f2tf(float f) {
    uint32_t r;
    asm("cvt.rna.tf32.f32 %0, %1;" : "=r"(r) : "f"(f));
    return r;
}
#define CP16(dst, src) \
    asm volatile("cp.async.cg.shared.global [%0], [%1], 16;" :: "r"(dst), "l"(src))
#define CP_COMMIT() asm volatile("cp.async.commit_group;" ::: "memory")
#define CP_WAIT1()  asm volatile("cp.async.wait_group 1;" ::: "memory")
#define CP_WAIT0()  asm volatile("cp.async.wait_group 0;" ::: "memory")

__device__ __forceinline__ void mma_tf32(float* d, const uint32_t* a, const uint32_t* b) {
    asm volatile(
        "mma.sync.aligned.m16n8k8.row.col.f32.tf32.tf32.f32 "
        "{%0,%1,%2,%3}, {%4,%5,%6,%7}, {%8,%9}, {%0,%1,%2,%3};"
        : "+f"(d[0]), "+f"(d[1]), "+f"(d[2]), "+f"(d[3])
        : "r"(a[0]), "r"(a[1]), "r"(a[2]), "r"(a[3]), "r"(b[0]), "r"(b[1]));
}

// ---------------------------------------------------------------------------
// mma.sync tf32 NT GEMM tile: C[128,128] = A[128,K] @ W[128,K]^T (fp32 acc)
// ---------------------------------------------------------------------------
__device__ __forceinline__ void gemm_mma_tile(const float* __restrict__ A,
                                              const float* __restrict__ W,
                                              float* __restrict__ Cp, int ldc)
{
    extern __shared__ float smf[];
    const uint32_t sbase = smem_u32(smf);

    const int tid  = threadIdx.x;
    const int wid  = tid >> 5, lane = tid & 31;
    const int wm   = wid & 1,  wn   = wid >> 1;
    const int g    = lane >> 2, tig = lane & 3;

    float acc[4][4][4];
#pragma unroll
    for (int i = 0; i < 4; ++i)
#pragma unroll
        for (int j = 0; j < 4; ++j)
#pragma unroll
            for (int e = 0; e < 4; ++e) acc[i][j][e] = 0.f;

    auto load_chunk = [&](int c, int buf) {
        const float* Ab = A + c * GBK;
        const float* Wb = W + c * GBK;
        const uint32_t da = sbase + (buf ? 2u * TILE_W * 4u : 0u);
        const uint32_t db = da + TILE_W * 4u;
#pragma unroll
        for (int i = 0; i < 4; ++i) {
            int lin = tid + i * 256;
            int r = lin >> 3, c4 = lin & 7;
            CP16(da + (uint32_t)(r * SSTRIDE + c4 * 4) * 4u,
                 Ab + (size_t)r * KDIM + c4 * 4);
        }
#pragma unroll
        for (int i = 0; i < 4; ++i) {
            int lin = tid + i * 256;
            int r = lin >> 3, c4 = lin & 7;
            CP16(db + (uint32_t)(r * SSTRIDE + c4 * 4) * 4u,
                 Wb + (size_t)r * KDIM + c4 * 4);
        }
        CP_COMMIT();
    };

    auto compute = [&](int buf) {
        const float* As = smf + buf * 2 * TILE_W;
        const float* Bs = As + TILE_W;
#pragma unroll
        for (int ks = 0; ks < 4; ++ks) {
            uint32_t a[4][4], b[4][2];
            const int kc = ks * 8 + tig;
#pragma unroll
            for (int mf = 0; mf < 4; ++mf) {
                const int row = wm * 64 + mf * 16 + g;
                a[mf][0] = f2tf(As[row * SSTRIDE + kc]);
                a[mf][1] = f2tf(As[(row + 8) * SSTRIDE + kc]);
                a[mf][2] = f2tf(As[row * SSTRIDE + kc + 4]);
                a[mf][3] = f2tf(As[(row + 8) * SSTRIDE + kc + 4]);
            }
#pragma unroll
            for (int nf = 0; nf < 4; ++nf) {
                const int col = wn * 32 + nf * 8 + g;
                b[nf][0] = f2tf(Bs[col * SSTRIDE + kc]);
                b[nf][1] = f2tf(Bs[col * SSTRIDE + kc + 4]);
            }
#pragma unroll
            for (int mf = 0; mf < 4; ++mf)
#pragma unroll
                for (int nf = 0; nf < 4; ++nf)
                    mma_tf32(acc[mf][nf], a[mf], b[nf]);
        }
    };

    load_chunk(0, 0);
    int buf = 0;
    for (int c = 0; c < NCHUNK; ++c) {
        if (c + 1 < NCHUNK) { load_chunk(c + 1, buf ^ 1); CP_WAIT1(); }
        else                { CP_WAIT0(); }
        __syncthreads();
        compute(buf);
        __syncthreads();
        buf ^= 1;
    }

#pragma unroll
    for (int mf = 0; mf < 4; ++mf) {
        const int r0 = wm * 64 + mf * 16 + g;
#pragma unroll
        for (int nf = 0; nf < 4; ++nf) {
            const int c0 = wn * 32 + nf * 8 + tig * 2;
            *(float2*)(Cp + (size_t)r0 * ldc + c0)       = make_float2(acc[mf][nf][0], acc[mf][nf][1]);
            *(float2*)(Cp + (size_t)(r0 + 8) * ldc + c0) = make_float2(acc[mf][nf][2], acc[mf][nf][3]);
        }
    }
}

__global__ void __launch_bounds__(256, 2)
gemm_qkv(const float* __restrict__ x,
         const float* __restrict__ Wq, const float* __restrict__ Wk, const float* __restrict__ Wv,
         float* __restrict__ q, float* __restrict__ k, float* __restrict__ v)
{
    const int nt = blockIdx.x;
    const int bm = blockIdx.y * GBM;
    const float* W; float* C; int ldc, cn;
    if (nt < 16)      { W = Wq; C = q; ldc = CC;        cn = nt * GBN; }
    else if (nt < 20) { W = Wk; C = k; ldc = KVHN * DD; cn = (nt - 16) * GBN; }
    else              { W = Wv; C = v; ldc = KVHN * DD; cn = (nt - 20) * GBN; }
    gemm_mma_tile(x + (size_t)bm * KDIM, W + (size_t)cn * KDIM,
                  C + (size_t)bm * ldc + cn, ldc);
}

__global__ void __launch_bounds__(256, 2)
gemm_oproj(const float* __restrict__ A, const float* __restrict__ W, float* __restrict__ C)
{
    const int bm = blockIdx.y * GBM;
    const int bn = blockIdx.x * GBN;
    gemm_mma_tile(A + (size_t)bm * KDIM, W + (size_t)bn * KDIM,
                  C + (size_t)bm * CC + bn, CC);
}

// ---------------------------------------------------------------------------
// RoPE in place on q (B*T x H*D) and k (B*T x KVH*D).
// ---------------------------------------------------------------------------
__global__ void rope_kernel(float* __restrict__ q, float* __restrict__ k,
                            const float* __restrict__ cosb, const float* __restrict__ sinb)
{
    const int halfs_q = BB * TT * HH * (DD / 2);
    const int halfs_k = BB * TT * KVHN * (DD / 2);
    int idx = blockIdx.x * blockDim.x + threadIdx.x;
    if (idx < halfs_q) {
        int d   = idx & 31;
        int h   = (idx >> 5) & (HH - 1);
        int row = idx >> 10;
        int t   = row & (TT - 1);
        float* p = q + (size_t)row * CC + h * DD;
        float c1 = cosb[t * DD + d],      s1 = sinb[t * DD + d];
        float c2 = cosb[t * DD + d + 32], s2 = sinb[t * DD + d + 32];
        float a = p[d], b2 = p[d + 32];
        p[d]      = a * c1 - b2 * s1;
        p[d + 32] = b2 * c2 + a * s2;
    } else if (idx < halfs_q + halfs_k) {
        int j   = idx - halfs_q;
        int d   = j & 31;
        int h   = (j >> 5) & (KVHN - 1);
        int row = j >> 8;
        int t   = row & (TT - 1);
        float* p = k + (size_t)row * (KVHN * DD) + h * DD;
        float c1 = cosb[t * DD + d],      s1 = sinb[t * DD + d];
        float c2 = cosb[t * DD + d + 32], s2 = sinb[t * DD + d + 32];
        float a = p[d], b2 = p[d + 32];
        p[d]      = a * c1 - b2 * s1;
        p[d + 32] = b2 * c2 + a * s2;
    }
}

// ---------------------------------------------------------------------------
// Tensor-core flash attention (tf32 mma.sync), causal, GQA G=4, D=64.
// CTA: 128 queries x (b,h). 8 warps, warp owns 16 query rows.
// K/V tiles: 64 keys, cp.async double-buffered. P via warp-private smem.
// ---------------------------------------------------------------------------
#define FQ 128
#define FK 64
#define FP 72                      // padded row stride (floats)
#define F_KOFF0 0
#define F_VOFF0 4608
#define F_KOFF1 9216
#define F_VOFF1 13824
#define F_POFF  18432
#define FLASH_SMEM ((18432 + 128 * FP) * 4)   // 110592 B

__global__ void __launch_bounds__(256)
flash_mma(const float* __restrict__ Qg, const float* __restrict__ Kg,
          const float* __restrict__ Vg, float* __restrict__ Og)
{
    extern __shared__ float sf[];
    const uint32_t sbase = smem_u32(sf);

    const int qt  = blockIdx.x;
    const int h   = blockIdx.y;
    const int b   = blockIdx.z;
    const int kvh = h >> 2;
    const int tid = threadIdx.x;
    const int w   = tid >> 5, lane = tid & 31;
    const int g   = lane >> 2, tig = lane & 3;

    // Q fragments in registers (tf32, pre-scaled by 1/sqrt(D))
    uint32_t qf[8][4];
    {
        const float* Qb = Qg + ((size_t)(b * TT + qt * FQ + w * 16)) * CC + h * DD;
#pragma unroll
        for (int ks = 0; ks < 8; ++ks) {
            qf[ks][0] = f2tf(Qb[(size_t)g * CC + ks * 8 + tig] * 0.125f);
            qf[ks][1] = f2tf(Qb[(size_t)(g + 8) * CC + ks * 8 + tig] * 0.125f);
            qf[ks][2] = f2tf(Qb[(size_t)g * CC + ks * 8 + tig + 4] * 0.125f);
            qf[ks][3] = f2tf(Qb[(size_t)(g + 8) * CC + ks * 8 + tig + 4] * 0.125f);
        }
    }

    float oacc[8][4];
#pragma unroll
    for (int nf = 0; nf < 8; ++nf)
#pragma unroll
        for (int e = 0; e < 4; ++e) oacc[nf][e] = 0.f;
    float m0 = -1e30f, m1 = -1e30f, l0 = 0.f, l1 = 0.f;

    const int ktmax = 2 * qt + 1;

    auto prefetch = [&](int kt, int buf) {
        const float* Kb = Kg + ((size_t)(b * TT + kt * FK)) * (KVHN * DD) + kvh * DD;
        const float* Vb = Vg + ((size_t)(b * TT + kt * FK)) * (KVHN * DD) + kvh * DD;
        const uint32_t kd = sbase + (buf ? F_KOFF1 : F_KOFF0) * 4u;
        const uint32_t vd = sbase + (buf ? F_VOFF1 : F_VOFF0) * 4u;
#pragma unroll
        for (int i = 0; i < 4; ++i) {
            int lin = tid + i * 256;
            int r = lin >> 4, c4 = lin & 15;
            CP16(kd + (uint32_t)(r * FP + c4 * 4) * 4u, Kb + (size_t)r * (KVHN * DD) + c4 * 4);
            CP16(vd + (uint32_t)(r * FP + c4 * 4) * 4u, Vb + (size_t)r * (KVHN * DD) + c4 * 4);
        }
        CP_COMMIT();
    };

    prefetch(0, 0);
    float* Pw = sf + F_POFF + w * 16 * FP;   // warp-private P rows

    for (int kt = 0; kt <= ktmax; ++kt) {
        const int buf = kt & 1;
        CP_WAIT0();
        __syncthreads();
        if (kt < ktmax) prefetch(kt + 1, buf ^ 1);

        const float* Ks = sf + (buf ? F_KOFF1 : F_KOFF0);
        const float* Vs = sf + (buf ? F_VOFF1 : F_VOFF0);

        // ---- S = Q @ K^T  (warp tile 16x64) ----
        float sacc[8][4];
#pragma unroll
        for (int nf = 0; nf < 8; ++nf)
#pragma unroll
            for (int e = 0; e < 4; ++e) sacc[nf][e] = 0.f;

#pragma unroll
        for (int ks = 0; ks < 8; ++ks) {
            uint32_t bf[8][2];
#pragma unroll
            for (int nf = 0; nf < 8; ++nf) {
                bf[nf][0] = f2tf(Ks[(nf * 8 + g) * FP + ks * 8 + tig]);
                bf[nf][1] = f2tf(Ks[(nf * 8 + g) * FP + ks * 8 + tig + 4]);
            }
#pragma unroll
            for (int nf = 0; nf < 8; ++nf)
                mma_tf32(sacc[nf], qf[ks], bf[nf]);
        }

        // ---- causal mask (only last two key blocks) ----
        if (kt >= 2 * qt) {
            const int q0 = qt * FQ + w * 16 + g;
            const int q1 = q0 + 8;
#pragma unroll
            for (int nf = 0; nf < 8; ++nf) {
                const int key = kt * FK + nf * 8 + tig * 2;
                if (key     > q0) sacc[nf][0] = -1e30f;
                if (key + 1 > q0) sacc[nf][1] = -1e30f;
                if (key     > q1) sacc[nf][2] = -1e30f;
                if (key + 1 > q1) sacc[nf][3] = -1e30f;
            }
        }

        // ---- online softmax (rows g, g+8; quad reduce) ----
        float mx0 = -1e30f, mx1 = -1e30f;
#pragma unroll
        for (int nf = 0; nf < 8; ++nf) {
            mx0 = fmaxf(mx0, fmaxf(sacc[nf][0], sacc[nf][1]));
            mx1 = fmaxf(mx1, fmaxf(sacc[nf][2], sacc[nf][3]));
        }
        mx0 = fmaxf(mx0, __shfl_xor_sync(0xffffffffu, mx0, 1));
        mx0 = fmaxf(mx0, __shfl_xor_sync(0xffffffffu, mx0, 2));
        mx1 = fmaxf(mx1, __shfl_xor_sync(0xffffffffu, mx1, 1));
        mx1 = fmaxf(mx1, __shfl_xor_sync(0xffffffffu, mx1, 2));

        const float mn0 = fmaxf(m0, mx0), mn1 = fmaxf(m1, mx1);
        const float c0 = __expf(m0 - mn0), c1 = __expf(m1 - mn1);
        float s0 = 0.f, s1 = 0.f;
#pragma unroll
        for (int nf = 0; nf < 8; ++nf) {
            sacc[nf][0] = __expf(sacc[nf][0] - mn0);
            sacc[nf][1] = __expf(sacc[nf][1] - mn0);
            sacc[nf][2] = __expf(sacc[nf][2] - mn1);
            sacc[nf][3] = __expf(sacc[nf][3] - mn1);
            s0 += sacc[nf][0] + sacc[nf][1];
            s1 += sacc[nf][2] + sacc[nf][3];
        }
        s0 += __shfl_xor_sync(0xffffffffu, s0, 1);
        s0 += __shfl_xor_sync(0xffffffffu, s0, 2);
        s1 += __shfl_xor_sync(0xffffffffu, s1, 1);
        s1 += __shfl_xor_sync(0xffffffffu, s1, 2);

        l0 = l0 * c0 + s0;  l1 = l1 * c1 + s1;
        m0 = mn0;           m1 = mn1;
#pragma unroll
        for (int nf = 0; nf < 8; ++nf) {
            oacc[nf][0] *= c0; oacc[nf][1] *= c0;
            oacc[nf][2] *= c1; oacc[nf][3] *= c1;
        }

        // ---- P -> warp-private smem (C-frag -> A-frag layout fix) ----
#pragma unroll
        for (int nf = 0; nf < 8; ++nf) {
            *(float2*)(Pw + g * FP + nf * 8 + tig * 2)       = make_float2(sacc[nf][0], sacc[nf][1]);
            *(float2*)(Pw + (g + 8) * FP + nf * 8 + tig * 2) = make_float2(sacc[nf][2], sacc[nf][3]);
        }
        __syncwarp();

        // ---- O += P @ V ----
#pragma unroll
        for (int ks = 0; ks < 8; ++ks) {
            uint32_t pa[4];
            pa[0] = f2tf(Pw[g * FP + ks * 8 + tig]);
            pa[1] = f2tf(Pw[(g + 8) * FP + ks * 8 + tig]);
            pa[2] = f2tf(Pw[g * FP + ks * 8 + tig + 4]);
            pa[3] = f2tf(Pw[(g + 8) * FP + ks * 8 + tig + 4]);
            uint32_t bv[8][2];
#pragma unroll
            for (int nf = 0; nf < 8; ++nf) {
                bv[nf][0] = f2tf(Vs[(ks * 8 + tig) * FP + nf * 8 + g]);
                bv[nf][1] = f2tf(Vs[(ks * 8 + tig + 4) * FP + nf * 8 + g]);
            }
#pragma unroll
            for (int nf = 0; nf < 8; ++nf)
                mma_tf32(oacc[nf], pa, bv[nf]);
        }
        __syncwarp();   // P WAR guard for next iteration
    }

    // ---- epilogue: normalize and store ----
    float* Ob = Og + ((size_t)(b * TT + qt * FQ + w * 16)) * CC + h * DD;
    const float i0 = 1.0f / l0, i1 = 1.0f / l1;
#pragma unroll
    for (int nf = 0; nf < 8; ++nf) {
        *(float2*)(Ob + (size_t)g * CC + nf * 8 + tig * 2) =
            make_float2(oacc[nf][0] * i0, oacc[nf][1] * i0);
        *(float2*)(Ob + (size_t)(g + 8) * CC + nf * 8 + tig * 2) =
            make_float2(oacc[nf][2] * i1, oacc[nf][3] * i1);
    }
}

// ---------------------------------------------------------------------------
extern "C" void kernel_launch(void* const* d_in, const int* in_sizes, int n_in,
                              void* d_out, int out_size)
{
    const float* x    = (const float*)d_in[0];
    const float* Wq   = (const float*)d_in[1];
    const float* Wk   = (const float*)d_in[2];
    const float* Wv   = (const float*)d_in[3];
    const float* Wo   = (const float*)d_in[4];
    const float* cosb = (const float*)d_in[5];
    const float* sinb = (const float*)d_in[6];
    float* out = (float*)d_out;

    float *q, *k, *v, *attn;
    cudaGetSymbolAddress((void**)&q,    g_q);
    cudaGetSymbolAddress((void**)&k,    g_k);
    cudaGetSymbolAddress((void**)&v,    g_v);
    cudaGetSymbolAddress((void**)&attn, g_attn);

    cudaFuncSetAttribute(gemm_qkv,   cudaFuncAttributeMaxDynamicSharedMemorySize, GEMM_SMEM);
    cudaFuncSetAttribute(gemm_oproj, cudaFuncAttributeMaxDynamicSharedMemorySize, GEMM_SMEM);
    cudaFuncSetAttribute(flash_mma,  cudaFuncAttributeMaxDynamicSharedMemorySize, FLASH_SMEM);

    // QKV projections (mma.sync tf32)
    gemm_qkv<<<dim3(24, 32), 256, GEMM_SMEM>>>(x, Wq, Wk, Wv, q, k, v);

    // RoPE (in place on q, k)
    {
        int total = BB * TT * (HH + KVHN) * (DD / 2);
        rope_kernel<<<(total + 255) / 256, 256>>>(q, k, cosb, sinb);
    }

    // Flash attention (mma.sync tf32)
    flash_mma<<<dim3(TT / FQ, HH, BB), 256, FLASH_SMEM>>>(q, k, v, attn);

    // Output projection (mma.sync tf32)
    gemm_oproj<<<dim3(16, 32), 256, GEMM_SMEM>>>(attn, Wo, out);
}

// round 6
// speedup vs baseline: 3.2724x; 1.0757x over previous
#include <cuda_runtime.h>
#include <math.h>
#include <stdint.h>

#define BB   2
#define TT   2048
#define CC   2048
#define HH   32
#define KVHN 8
#define DD   64
#define KDIM 2048

// GEMM tile config
#define GBM  128
#define GBN  128
#define GBK  32
#define NCHUNK (KDIM / GBK)       // 64
#define SSTRIDE 36
#define TILE_W (128 * SSTRIDE)
#define GEMM_SMEM (4 * TILE_W * 4)  // 73728 B

// Scratch (allocation-free rule: __device__ globals)
__device__ float g_q[(size_t)BB * TT * CC];
__device__ float g_k[(size_t)BB * TT * KVHN * DD];
__device__ float g_v[(size_t)BB * TT * KVHN * DD];
__device__ float g_attn[(size_t)BB * TT * CC];
// tf32-pre-rounded operand copies
__device__ float g_xt [(size_t)BB * TT * CC];
__device__ float g_wqt[(size_t)CC * CC];
__device__ float g_wkt[(size_t)KVHN * DD * CC];
__device__ float g_wvt[(size_t)KVHN * DD * CC];
__device__ float g_wot[(size_t)CC * CC];

// ---------------------------------------------------------------------------
// helpers
// ---------------------------------------------------------------------------
__device__ __forceinline__ uint32_t smem_u32(const void* p) {
    uint32_t r;
    asm("{ .reg .u64 t; cvta.to.shared.u64 t, %1; cvt.u32.u64 %0, t; }" : "=r"(r) : "l"(p));
    return r;
}
__device__ __forceinline__ uint32_t f2tf(float f) {
    uint32_t r;
    asm("cvt.rna.tf32.f32 %0, %1;" : "=r"(r) : "f"(f));
    return r;
}
#define CP16(dst, src) \
    asm volatile("cp.async.cg.shared.global [%0], [%1], 16;" :: "r"(dst), "l"(src))
#define CP_COMMIT() asm volatile("cp.async.commit_group;" ::: "memory")
#define CP_WAIT1()  asm volatile("cp.async.wait_group 1;" ::: "memory")
#define CP_WAIT0()  asm volatile("cp.async.wait_group 0;" ::: "memory")

__device__ __forceinline__ void mma_tf32(float* d, const uint32_t* a, const uint32_t* b) {
    asm volatile(
        "mma.sync.aligned.m16n8k8.row.col.f32.tf32.tf32.f32 "
        "{%0,%1,%2,%3}, {%4,%5,%6,%7}, {%8,%9}, {%0,%1,%2,%3};"
        : "+f"(d[0]), "+f"(d[1]), "+f"(d[2]), "+f"(d[3])
        : "r"(a[0]), "r"(a[1]), "r"(a[2]), "r"(a[3]), "r"(b[0]), "r"(b[1]));
}

// ---------------------------------------------------------------------------
// tf32 pre-rounding copy (float4 grid-stride)
// ---------------------------------------------------------------------------
__global__ void round_copy(const float4* __restrict__ in, float4* __restrict__ out, int n4)
{
    int i = blockIdx.x * blockDim.x + threadIdx.x;
    if (i < n4) {
        float4 v = in[i];
        float4 w;
        w.x = __uint_as_float(f2tf(v.x));
        w.y = __uint_as_float(f2tf(v.y));
        w.z = __uint_as_float(f2tf(v.z));
        w.w = __uint_as_float(f2tf(v.w));
        out[i] = w;
    }
}

// ---------------------------------------------------------------------------
// mma.sync tf32 NT GEMM tile (operands PRE-ROUNDED: no cvt in inner loop)
// ---------------------------------------------------------------------------
__device__ __forceinline__ void gemm_mma_tile(const float* __restrict__ A,
                                              const float* __restrict__ W,
                                              float* __restrict__ Cp, int ldc)
{
    extern __shared__ float smf[];
    const uint32_t sbase = smem_u32(smf);

    const int tid  = threadIdx.x;
    const int wid  = tid >> 5, lane = tid & 31;
    const int wm   = wid & 1,  wn   = wid >> 1;
    const int g    = lane >> 2, tig = lane & 3;

    float acc[4][4][4];
#pragma unroll
    for (int i = 0; i < 4; ++i)
#pragma unroll
        for (int j = 0; j < 4; ++j)
#pragma unroll
            for (int e = 0; e < 4; ++e) acc[i][j][e] = 0.f;

    auto load_chunk = [&](int c, int buf) {
        const float* Ab = A + c * GBK;
        const float* Wb = W + c * GBK;
        const uint32_t da = sbase + (buf ? 2u * TILE_W * 4u : 0u);
        const uint32_t db = da + TILE_W * 4u;
#pragma unroll
        for (int i = 0; i < 4; ++i) {
            int lin = tid + i * 256;
            int r = lin >> 3, c4 = lin & 7;
            CP16(da + (uint32_t)(r * SSTRIDE + c4 * 4) * 4u,
                 Ab + (size_t)r * KDIM + c4 * 4);
        }
#pragma unroll
        for (int i = 0; i < 4; ++i) {
            int lin = tid + i * 256;
            int r = lin >> 3, c4 = lin & 7;
            CP16(db + (uint32_t)(r * SSTRIDE + c4 * 4) * 4u,
                 Wb + (size_t)r * KDIM + c4 * 4);
        }
        CP_COMMIT();
    };

    auto compute = [&](int buf) {
        const uint32_t* As = (const uint32_t*)(smf + buf * 2 * TILE_W);
        const uint32_t* Bs = As + TILE_W;
#pragma unroll
        for (int ks = 0; ks < 4; ++ks) {
            uint32_t a[4][4], b[4][2];
            const int kc = ks * 8 + tig;
#pragma unroll
            for (int mf = 0; mf < 4; ++mf) {
                const int row = wm * 64 + mf * 16 + g;
                a[mf][0] = As[row * SSTRIDE + kc];
                a[mf][1] = As[(row + 8) * SSTRIDE + kc];
                a[mf][2] = As[row * SSTRIDE + kc + 4];
                a[mf][3] = As[(row + 8) * SSTRIDE + kc + 4];
            }
#pragma unroll
            for (int nf = 0; nf < 4; ++nf) {
                const int col = wn * 32 + nf * 8 + g;
                b[nf][0] = Bs[col * SSTRIDE + kc];
                b[nf][1] = Bs[col * SSTRIDE + kc + 4];
            }
#pragma unroll
            for (int mf = 0; mf < 4; ++mf)
#pragma unroll
                for (int nf = 0; nf < 4; ++nf)
                    mma_tf32(acc[mf][nf], a[mf], b[nf]);
        }
    };

    load_chunk(0, 0);
    int buf = 0;
    for (int c = 0; c < NCHUNK; ++c) {
        if (c + 1 < NCHUNK) { load_chunk(c + 1, buf ^ 1); CP_WAIT1(); }
        else                { CP_WAIT0(); }
        __syncthreads();
        compute(buf);
        __syncthreads();
        buf ^= 1;
    }

#pragma unroll
    for (int mf = 0; mf < 4; ++mf) {
        const int r0 = wm * 64 + mf * 16 + g;
#pragma unroll
        for (int nf = 0; nf < 4; ++nf) {
            const int c0 = wn * 32 + nf * 8 + tig * 2;
            *(float2*)(Cp + (size_t)r0 * ldc + c0)       = make_float2(acc[mf][nf][0], acc[mf][nf][1]);
            *(float2*)(Cp + (size_t)(r0 + 8) * ldc + c0) = make_float2(acc[mf][nf][2], acc[mf][nf][3]);
        }
    }
}

__global__ void __launch_bounds__(256, 2)
gemm_qkv(const float* __restrict__ x,
         const float* __restrict__ Wq, const float* __restrict__ Wk, const float* __restrict__ Wv,
         float* __restrict__ q, float* __restrict__ k, float* __restrict__ v)
{
    const int nt = blockIdx.x;
    const int bm = blockIdx.y * GBM;
    const float* W; float* C; int ldc, cn;
    if (nt < 16)      { W = Wq; C = q; ldc = CC;        cn = nt * GBN; }
    else if (nt < 20) { W = Wk; C = k; ldc = KVHN * DD; cn = (nt - 16) * GBN; }
    else              { W = Wv; C = v; ldc = KVHN * DD; cn = (nt - 20) * GBN; }
    gemm_mma_tile(x + (size_t)bm * KDIM, W + (size_t)cn * KDIM,
                  C + (size_t)bm * ldc + cn, ldc);
}

__global__ void __launch_bounds__(256, 2)
gemm_oproj(const float* __restrict__ A, const float* __restrict__ W, float* __restrict__ C)
{
    const int bm = blockIdx.y * GBM;
    const int bn = blockIdx.x * GBN;
    gemm_mma_tile(A + (size_t)bm * KDIM, W + (size_t)bn * KDIM,
                  C + (size_t)bm * CC + bn, CC);
}

// ---------------------------------------------------------------------------
// RoPE in place on q, k; outputs tf32-rounded. Also rounds v in place.
// ---------------------------------------------------------------------------
__global__ void rope_kernel(float* __restrict__ q, float* __restrict__ k,
                            float* __restrict__ v,
                            const float* __restrict__ cosb, const float* __restrict__ sinb)
{
    const int halfs_q = BB * TT * HH * (DD / 2);
    const int halfs_k = BB * TT * KVHN * (DD / 2);
    const int v_elems = BB * TT * KVHN * DD;
    int idx = blockIdx.x * blockDim.x + threadIdx.x;
    if (idx < halfs_q) {
        int d   = idx & 31;
        int h   = (idx >> 5) & (HH - 1);
        int row = idx >> 10;
        int t   = row & (TT - 1);
        float* p = q + (size_t)row * CC + h * DD;
        float c1 = cosb[t * DD + d],      s1 = sinb[t * DD + d];
        float c2 = cosb[t * DD + d + 32], s2 = sinb[t * DD + d + 32];
        float a = p[d], b2 = p[d + 32];
        p[d]      = __uint_as_float(f2tf(a * c1 - b2 * s1));
        p[d + 32] = __uint_as_float(f2tf(b2 * c2 + a * s2));
    } else if (idx < halfs_q + halfs_k) {
        int j   = idx - halfs_q;
        int d   = j & 31;
        int h   = (j >> 5) & (KVHN - 1);
        int row = j >> 8;
        int t   = row & (TT - 1);
        float* p = k + (size_t)row * (KVHN * DD) + h * DD;
        float c1 = cosb[t * DD + d],      s1 = sinb[t * DD + d];
        float c2 = cosb[t * DD + d + 32], s2 = sinb[t * DD + d + 32];
        float a = p[d], b2 = p[d + 32];
        p[d]      = __uint_as_float(f2tf(a * c1 - b2 * s1));
        p[d + 32] = __uint_as_float(f2tf(b2 * c2 + a * s2));
    } else if (idx < halfs_q + halfs_k + v_elems) {
        int j = idx - halfs_q - halfs_k;
        v[j] = __uint_as_float(f2tf(v[j]));
    }
}

// ---------------------------------------------------------------------------
// Tensor-core flash attention (tf32 mma.sync), causal, GQA G=4, D=64.
// Q/K/V pre-rounded -> raw-bit operand loads; only P needs cvt after exp.
// Epilogue stores attn tf32-rounded (feeds pre-rounded A into oproj).
// ---------------------------------------------------------------------------
#define FQ 128
#define FK 64
#define FP 72
#define F_KOFF0 0
#define F_VOFF0 4608
#define F_KOFF1 9216
#define F_VOFF1 13824
#define F_POFF  18432
#define FLASH_SMEM ((18432 + 128 * FP) * 4)   // 110592 B

__global__ void __launch_bounds__(256)
flash_mma(const float* __restrict__ Qg, const float* __restrict__ Kg,
          const float* __restrict__ Vg, float* __restrict__ Og)
{
    extern __shared__ float sf[];
    const uint32_t sbase = smem_u32(sf);

    const int qt  = blockIdx.x;
    const int h   = blockIdx.y;
    const int b   = blockIdx.z;
    const int kvh = h >> 2;
    const int tid = threadIdx.x;
    const int w   = tid >> 5, lane = tid & 31;
    const int g   = lane >> 2, tig = lane & 3;

    // Q fragments in registers (pre-rounded; *0.125f is exact)
    uint32_t qf[8][4];
    {
        const float* Qb = Qg + ((size_t)(b * TT + qt * FQ + w * 16)) * CC + h * DD;
#pragma unroll
        for (int ks = 0; ks < 8; ++ks) {
            qf[ks][0] = __float_as_uint(Qb[(size_t)g * CC + ks * 8 + tig] * 0.125f);
            qf[ks][1] = __float_as_uint(Qb[(size_t)(g + 8) * CC + ks * 8 + tig] * 0.125f);
            qf[ks][2] = __float_as_uint(Qb[(size_t)g * CC + ks * 8 + tig + 4] * 0.125f);
            qf[ks][3] = __float_as_uint(Qb[(size_t)(g + 8) * CC + ks * 8 + tig + 4] * 0.125f);
        }
    }

    float oacc[8][4];
#pragma unroll
    for (int nf = 0; nf < 8; ++nf)
#pragma unroll
        for (int e = 0; e < 4; ++e) oacc[nf][e] = 0.f;
    float m0 = -1e30f, m1 = -1e30f, l0 = 0.f, l1 = 0.f;

    const int ktmax = 2 * qt + 1;

    auto prefetch = [&](int kt, int buf) {
        const float* Kb = Kg + ((size_t)(b * TT + kt * FK)) * (KVHN * DD) + kvh * DD;
        const float* Vb = Vg + ((size_t)(b * TT + kt * FK)) * (KVHN * DD) + kvh * DD;
        const uint32_t kd = sbase + (buf ? F_KOFF1 : F_KOFF0) * 4u;
        const uint32_t vd = sbase + (buf ? F_VOFF1 : F_VOFF0) * 4u;
#pragma unroll
        for (int i = 0; i < 4; ++i) {
            int lin = tid + i * 256;
            int r = lin >> 4, c4 = lin & 15;
            CP16(kd + (uint32_t)(r * FP + c4 * 4) * 4u, Kb + (size_t)r * (KVHN * DD) + c4 * 4);
            CP16(vd + (uint32_t)(r * FP + c4 * 4) * 4u, Vb + (size_t)r * (KVHN * DD) + c4 * 4);
        }
        CP_COMMIT();
    };

    prefetch(0, 0);
    float* Pw = sf + F_POFF + w * 16 * FP;

    for (int kt = 0; kt <= ktmax; ++kt) {
        const int buf = kt & 1;
        CP_WAIT0();
        __syncthreads();
        if (kt < ktmax) prefetch(kt + 1, buf ^ 1);

        const uint32_t* Ks = (const uint32_t*)(sf + (buf ? F_KOFF1 : F_KOFF0));
        const uint32_t* Vs = (const uint32_t*)(sf + (buf ? F_VOFF1 : F_VOFF0));

        // ---- S = Q @ K^T ----
        float sacc[8][4];
#pragma unroll
        for (int nf = 0; nf < 8; ++nf)
#pragma unroll
            for (int e = 0; e < 4; ++e) sacc[nf][e] = 0.f;

#pragma unroll
        for (int ks = 0; ks < 8; ++ks) {
            uint32_t bf[8][2];
#pragma unroll
            for (int nf = 0; nf < 8; ++nf) {
                bf[nf][0] = Ks[(nf * 8 + g) * FP + ks * 8 + tig];
                bf[nf][1] = Ks[(nf * 8 + g) * FP + ks * 8 + tig + 4];
            }
#pragma unroll
            for (int nf = 0; nf < 8; ++nf)
                mma_tf32(sacc[nf], qf[ks], bf[nf]);
        }

        // ---- causal mask (only last two key blocks) ----
        if (kt >= 2 * qt) {
            const int q0 = qt * FQ + w * 16 + g;
            const int q1 = q0 + 8;
#pragma unroll
            for (int nf = 0; nf < 8; ++nf) {
                const int key = kt * FK + nf * 8 + tig * 2;
                if (key     > q0) sacc[nf][0] = -1e30f;
                if (key + 1 > q0) sacc[nf][1] = -1e30f;
                if (key     > q1) sacc[nf][2] = -1e30f;
                if (key + 1 > q1) sacc[nf][3] = -1e30f;
            }
        }

        // ---- online softmax ----
        float mx0 = -1e30f, mx1 = -1e30f;
#pragma unroll
        for (int nf = 0; nf < 8; ++nf) {
            mx0 = fmaxf(mx0, fmaxf(sacc[nf][0], sacc[nf][1]));
            mx1 = fmaxf(mx1, fmaxf(sacc[nf][2], sacc[nf][3]));
        }
        mx0 = fmaxf(mx0, __shfl_xor_sync(0xffffffffu, mx0, 1));
        mx0 = fmaxf(mx0, __shfl_xor_sync(0xffffffffu, mx0, 2));
        mx1 = fmaxf(mx1, __shfl_xor_sync(0xffffffffu, mx1, 1));
        mx1 = fmaxf(mx1, __shfl_xor_sync(0xffffffffu, mx1, 2));

        const float mn0 = fmaxf(m0, mx0), mn1 = fmaxf(m1, mx1);
        const float c0 = __expf(m0 - mn0), c1 = __expf(m1 - mn1);
        float s0 = 0.f, s1 = 0.f;
#pragma unroll
        for (int nf = 0; nf < 8; ++nf) {
            sacc[nf][0] = __expf(sacc[nf][0] - mn0);
            sacc[nf][1] = __expf(sacc[nf][1] - mn0);
            sacc[nf][2] = __expf(sacc[nf][2] - mn1);
            sacc[nf][3] = __expf(sacc[nf][3] - mn1);
            s0 += sacc[nf][0] + sacc[nf][1];
            s1 += sacc[nf][2] + sacc[nf][3];
        }
        s0 += __shfl_xor_sync(0xffffffffu, s0, 1);
        s0 += __shfl_xor_sync(0xffffffffu, s0, 2);
        s1 += __shfl_xor_sync(0xffffffffu, s1, 1);
        s1 += __shfl_xor_sync(0xffffffffu, s1, 2);

        l0 = l0 * c0 + s0;  l1 = l1 * c1 + s1;
        m0 = mn0;           m1 = mn1;
#pragma unroll
        for (int nf = 0; nf < 8; ++nf) {
            oacc[nf][0] *= c0; oacc[nf][1] *= c0;
            oacc[nf][2] *= c1; oacc[nf][3] *= c1;
        }

        // ---- P -> warp-private smem (store tf32-rounded bits) ----
#pragma unroll
        for (int nf = 0; nf < 8; ++nf) {
            *(float2*)(Pw + g * FP + nf * 8 + tig * 2) =
                make_float2(__uint_as_float(f2tf(sacc[nf][0])), __uint_as_float(f2tf(sacc[nf][1])));
            *(float2*)(Pw + (g + 8) * FP + nf * 8 + tig * 2) =
                make_float2(__uint_as_float(f2tf(sacc[nf][2])), __uint_as_float(f2tf(sacc[nf][3])));
        }
        __syncwarp();

        // ---- O += P @ V ----
        const uint32_t* Pu = (const uint32_t*)Pw;
#pragma unroll
        for (int ks = 0; ks < 8; ++ks) {
            uint32_t pa[4];
            pa[0] = Pu[g * FP + ks * 8 + tig];
            pa[1] = Pu[(g + 8) * FP + ks * 8 + tig];
            pa[2] = Pu[g * FP + ks * 8 + tig + 4];
            pa[3] = Pu[(g + 8) * FP + ks * 8 + tig + 4];
            uint32_t bv[8][2];
#pragma unroll
            for (int nf = 0; nf < 8; ++nf) {
                bv[nf][0] = Vs[(ks * 8 + tig) * FP + nf * 8 + g];
                bv[nf][1] = Vs[(ks * 8 + tig + 4) * FP + nf * 8 + g];
            }
#pragma unroll
            for (int nf = 0; nf < 8; ++nf)
                mma_tf32(oacc[nf], pa, bv[nf]);
        }
        __syncwarp();
    }

    // ---- epilogue: normalize, tf32-round, store ----
    float* Ob = Og + ((size_t)(b * TT + qt * FQ + w * 16)) * CC + h * DD;
    const float i0 = 1.0f / l0, i1 = 1.0f / l1;
#pragma unroll
    for (int nf = 0; nf < 8; ++nf) {
        *(float2*)(Ob + (size_t)g * CC + nf * 8 + tig * 2) =
            make_float2(__uint_as_float(f2tf(oacc[nf][0] * i0)),
                        __uint_as_float(f2tf(oacc[nf][1] * i0)));
        *(float2*)(Ob + (size_t)(g + 8) * CC + nf * 8 + tig * 2) =
            make_float2(__uint_as_float(f2tf(oacc[nf][2] * i1)),
                        __uint_as_float(f2tf(oacc[nf][3] * i1)));
    }
}

// ---------------------------------------------------------------------------
extern "C" void kernel_launch(void* const* d_in, const int* in_sizes, int n_in,
                              void* d_out, int out_size)
{
    const float* x    = (const float*)d_in[0];
    const float* Wq   = (const float*)d_in[1];
    const float* Wk   = (const float*)d_in[2];
    const float* Wv   = (const float*)d_in[3];
    const float* Wo   = (const float*)d_in[4];
    const float* cosb = (const float*)d_in[5];
    const float* sinb = (const float*)d_in[6];
    float* out = (float*)d_out;

    float *q, *k, *v, *attn, *xt, *wqt, *wkt, *wvt, *wot;
    cudaGetSymbolAddress((void**)&q,    g_q);
    cudaGetSymbolAddress((void**)&k,    g_k);
    cudaGetSymbolAddress((void**)&v,    g_v);
    cudaGetSymbolAddress((void**)&attn, g_attn);
    cudaGetSymbolAddress((void**)&xt,   g_xt);
    cudaGetSymbolAddress((void**)&wqt,  g_wqt);
    cudaGetSymbolAddress((void**)&wkt,  g_wkt);
    cudaGetSymbolAddress((void**)&wvt,  g_wvt);
    cudaGetSymbolAddress((void**)&wot,  g_wot);

    cudaFuncSetAttribute(gemm_qkv,   cudaFuncAttributeMaxDynamicSharedMemorySize, GEMM_SMEM);
    cudaFuncSetAttribute(gemm_oproj, cudaFuncAttributeMaxDynamicSharedMemorySize, GEMM_SMEM);
    cudaFuncSetAttribute(flash_mma,  cudaFuncAttributeMaxDynamicSharedMemorySize, FLASH_SMEM);

    // tf32 pre-rounding copies
    {
        const int nx  = BB * TT * CC / 4;        // 2097152
        const int nwq = CC * CC / 4;             // 1048576
        const int nwk = KVHN * DD * CC / 4;      // 262144
        round_copy<<<(nx  + 255) / 256, 256>>>((const float4*)x,  (float4*)xt,  nx);
        round_copy<<<(nwq + 255) / 256, 256>>>((const float4*)Wq, (float4*)wqt, nwq);
        round_copy<<<(nwk + 255) / 256, 256>>>((const float4*)Wk, (float4*)wkt, nwk);
        round_copy<<<(nwk + 255) / 256, 256>>>((const float4*)Wv, (float4*)wvt, nwk);
        round_copy<<<(nwq + 255) / 256, 256>>>((const float4*)Wo, (float4*)wot, nwq);
    }

    // QKV projections (mma.sync tf32, pre-rounded operands)
    gemm_qkv<<<dim3(24, 32), 256, GEMM_SMEM>>>(xt, wqt, wkt, wvt, q, k, v);

    // RoPE (in place; outputs rounded; also rounds v)
    {
        int total = BB * TT * (HH + KVHN) * (DD / 2) + BB * TT * KVHN * DD;
        rope_kernel<<<(total + 255) / 256, 256>>>(q, k, v, cosb, sinb);
    }

    // Flash attention (mma.sync tf32, raw-bit operands)
    flash_mma<<<dim3(TT / FQ, HH, BB), 256, FLASH_SMEM>>>(q, k, v, attn);

    // Output projection
    gemm_oproj<<<dim3(16, 32), 256, GEMM_SMEM>>>(attn, wot, out);
}

// round 7
// speedup vs baseline: 3.5675x; 1.0902x over previous
#include <cuda_runtime.h>
#include <math.h>
#include <stdint.h>

#define BB   2
#define TT   2048
#define CC   2048
#define HH   32
#define KVHN 8
#define DD   64
#define KDIM 2048

// GEMM tile config
#define GBM  128
#define GBN  128
#define GBK  32
#define NCHUNK (KDIM / GBK)       // 64
#define SSTRIDE 36
#define TILE_W (128 * SSTRIDE)
#define GEMM_SMEM (4 * TILE_W * 4)  // 73728 B

// Scratch (allocation-free rule: __device__ globals)
__device__ float g_q[(size_t)BB * TT * CC];
__device__ float g_k[(size_t)BB * TT * KVHN * DD];
__device__ float g_v[(size_t)BB * TT * KVHN * DD];
__device__ float g_vT[(size_t)BB * KVHN * DD * TT];
__device__ float g_attn[(size_t)BB * TT * CC];
// tf32-pre-rounded operand copies
__device__ float g_xt [(size_t)BB * TT * CC];
__device__ float g_wqt[(size_t)CC * CC];
__device__ float g_wkt[(size_t)KVHN * DD * CC];
__device__ float g_wvt[(size_t)KVHN * DD * CC];
__device__ float g_wot[(size_t)CC * CC];

// ---------------------------------------------------------------------------
// helpers
// ---------------------------------------------------------------------------
__device__ __forceinline__ uint32_t smem_u32(const void* p) {
    uint32_t r;
    asm("{ .reg .u64 t; cvta.to.shared.u64 t, %1; cvt.u32.u64 %0, t; }" : "=r"(r) : "l"(p));
    return r;
}
__device__ __forceinline__ uint32_t f2tf(float f) {
    uint32_t r;
    asm("cvt.rna.tf32.f32 %0, %1;" : "=r"(r) : "f"(f));
    return r;
}
#define CP16(dst, src) \
    asm volatile("cp.async.cg.shared.global [%0], [%1], 16;" :: "r"(dst), "l"(src))
#define CP_COMMIT() asm volatile("cp.async.commit_group;" ::: "memory")
#define CP_WAIT1()  asm volatile("cp.async.wait_group 1;" ::: "memory")
#define CP_WAIT0()  asm volatile("cp.async.wait_group 0;" ::: "memory")

#define LDMX4(r0, r1, r2, r3, addr) \
    asm volatile("ldmatrix.sync.aligned.m8n8.x4.shared.b16 {%0,%1,%2,%3}, [%4];" \
        : "=r"(r0), "=r"(r1), "=r"(r2), "=r"(r3) : "r"(addr))

__device__ __forceinline__ void mma_tf32(float* d, const uint32_t* a, const uint32_t* b) {
    asm volatile(
        "mma.sync.aligned.m16n8k8.row.col.f32.tf32.tf32.f32 "
        "{%0,%1,%2,%3}, {%4,%5,%6,%7}, {%8,%9}, {%0,%1,%2,%3};"
        : "+f"(d[0]), "+f"(d[1]), "+f"(d[2]), "+f"(d[3])
        : "r"(a[0]), "r"(a[1]), "r"(a[2]), "r"(a[3]), "r"(b[0]), "r"(b[1]));
}

// ---------------------------------------------------------------------------
// tf32 pre-rounding copy
// ---------------------------------------------------------------------------
__global__ void round_copy(const float4* __restrict__ in, float4* __restrict__ out, int n4)
{
    int i = blockIdx.x * blockDim.x + threadIdx.x;
    if (i < n4) {
        float4 v = in[i];
        float4 w;
        w.x = __uint_as_float(f2tf(v.x));
        w.y = __uint_as_float(f2tf(v.y));
        w.z = __uint_as_float(f2tf(v.z));
        w.w = __uint_as_float(f2tf(v.w));
        out[i] = w;
    }
}

// ---------------------------------------------------------------------------
// V transpose + tf32 round: v[(b*TT+t)*512 + kvh*64 + d] -> vT[((b*8+kvh)*64+d)*TT + t]
// ---------------------------------------------------------------------------
__global__ void vt_kernel(const float* __restrict__ v, float* __restrict__ vt)
{
    __shared__ float tile[32][33];
    const int bk = blockIdx.z;            // b*KVHN + kvh
    const int b  = bk >> 3, kvh = bk & 7;
    const int t0 = blockIdx.x * 32, d0 = blockIdx.y * 32;
    const int tx = threadIdx.x, ty = threadIdx.y;
#pragma unroll
    for (int i = 0; i < 4; ++i)
        tile[ty + i * 8][tx] =
            v[((size_t)(b * TT + t0 + ty + i * 8)) * (KVHN * DD) + kvh * DD + d0 + tx];
    __syncthreads();
#pragma unroll
    for (int i = 0; i < 4; ++i)
        vt[((size_t)(bk * DD + d0 + ty + i * 8)) * TT + t0 + tx] =
            __uint_as_float(f2tf(tile[tx][ty + i * 8]));
}

// ---------------------------------------------------------------------------
// mma.sync tf32 NT GEMM tile with ldmatrix fragment loads
// ---------------------------------------------------------------------------
__device__ __forceinline__ void gemm_mma_tile(const float* __restrict__ A,
                                              const float* __restrict__ W,
                                              float* __restrict__ Cp, int ldc)
{
    extern __shared__ float smf[];
    const uint32_t sbase = smem_u32(smf);

    const int tid  = threadIdx.x;
    const int wid  = tid >> 5, lane = tid & 31;
    const int wm   = wid & 1,  wn   = wid >> 1;
    const int g    = lane >> 2, tig = lane & 3;

    // ldmatrix per-thread address components (word offsets within a tile)
    const int lrowA = lane & 15;                      // A: row offset
    const int lcolA = (lane >> 4) * 4;                // A: 0 or 4 (k-words)
    const int lrowB = (lane & 7) + ((lane >> 4) << 3);// B: row offset
    const int lcolB = (lane & 8) ? 4 : 0;             // B: 0 or 4

    float acc[4][4][4];
#pragma unroll
    for (int i = 0; i < 4; ++i)
#pragma unroll
        for (int j = 0; j < 4; ++j)
#pragma unroll
            for (int e = 0; e < 4; ++e) acc[i][j][e] = 0.f;

    auto load_chunk = [&](int c, int buf) {
        const float* Ab = A + c * GBK;
        const float* Wb = W + c * GBK;
        const uint32_t da = sbase + (buf ? 2u * TILE_W * 4u : 0u);
        const uint32_t db = da + TILE_W * 4u;
#pragma unroll
        for (int i = 0; i < 4; ++i) {
            int lin = tid + i * 256;
            int r = lin >> 3, c4 = lin & 7;
            CP16(da + (uint32_t)(r * SSTRIDE + c4 * 4) * 4u,
                 Ab + (size_t)r * KDIM + c4 * 4);
        }
#pragma unroll
        for (int i = 0; i < 4; ++i) {
            int lin = tid + i * 256;
            int r = lin >> 3, c4 = lin & 7;
            CP16(db + (uint32_t)(r * SSTRIDE + c4 * 4) * 4u,
                 Wb + (size_t)r * KDIM + c4 * 4);
        }
        CP_COMMIT();
    };

    auto compute = [&](int buf) {
        const uint32_t abase = sbase + (buf ? 2u * TILE_W * 4u : 0u);
        const uint32_t bbase = abase + TILE_W * 4u;
        uint32_t aaddr[4], baddr[2];
#pragma unroll
        for (int mf = 0; mf < 4; ++mf)
            aaddr[mf] = abase + (uint32_t)((wm * 64 + mf * 16 + lrowA) * SSTRIDE + lcolA) * 4u;
#pragma unroll
        for (int np = 0; np < 2; ++np)
            baddr[np] = bbase + (uint32_t)((wn * 32 + np * 16 + lrowB) * SSTRIDE + lcolB) * 4u;

#pragma unroll
        for (int ks = 0; ks < 4; ++ks) {
            uint32_t a[4][4], b2[2][4];
#pragma unroll
            for (int mf = 0; mf < 4; ++mf)
                LDMX4(a[mf][0], a[mf][1], a[mf][2], a[mf][3], aaddr[mf] + ks * 32);
#pragma unroll
            for (int np = 0; np < 2; ++np)
                LDMX4(b2[np][0], b2[np][1], b2[np][2], b2[np][3], baddr[np] + ks * 32);
#pragma unroll
            for (int mf = 0; mf < 4; ++mf)
#pragma unroll
                for (int nf = 0; nf < 4; ++nf)
                    mma_tf32(acc[mf][nf], a[mf], &b2[nf >> 1][(nf & 1) * 2]);
        }
    };

    load_chunk(0, 0);
    int buf = 0;
    for (int c = 0; c < NCHUNK; ++c) {
        if (c + 1 < NCHUNK) { load_chunk(c + 1, buf ^ 1); CP_WAIT1(); }
        else                { CP_WAIT0(); }
        __syncthreads();
        compute(buf);
        __syncthreads();
        buf ^= 1;
    }

#pragma unroll
    for (int mf = 0; mf < 4; ++mf) {
        const int r0 = wm * 64 + mf * 16 + g;
#pragma unroll
        for (int nf = 0; nf < 4; ++nf) {
            const int c0 = wn * 32 + nf * 8 + tig * 2;
            *(float2*)(Cp + (size_t)r0 * ldc + c0)       = make_float2(acc[mf][nf][0], acc[mf][nf][1]);
            *(float2*)(Cp + (size_t)(r0 + 8) * ldc + c0) = make_float2(acc[mf][nf][2], acc[mf][nf][3]);
        }
    }
}

__global__ void __launch_bounds__(256, 2)
gemm_qkv(const float* __restrict__ x,
         const float* __restrict__ Wq, const float* __restrict__ Wk, const float* __restrict__ Wv,
         float* __restrict__ q, float* __restrict__ k, float* __restrict__ v)
{
    const int nt = blockIdx.x;
    const int bm = blockIdx.y * GBM;
    const float* W; float* C; int ldc, cn;
    if (nt < 16)      { W = Wq; C = q; ldc = CC;        cn = nt * GBN; }
    else if (nt < 20) { W = Wk; C = k; ldc = KVHN * DD; cn = (nt - 16) * GBN; }
    else              { W = Wv; C = v; ldc = KVHN * DD; cn = (nt - 20) * GBN; }
    gemm_mma_tile(x + (size_t)bm * KDIM, W + (size_t)cn * KDIM,
                  C + (size_t)bm * ldc + cn, ldc);
}

__global__ void __launch_bounds__(256, 2)
gemm_oproj(const float* __restrict__ A, const float* __restrict__ W, float* __restrict__ C)
{
    const int bm = blockIdx.y * GBM;
    const int bn = blockIdx.x * GBN;
    gemm_mma_tile(A + (size_t)bm * KDIM, W + (size_t)bn * KDIM,
                  C + (size_t)bm * CC + bn, CC);
}

// ---------------------------------------------------------------------------
// RoPE in place on q, k (outputs tf32-rounded). V handled by vt_kernel.
// ---------------------------------------------------------------------------
__global__ void rope_kernel(float* __restrict__ q, float* __restrict__ k,
                            const float* __restrict__ cosb, const float* __restrict__ sinb)
{
    const int halfs_q = BB * TT * HH * (DD / 2);
    const int halfs_k = BB * TT * KVHN * (DD / 2);
    int idx = blockIdx.x * blockDim.x + threadIdx.x;
    if (idx < halfs_q) {
        int d   = idx & 31;
        int h   = (idx >> 5) & (HH - 1);
        int row = idx >> 10;
        int t   = row & (TT - 1);
        float* p = q + (size_t)row * CC + h * DD;
        float c1 = cosb[t * DD + d],      s1 = sinb[t * DD + d];
        float c2 = cosb[t * DD + d + 32], s2 = sinb[t * DD + d + 32];
        float a = p[d], b2 = p[d + 32];
        p[d]      = __uint_as_float(f2tf(a * c1 - b2 * s1));
        p[d + 32] = __uint_as_float(f2tf(b2 * c2 + a * s2));
    } else if (idx < halfs_q + halfs_k) {
        int j   = idx - halfs_q;
        int d   = j & 31;
        int h   = (j >> 5) & (KVHN - 1);
        int row = j >> 8;
        int t   = row & (TT - 1);
        float* p = k + (size_t)row * (KVHN * DD) + h * DD;
        float c1 = cosb[t * DD + d],      s1 = sinb[t * DD + d];
        float c2 = cosb[t * DD + d + 32], s2 = sinb[t * DD + d + 32];
        float a = p[d], b2 = p[d + 32];
        p[d]      = __uint_as_float(f2tf(a * c1 - b2 * s1));
        p[d + 32] = __uint_as_float(f2tf(b2 * c2 + a * s2));
    }
}

// ---------------------------------------------------------------------------
// Tensor-core flash attention with ldmatrix loads. Causal, GQA G=4, D=64.
// K in [key][d] (stride 68), V^T in [d][key] (stride 68), P (stride 68).
// ---------------------------------------------------------------------------
#define FQ 128
#define FK 64
#define FST 68                          // smem row stride (words)
#define FW_K0  0
#define FW_K1  (64 * FST)               // 4352
#define FW_V0  (2 * 64 * FST)           // 8704
#define FW_V1  (3 * 64 * FST)
#define FW_P   (4 * 64 * FST)           // 17408
#define FLASH_SMEM ((4 * 64 * FST + 128 * FST) * 4)   // 104448 B

__global__ void __launch_bounds__(256)
flash_mma(const float* __restrict__ Qg, const float* __restrict__ Kg,
          const float* __restrict__ VTg, float* __restrict__ Og)
{
    extern __shared__ float sf[];
    const uint32_t sbase = smem_u32(sf);

    const int qt  = blockIdx.x;
    const int h   = blockIdx.y;
    const int b   = blockIdx.z;
    const int kvh = h >> 2;
    const int tid = threadIdx.x;
    const int w   = tid >> 5, lane = tid & 31;
    const int g   = lane >> 2, tig = lane & 3;

    // ldmatrix per-thread address components
    const int lrowA = lane & 15;
    const int lcolA = (lane >> 4) * 4;
    const int lrowB = (lane & 7) + ((lane >> 4) << 3);
    const int lcolB = (lane & 8) ? 4 : 0;

    // Q fragments (pre-rounded; *0.125f exact)
    uint32_t qf[8][4];
    {
        const float* Qb = Qg + ((size_t)(b * TT + qt * FQ + w * 16)) * CC + h * DD;
#pragma unroll
        for (int ks = 0; ks < 8; ++ks) {
            qf[ks][0] = __float_as_uint(Qb[(size_t)g * CC + ks * 8 + tig] * 0.125f);
            qf[ks][1] = __float_as_uint(Qb[(size_t)(g + 8) * CC + ks * 8 + tig] * 0.125f);
            qf[ks][2] = __float_as_uint(Qb[(size_t)g * CC + ks * 8 + tig + 4] * 0.125f);
            qf[ks][3] = __float_as_uint(Qb[(size_t)(g + 8) * CC + ks * 8 + tig + 4] * 0.125f);
        }
    }

    float oacc[8][4];
#pragma unroll
    for (int nf = 0; nf < 8; ++nf)
#pragma unroll
        for (int e = 0; e < 4; ++e) oacc[nf][e] = 0.f;
    float m0 = -1e30f, m1 = -1e30f, l0 = 0.f, l1 = 0.f;

    const int ktmax = 2 * qt + 1;
    const float* VTb = VTg + ((size_t)(b * KVHN + kvh)) * DD * TT;

    auto prefetch = [&](int kt, int buf) {
        const float* Kb = Kg + ((size_t)(b * TT + kt * FK)) * (KVHN * DD) + kvh * DD;
        const uint32_t kd = sbase + (buf ? FW_K1 : FW_K0) * 4u;
        const uint32_t vd = sbase + (buf ? FW_V1 : FW_V0) * 4u;
#pragma unroll
        for (int i = 0; i < 4; ++i) {
            int lin = tid + i * 256;
            int r = lin >> 4, c4 = lin & 15;
            CP16(kd + (uint32_t)(r * FST + c4 * 4) * 4u, Kb + (size_t)r * (KVHN * DD) + c4 * 4);
            CP16(vd + (uint32_t)(r * FST + c4 * 4) * 4u, VTb + (size_t)r * TT + kt * FK + c4 * 4);
        }
        CP_COMMIT();
    };

    prefetch(0, 0);
    const uint32_t pw_base = sbase + (FW_P + w * 16 * FST) * 4u;
    float* Pw = sf + FW_P + w * 16 * FST;
    const uint32_t paddr = pw_base + (uint32_t)(lrowA * FST + lcolA) * 4u;

    for (int kt = 0; kt <= ktmax; ++kt) {
        const int buf = kt & 1;
        CP_WAIT0();
        __syncthreads();
        if (kt < ktmax) prefetch(kt + 1, buf ^ 1);

        const uint32_t kbase = sbase + (buf ? FW_K1 : FW_K0) * 4u;
        const uint32_t vbase = sbase + (buf ? FW_V1 : FW_V0) * 4u;

        // ---- S = Q @ K^T ----
        float sacc[8][4];
#pragma unroll
        for (int nf = 0; nf < 8; ++nf)
#pragma unroll
            for (int e = 0; e < 4; ++e) sacc[nf][e] = 0.f;

#pragma unroll
        for (int ks = 0; ks < 8; ++ks) {
            uint32_t b2[4][4];
#pragma unroll
            for (int np = 0; np < 4; ++np)
                LDMX4(b2[np][0], b2[np][1], b2[np][2], b2[np][3],
                      kbase + (uint32_t)((np * 16 + lrowB) * FST + lcolB) * 4u + ks * 32);
#pragma unroll
            for (int nf = 0; nf < 8; ++nf)
                mma_tf32(sacc[nf], qf[ks], &b2[nf >> 1][(nf & 1) * 2]);
        }

        // ---- causal mask (only last two key blocks) ----
        if (kt >= 2 * qt) {
            const int q0 = qt * FQ + w * 16 + g;
            const int q1 = q0 + 8;
#pragma unroll
            for (int nf = 0; nf < 8; ++nf) {
                const int key = kt * FK + nf * 8 + tig * 2;
                if (key     > q0) sacc[nf][0] = -1e30f;
                if (key + 1 > q0) sacc[nf][1] = -1e30f;
                if (key     > q1) sacc[nf][2] = -1e30f;
                if (key + 1 > q1) sacc[nf][3] = -1e30f;
            }
        }

        // ---- online softmax ----
        float mx0 = -1e30f, mx1 = -1e30f;
#pragma unroll
        for (int nf = 0; nf < 8; ++nf) {
            mx0 = fmaxf(mx0, fmaxf(sacc[nf][0], sacc[nf][1]));
            mx1 = fmaxf(mx1, fmaxf(sacc[nf][2], sacc[nf][3]));
        }
        mx0 = fmaxf(mx0, __shfl_xor_sync(0xffffffffu, mx0, 1));
        mx0 = fmaxf(mx0, __shfl_xor_sync(0xffffffffu, mx0, 2));
        mx1 = fmaxf(mx1, __shfl_xor_sync(0xffffffffu, mx1, 1));
        mx1 = fmaxf(mx1, __shfl_xor_sync(0xffffffffu, mx1, 2));

        const float mn0 = fmaxf(m0, mx0), mn1 = fmaxf(m1, mx1);
        const float c0 = __expf(m0 - mn0), c1 = __expf(m1 - mn1);
        float s0 = 0.f, s1 = 0.f;
#pragma unroll
        for (int nf = 0; nf < 8; ++nf) {
            sacc[nf][0] = __expf(sacc[nf][0] - mn0);
            sacc[nf][1] = __expf(sacc[nf][1] - mn0);
            sacc[nf][2] = __expf(sacc[nf][2] - mn1);
            sacc[nf][3] = __expf(sacc[nf][3] - mn1);
            s0 += sacc[nf][0] + sacc[nf][1];
            s1 += sacc[nf][2] + sacc[nf][3];
        }
        s0 += __shfl_xor_sync(0xffffffffu, s0, 1);
        s0 += __shfl_xor_sync(0xffffffffu, s0, 2);
        s1 += __shfl_xor_sync(0xffffffffu, s1, 1);
        s1 += __shfl_xor_sync(0xffffffffu, s1, 2);

        l0 = l0 * c0 + s0;  l1 = l1 * c1 + s1;
        m0 = mn0;           m1 = mn1;
#pragma unroll
        for (int nf = 0; nf < 8; ++nf) {
            oacc[nf][0] *= c0; oacc[nf][1] *= c0;
            oacc[nf][2] *= c1; oacc[nf][3] *= c1;
        }

        // ---- P -> warp-private smem (tf32-rounded bits) ----
#pragma unroll
        for (int nf = 0; nf < 8; ++nf) {
            *(float2*)(Pw + g * FST + nf * 8 + tig * 2) =
                make_float2(__uint_as_float(f2tf(sacc[nf][0])), __uint_as_float(f2tf(sacc[nf][1])));
            *(float2*)(Pw + (g + 8) * FST + nf * 8 + tig * 2) =
                make_float2(__uint_as_float(f2tf(sacc[nf][2])), __uint_as_float(f2tf(sacc[nf][3])));
        }
        __syncwarp();

        // ---- O += P @ V  (V^T smem rows = d, ldmatrix B loads) ----
#pragma unroll
        for (int ks = 0; ks < 8; ++ks) {
            uint32_t pa[4];
            LDMX4(pa[0], pa[1], pa[2], pa[3], paddr + ks * 32);
            uint32_t b2[4][4];
#pragma unroll
            for (int np = 0; np < 4; ++np)
                LDMX4(b2[np][0], b2[np][1], b2[np][2], b2[np][3],
                      vbase + (uint32_t)((np * 16 + lrowB) * FST + lcolB) * 4u + ks * 32);
#pragma unroll
            for (int nf = 0; nf < 8; ++nf)
                mma_tf32(oacc[nf], pa, &b2[nf >> 1][(nf & 1) * 2]);
        }
        __syncwarp();
    }

    // ---- epilogue: normalize, tf32-round, store ----
    float* Ob = Og + ((size_t)(b * TT + qt * FQ + w * 16)) * CC + h * DD;
    const float i0 = 1.0f / l0, i1 = 1.0f / l1;
#pragma unroll
    for (int nf = 0; nf < 8; ++nf) {
        *(float2*)(Ob + (size_t)g * CC + nf * 8 + tig * 2) =
            make_float2(__uint_as_float(f2tf(oacc[nf][0] * i0)),
                        __uint_as_float(f2tf(oacc[nf][1] * i0)));
        *(float2*)(Ob + (size_t)(g + 8) * CC + nf * 8 + tig * 2) =
            make_float2(__uint_as_float(f2tf(oacc[nf][2] * i1)),
                        __uint_as_float(f2tf(oacc[nf][3] * i1)));
    }
}

// ---------------------------------------------------------------------------
extern "C" void kernel_launch(void* const* d_in, const int* in_sizes, int n_in,
                              void* d_out, int out_size)
{
    const float* x    = (const float*)d_in[0];
    const float* Wq   = (const float*)d_in[1];
    const float* Wk   = (const float*)d_in[2];
    const float* Wv   = (const float*)d_in[3];
    const float* Wo   = (const float*)d_in[4];
    const float* cosb = (const float*)d_in[5];
    const float* sinb = (const float*)d_in[6];
    float* out = (float*)d_out;

    float *q, *k, *v, *vT, *attn, *xt, *wqt, *wkt, *wvt, *wot;
    cudaGetSymbolAddress((void**)&q,    g_q);
    cudaGetSymbolAddress((void**)&k,    g_k);
    cudaGetSymbolAddress((void**)&v,    g_v);
    cudaGetSymbolAddress((void**)&vT,   g_vT);
    cudaGetSymbolAddress((void**)&attn, g_attn);
    cudaGetSymbolAddress((void**)&xt,   g_xt);
    cudaGetSymbolAddress((void**)&wqt,  g_wqt);
    cudaGetSymbolAddress((void**)&wkt,  g_wkt);
    cudaGetSymbolAddress((void**)&wvt,  g_wvt);
    cudaGetSymbolAddress((void**)&wot,  g_wot);

    cudaFuncSetAttribute(gemm_qkv,   cudaFuncAttributeMaxDynamicSharedMemorySize, GEMM_SMEM);
    cudaFuncSetAttribute(gemm_oproj, cudaFuncAttributeMaxDynamicSharedMemorySize, GEMM_SMEM);
    cudaFuncSetAttribute(flash_mma,  cudaFuncAttributeMaxDynamicSharedMemorySize, FLASH_SMEM);

    // tf32 pre-rounding copies
    {
        const int nx  = BB * TT * CC / 4;
        const int nwq = CC * CC / 4;
        const int nwk = KVHN * DD * CC / 4;
        round_copy<<<(nx  + 255) / 256, 256>>>((const float4*)x,  (float4*)xt,  nx);
        round_copy<<<(nwq + 255) / 256, 256>>>((const float4*)Wq, (float4*)wqt, nwq);
        round_copy<<<(nwk + 255) / 256, 256>>>((const float4*)Wk, (float4*)wkt, nwk);
        round_copy<<<(nwk + 255) / 256, 256>>>((const float4*)Wv, (float4*)wvt, nwk);
        round_copy<<<(nwq + 255) / 256, 256>>>((const float4*)Wo, (float4*)wot, nwq);
    }

    // QKV projections
    gemm_qkv<<<dim3(24, 32), 256, GEMM_SMEM>>>(xt, wqt, wkt, wvt, q, k, v);

    // RoPE (q, k in place, rounded)
    {
        int total = BB * TT * (HH + KVHN) * (DD / 2);
        rope_kernel<<<(total + 255) / 256, 256>>>(q, k, cosb, sinb);
    }

    // V transpose + round
    vt_kernel<<<dim3(TT / 32, DD / 32, BB * KVHN), dim3(32, 8)>>>(v, vT);

    // Flash attention
    flash_mma<<<dim3(TT / FQ, HH, BB), 256, FLASH_SMEM>>>(q, k, vT, attn);

    // Output projection
    gemm_oproj<<<dim3(16, 32), 256, GEMM_SMEM>>>(attn, wot, out);
}

// round 8
// speedup vs baseline: 3.5904x; 1.0064x over previous
#include <cuda_runtime.h>
#include <math.h>
#include <stdint.h>

#define BB   2
#define TT   2048
#define CC   2048
#define HH   32
#define KVHN 8
#define DD   64
#define KDIM 2048

// GEMM tile config
#define GBM  128
#define GBN  128
#define GBK  32
#define NCHUNK (KDIM / GBK)       // 64
#define SSTRIDE 36
#define TILE_W (128 * SSTRIDE)
#define GEMM_SMEM (3 * 2 * TILE_W * 4)  // 3-stage: 110592 B

// Scratch (allocation-free rule: __device__ globals)
__device__ float g_q[(size_t)BB * TT * CC];
__device__ float g_k[(size_t)BB * TT * KVHN * DD];
__device__ float g_v[(size_t)BB * TT * KVHN * DD];
__device__ float g_vT[(size_t)BB * KVHN * DD * TT];
__device__ float g_attn[(size_t)BB * TT * CC];
// tf32-pre-rounded operand copies
__device__ float g_xt [(size_t)BB * TT * CC];
__device__ float g_wqt[(size_t)CC * CC];
__device__ float g_wkt[(size_t)KVHN * DD * CC];
__device__ float g_wvt[(size_t)KVHN * DD * CC];
__device__ float g_wot[(size_t)CC * CC];

// ---------------------------------------------------------------------------
// helpers
// ---------------------------------------------------------------------------
__device__ __forceinline__ uint32_t smem_u32(const void* p) {
    uint32_t r;
    asm("{ .reg .u64 t; cvta.to.shared.u64 t, %1; cvt.u32.u64 %0, t; }" : "=r"(r) : "l"(p));
    return r;
}
__device__ __forceinline__ uint32_t f2tf(float f) {
    uint32_t r;
    asm("cvt.rna.tf32.f32 %0, %1;" : "=r"(r) : "f"(f));
    return r;
}
#define CP16(dst, src) \
    asm volatile("cp.async.cg.shared.global [%0], [%1], 16;" :: "r"(dst), "l"(src))
#define CP_COMMIT() asm volatile("cp.async.commit_group;" ::: "memory")
#define CP_WAITG1() asm volatile("cp.async.wait_group 1;" ::: "memory")
#define CP_WAIT0()  asm volatile("cp.async.wait_group 0;" ::: "memory")

#define LDMX4(r0, r1, r2, r3, addr) \
    asm volatile("ldmatrix.sync.aligned.m8n8.x4.shared.b16 {%0,%1,%2,%3}, [%4];" \
        : "=r"(r0), "=r"(r1), "=r"(r2), "=r"(r3) : "r"(addr))

__device__ __forceinline__ void mma_tf32(float* d, const uint32_t* a, const uint32_t* b) {
    asm volatile(
        "mma.sync.aligned.m16n8k8.row.col.f32.tf32.tf32.f32 "
        "{%0,%1,%2,%3}, {%4,%5,%6,%7}, {%8,%9}, {%0,%1,%2,%3};"
        : "+f"(d[0]), "+f"(d[1]), "+f"(d[2]), "+f"(d[3])
        : "r"(a[0]), "r"(a[1]), "r"(a[2]), "r"(a[3]), "r"(b[0]), "r"(b[1]));
}

// ---------------------------------------------------------------------------
// Fused tf32 pre-rounding copy (x, Wq, Wk, Wv, Wo in one launch)
// ---------------------------------------------------------------------------
#define N4_X  (BB * TT * CC / 4)
#define N4_WQ (CC * CC / 4)
#define N4_WK (KVHN * DD * CC / 4)

__global__ void round_copy_all(const float4* __restrict__ x,  float4* __restrict__ xt,
                               const float4* __restrict__ wq, float4* __restrict__ wqt,
                               const float4* __restrict__ wk, float4* __restrict__ wkt,
                               const float4* __restrict__ wv, float4* __restrict__ wvt,
                               const float4* __restrict__ wo, float4* __restrict__ wot)
{
    int i = blockIdx.x * blockDim.x + threadIdx.x;
    const float4* in; float4* out; int j = i;
    if (j < N4_X)                      { in = x;  out = xt; }
    else if ((j -= N4_X) < N4_WQ)      { in = wq; out = wqt; }
    else if ((j -= N4_WQ) < N4_WK)     { in = wk; out = wkt; }
    else if ((j -= N4_WK) < N4_WK)     { in = wv; out = wvt; }
    else if ((j -= N4_WK) < N4_WQ)     { in = wo; out = wot; }
    else return;
    float4 v = in[j];
    float4 w;
    w.x = __uint_as_float(f2tf(v.x));
    w.y = __uint_as_float(f2tf(v.y));
    w.z = __uint_as_float(f2tf(v.z));
    w.w = __uint_as_float(f2tf(v.w));
    out[j] = w;
}

// ---------------------------------------------------------------------------
// V transpose + tf32 round
// ---------------------------------------------------------------------------
__global__ void vt_kernel(const float* __restrict__ v, float* __restrict__ vt)
{
    __shared__ float tile[32][33];
    const int bk = blockIdx.z;
    const int b  = bk >> 3, kvh = bk & 7;
    const int t0 = blockIdx.x * 32, d0 = blockIdx.y * 32;
    const int tx = threadIdx.x, ty = threadIdx.y;
#pragma unroll
    for (int i = 0; i < 4; ++i)
        tile[ty + i * 8][tx] =
            v[((size_t)(b * TT + t0 + ty + i * 8)) * (KVHN * DD) + kvh * DD + d0 + tx];
    __syncthreads();
#pragma unroll
    for (int i = 0; i < 4; ++i)
        vt[((size_t)(bk * DD + d0 + ty + i * 8)) * TT + t0 + tx] =
            __uint_as_float(f2tf(tile[tx][ty + i * 8]));
}

// ---------------------------------------------------------------------------
// mma.sync tf32 NT GEMM tile: 3-stage cp.async pipeline, 1 barrier/chunk,
// ldmatrix fragment loads.
// ---------------------------------------------------------------------------
__device__ __forceinline__ void gemm_mma_tile(const float* __restrict__ A,
                                              const float* __restrict__ W,
                                              float* __restrict__ Cp, int ldc)
{
    extern __shared__ float smf[];
    const uint32_t sbase = smem_u32(smf);

    const int tid  = threadIdx.x;
    const int wid  = tid >> 5, lane = tid & 31;
    const int wm   = wid & 1,  wn   = wid >> 1;
    const int g    = lane >> 2, tig = lane & 3;

    const int lrowA = lane & 15;
    const int lcolA = (lane >> 4) * 4;
    const int lrowB = (lane & 7) + ((lane >> 4) << 3);
    const int lcolB = (lane & 8) ? 4 : 0;

    float acc[4][4][4];
#pragma unroll
    for (int i = 0; i < 4; ++i)
#pragma unroll
        for (int j = 0; j < 4; ++j)
#pragma unroll
            for (int e = 0; e < 4; ++e) acc[i][j][e] = 0.f;

    auto load_chunk = [&](int c, int buf) {
        const float* Ab = A + c * GBK;
        const float* Wb = W + c * GBK;
        const uint32_t da = sbase + (uint32_t)buf * 2u * TILE_W * 4u;
        const uint32_t db = da + TILE_W * 4u;
#pragma unroll
        for (int i = 0; i < 4; ++i) {
            int lin = tid + i * 256;
            int r = lin >> 3, c4 = lin & 7;
            CP16(da + (uint32_t)(r * SSTRIDE + c4 * 4) * 4u,
                 Ab + (size_t)r * KDIM + c4 * 4);
        }
#pragma unroll
        for (int i = 0; i < 4; ++i) {
            int lin = tid + i * 256;
            int r = lin >> 3, c4 = lin & 7;
            CP16(db + (uint32_t)(r * SSTRIDE + c4 * 4) * 4u,
                 Wb + (size_t)r * KDIM + c4 * 4);
        }
        CP_COMMIT();
    };

    auto compute = [&](int buf) {
        const uint32_t abase = sbase + (uint32_t)buf * 2u * TILE_W * 4u;
        const uint32_t bbase = abase + TILE_W * 4u;
        uint32_t aaddr[4], baddr[2];
#pragma unroll
        for (int mf = 0; mf < 4; ++mf)
            aaddr[mf] = abase + (uint32_t)((wm * 64 + mf * 16 + lrowA) * SSTRIDE + lcolA) * 4u;
#pragma unroll
        for (int np = 0; np < 2; ++np)
            baddr[np] = bbase + (uint32_t)((wn * 32 + np * 16 + lrowB) * SSTRIDE + lcolB) * 4u;

#pragma unroll
        for (int ks = 0; ks < 4; ++ks) {
            uint32_t a[4][4], b2[2][4];
#pragma unroll
            for (int mf = 0; mf < 4; ++mf)
                LDMX4(a[mf][0], a[mf][1], a[mf][2], a[mf][3], aaddr[mf] + ks * 32);
#pragma unroll
            for (int np = 0; np < 2; ++np)
                LDMX4(b2[np][0], b2[np][1], b2[np][2], b2[np][3], baddr[np] + ks * 32);
#pragma unroll
            for (int mf = 0; mf < 4; ++mf)
#pragma unroll
                for (int nf = 0; nf < 4; ++nf)
                    mma_tf32(acc[mf][nf], a[mf], &b2[nf >> 1][(nf & 1) * 2]);
        }
    };

    // 3-stage pipeline: one barrier per chunk
    load_chunk(0, 0);
    load_chunk(1, 1);
    int buf = 0;
    for (int c = 0; c < NCHUNK; ++c) {
        if (c + 1 < NCHUNK) CP_WAITG1();   // chunk c complete (c+1 may stay in flight)
        else                CP_WAIT0();
        __syncthreads();                   // data visible + buffer (c-1) consumed by all
        if (c + 2 < NCHUNK) load_chunk(c + 2, (buf + 2) % 3);
        compute(buf);
        buf = (buf + 1) % 3;
    }

#pragma unroll
    for (int mf = 0; mf < 4; ++mf) {
        const int r0 = wm * 64 + mf * 16 + g;
#pragma unroll
        for (int nf = 0; nf < 4; ++nf) {
            const int c0 = wn * 32 + nf * 8 + tig * 2;
            *(float2*)(Cp + (size_t)r0 * ldc + c0)       = make_float2(acc[mf][nf][0], acc[mf][nf][1]);
            *(float2*)(Cp + (size_t)(r0 + 8) * ldc + c0) = make_float2(acc[mf][nf][2], acc[mf][nf][3]);
        }
    }
}

__global__ void __launch_bounds__(256, 2)
gemm_qkv(const float* __restrict__ x,
         const float* __restrict__ Wq, const float* __restrict__ Wk, const float* __restrict__ Wv,
         float* __restrict__ q, float* __restrict__ k, float* __restrict__ v)
{
    const int nt = blockIdx.x;
    const int bm = blockIdx.y * GBM;
    const float* W; float* C; int ldc, cn;
    if (nt < 16)      { W = Wq; C = q; ldc = CC;        cn = nt * GBN; }
    else if (nt < 20) { W = Wk; C = k; ldc = KVHN * DD; cn = (nt - 16) * GBN; }
    else              { W = Wv; C = v; ldc = KVHN * DD; cn = (nt - 20) * GBN; }
    gemm_mma_tile(x + (size_t)bm * KDIM, W + (size_t)cn * KDIM,
                  C + (size_t)bm * ldc + cn, ldc);
}

__global__ void __launch_bounds__(256, 2)
gemm_oproj(const float* __restrict__ A, const float* __restrict__ W, float* __restrict__ C)
{
    const int bm = blockIdx.y * GBM;
    const int bn = blockIdx.x * GBN;
    gemm_mma_tile(A + (size_t)bm * KDIM, W + (size_t)bn * KDIM,
                  C + (size_t)bm * CC + bn, CC);
}

// ---------------------------------------------------------------------------
// RoPE in place on q, k (outputs tf32-rounded).
// ---------------------------------------------------------------------------
__global__ void rope_kernel(float* __restrict__ q, float* __restrict__ k,
                            const float* __restrict__ cosb, const float* __restrict__ sinb)
{
    const int halfs_q = BB * TT * HH * (DD / 2);
    const int halfs_k = BB * TT * KVHN * (DD / 2);
    int idx = blockIdx.x * blockDim.x + threadIdx.x;
    if (idx < halfs_q) {
        int d   = idx & 31;
        int h   = (idx >> 5) & (HH - 1);
        int row = idx >> 10;
        int t   = row & (TT - 1);
        float* p = q + (size_t)row * CC + h * DD;
        float c1 = cosb[t * DD + d],      s1 = sinb[t * DD + d];
        float c2 = cosb[t * DD + d + 32], s2 = sinb[t * DD + d + 32];
        float a = p[d], b2 = p[d + 32];
        p[d]      = __uint_as_float(f2tf(a * c1 - b2 * s1));
        p[d + 32] = __uint_as_float(f2tf(b2 * c2 + a * s2));
    } else if (idx < halfs_q + halfs_k) {
        int j   = idx - halfs_q;
        int d   = j & 31;
        int h   = (j >> 5) & (KVHN - 1);
        int row = j >> 8;
        int t   = row & (TT - 1);
        float* p = k + (size_t)row * (KVHN * DD) + h * DD;
        float c1 = cosb[t * DD + d],      s1 = sinb[t * DD + d];
        float c2 = cosb[t * DD + d + 32], s2 = sinb[t * DD + d + 32];
        float a = p[d], b2 = p[d + 32];
        p[d]      = __uint_as_float(f2tf(a * c1 - b2 * s1));
        p[d + 32] = __uint_as_float(f2tf(b2 * c2 + a * s2));
    }
}

// ---------------------------------------------------------------------------
// Tensor-core flash attention with ldmatrix loads. Causal, GQA G=4, D=64.
// ---------------------------------------------------------------------------
#define FQ 128
#define FK 64
#define FST 68
#define FW_K0  0
#define FW_K1  (64 * FST)
#define FW_V0  (2 * 64 * FST)
#define FW_V1  (3 * 64 * FST)
#define FW_P   (4 * 64 * FST)
#define FLASH_SMEM ((4 * 64 * FST + 128 * FST) * 4)   // 104448 B

__global__ void __launch_bounds__(256)
flash_mma(const float* __restrict__ Qg, const float* __restrict__ Kg,
          const float* __restrict__ VTg, float* __restrict__ Og)
{
    extern __shared__ float sf[];
    const uint32_t sbase = smem_u32(sf);

    const int qt  = blockIdx.x;
    const int h   = blockIdx.y;
    const int b   = blockIdx.z;
    const int kvh = h >> 2;
    const int tid = threadIdx.x;
    const int w   = tid >> 5, lane = tid & 31;
    const int g   = lane >> 2, tig = lane & 3;

    const int lrowA = lane & 15;
    const int lcolA = (lane >> 4) * 4;
    const int lrowB = (lane & 7) + ((lane >> 4) << 3);
    const int lcolB = (lane & 8) ? 4 : 0;

    uint32_t qf[8][4];
    {
        const float* Qb = Qg + ((size_t)(b * TT + qt * FQ + w * 16)) * CC + h * DD;
#pragma unroll
        for (int ks = 0; ks < 8; ++ks) {
            qf[ks][0] = __float_as_uint(Qb[(size_t)g * CC + ks * 8 + tig] * 0.125f);
            qf[ks][1] = __float_as_uint(Qb[(size_t)(g + 8) * CC + ks * 8 + tig] * 0.125f);
            qf[ks][2] = __float_as_uint(Qb[(size_t)g * CC + ks * 8 + tig + 4] * 0.125f);
            qf[ks][3] = __float_as_uint(Qb[(size_t)(g + 8) * CC + ks * 8 + tig + 4] * 0.125f);
        }
    }

    float oacc[8][4];
#pragma unroll
    for (int nf = 0; nf < 8; ++nf)
#pragma unroll
        for (int e = 0; e < 4; ++e) oacc[nf][e] = 0.f;
    float m0 = -1e30f, m1 = -1e30f, l0 = 0.f, l1 = 0.f;

    const int ktmax = 2 * qt + 1;
    const float* VTb = VTg + ((size_t)(b * KVHN + kvh)) * DD * TT;

    auto prefetch = [&](int kt, int buf) {
        const float* Kb = Kg + ((size_t)(b * TT + kt * FK)) * (KVHN * DD) + kvh * DD;
        const uint32_t kd = sbase + (buf ? FW_K1 : FW_K0) * 4u;
        const uint32_t vd = sbase + (buf ? FW_V1 : FW_V0) * 4u;
#pragma unroll
        for (int i = 0; i < 4; ++i) {
            int lin = tid + i * 256;
            int r = lin >> 4, c4 = lin & 15;
            CP16(kd + (uint32_t)(r * FST + c4 * 4) * 4u, Kb + (size_t)r * (KVHN * DD) + c4 * 4);
            CP16(vd + (uint32_t)(r * FST + c4 * 4) * 4u, VTb + (size_t)r * TT + kt * FK + c4 * 4);
        }
        CP_COMMIT();
    };

    prefetch(0, 0);
    const uint32_t pw_base = sbase + (FW_P + w * 16 * FST) * 4u;
    float* Pw = sf + FW_P + w * 16 * FST;
    const uint32_t paddr = pw_base + (uint32_t)(lrowA * FST + lcolA) * 4u;

    for (int kt = 0; kt <= ktmax; ++kt) {
        const int buf = kt & 1;
        CP_WAIT0();
        __syncthreads();
        if (kt < ktmax) prefetch(kt + 1, buf ^ 1);

        const uint32_t kbase = sbase + (buf ? FW_K1 : FW_K0) * 4u;
        const uint32_t vbase = sbase + (buf ? FW_V1 : FW_V0) * 4u;

        // ---- S = Q @ K^T ----
        float sacc[8][4];
#pragma unroll
        for (int nf = 0; nf < 8; ++nf)
#pragma unroll
            for (int e = 0; e < 4; ++e) sacc[nf][e] = 0.f;

#pragma unroll
        for (int ks = 0; ks < 8; ++ks) {
            uint32_t b2[4][4];
#pragma unroll
            for (int np = 0; np < 4; ++np)
                LDMX4(b2[np][0], b2[np][1], b2[np][2], b2[np][3],
                      kbase + (uint32_t)((np * 16 + lrowB) * FST + lcolB) * 4u + ks * 32);
#pragma unroll
            for (int nf = 0; nf < 8; ++nf)
                mma_tf32(sacc[nf], qf[ks], &b2[nf >> 1][(nf & 1) * 2]);
        }

        if (kt >= 2 * qt) {
            const int q0 = qt * FQ + w * 16 + g;
            const int q1 = q0 + 8;
#pragma unroll
            for (int nf = 0; nf < 8; ++nf) {
                const int key = kt * FK + nf * 8 + tig * 2;
                if (key     > q0) sacc[nf][0] = -1e30f;
                if (key + 1 > q0) sacc[nf][1] = -1e30f;
                if (key     > q1) sacc[nf][2] = -1e30f;
                if (key + 1 > q1) sacc[nf][3] = -1e30f;
            }
        }

        // ---- online softmax ----
        float mx0 = -1e30f, mx1 = -1e30f;
#pragma unroll
        for (int nf = 0; nf < 8; ++nf) {
            mx0 = fmaxf(mx0, fmaxf(sacc[nf][0], sacc[nf][1]));
            mx1 = fmaxf(mx1, fmaxf(sacc[nf][2], sacc[nf][3]));
        }
        mx0 = fmaxf(mx0, __shfl_xor_sync(0xffffffffu, mx0, 1));
        mx0 = fmaxf(mx0, __shfl_xor_sync(0xffffffffu, mx0, 2));
        mx1 = fmaxf(mx1, __shfl_xor_sync(0xffffffffu, mx1, 1));
        mx1 = fmaxf(mx1, __shfl_xor_sync(0xffffffffu, mx1, 2));

        const float mn0 = fmaxf(m0, mx0), mn1 = fmaxf(m1, mx1);
        const float c0 = __expf(m0 - mn0), c1 = __expf(m1 - mn1);
        float s0 = 0.f, s1 = 0.f;
#pragma unroll
        for (int nf = 0; nf < 8; ++nf) {
            sacc[nf][0] = __expf(sacc[nf][0] - mn0);
            sacc[nf][1] = __expf(sacc[nf][1] - mn0);
            sacc[nf][2] = __expf(sacc[nf][2] - mn1);
            sacc[nf][3] = __expf(sacc[nf][3] - mn1);
            s0 += sacc[nf][0] + sacc[nf][1];
            s1 += sacc[nf][2] + sacc[nf][3];
        }
        s0 += __shfl_xor_sync(0xffffffffu, s0, 1);
        s0 += __shfl_xor_sync(0xffffffffu, s0, 2);
        s1 += __shfl_xor_sync(0xffffffffu, s1, 1);
        s1 += __shfl_xor_sync(0xffffffffu, s1, 2);

        l0 = l0 * c0 + s0;  l1 = l1 * c1 + s1;
        m0 = mn0;           m1 = mn1;
#pragma unroll
        for (int nf = 0; nf < 8; ++nf) {
            oacc[nf][0] *= c0; oacc[nf][1] *= c0;
            oacc[nf][2] *= c1; oacc[nf][3] *= c1;
        }

        // ---- P -> warp-private smem ----
#pragma unroll
        for (int nf = 0; nf < 8; ++nf) {
            *(float2*)(Pw + g * FST + nf * 8 + tig * 2) =
                make_float2(__uint_as_float(f2tf(sacc[nf][0])), __uint_as_float(f2tf(sacc[nf][1])));
            *(float2*)(Pw + (g + 8) * FST + nf * 8 + tig * 2) =
                make_float2(__uint_as_float(f2tf(sacc[nf][2])), __uint_as_float(f2tf(sacc[nf][3])));
        }
        __syncwarp();

        // ---- O += P @ V ----
#pragma unroll
        for (int ks = 0; ks < 8; ++ks) {
            uint32_t pa[4];
            LDMX4(pa[0], pa[1], pa[2], pa[3], paddr + ks * 32);
            uint32_t b2[4][4];
#pragma unroll
            for (int np = 0; np < 4; ++np)
                LDMX4(b2[np][0], b2[np][1], b2[np][2], b2[np][3],
                      vbase + (uint32_t)((np * 16 + lrowB) * FST + lcolB) * 4u + ks * 32);
#pragma unroll
            for (int nf = 0; nf < 8; ++nf)
                mma_tf32(oacc[nf], pa, &b2[nf >> 1][(nf & 1) * 2]);
        }
        __syncwarp();
    }

    // ---- epilogue ----
    float* Ob = Og + ((size_t)(b * TT + qt * FQ + w * 16)) * CC + h * DD;
    const float i0 = 1.0f / l0, i1 = 1.0f / l1;
#pragma unroll
    for (int nf = 0; nf < 8; ++nf) {
        *(float2*)(Ob + (size_t)g * CC + nf * 8 + tig * 2) =
            make_float2(__uint_as_float(f2tf(oacc[nf][0] * i0)),
                        __uint_as_float(f2tf(oacc[nf][1] * i0)));
        *(float2*)(Ob + (size_t)(g + 8) * CC + nf * 8 + tig * 2) =
            make_float2(__uint_as_float(f2tf(oacc[nf][2] * i1)),
                        __uint_as_float(f2tf(oacc[nf][3] * i1)));
    }
}

// ---------------------------------------------------------------------------
extern "C" void kernel_launch(void* const* d_in, const int* in_sizes, int n_in,
                              void* d_out, int out_size)
{
    const float* x    = (const float*)d_in[0];
    const float* Wq   = (const float*)d_in[1];
    const float* Wk   = (const float*)d_in[2];
    const float* Wv   = (const float*)d_in[3];
    const float* Wo   = (const float*)d_in[4];
    const float* cosb = (const float*)d_in[5];
    const float* sinb = (const float*)d_in[6];
    float* out = (float*)d_out;

    float *q, *k, *v, *vT, *attn, *xt, *wqt, *wkt, *wvt, *wot;
    cudaGetSymbolAddress((void**)&q,    g_q);
    cudaGetSymbolAddress((void**)&k,    g_k);
    cudaGetSymbolAddress((void**)&v,    g_v);
    cudaGetSymbolAddress((void**)&vT,   g_vT);
    cudaGetSymbolAddress((void**)&attn, g_attn);
    cudaGetSymbolAddress((void**)&xt,   g_xt);
    cudaGetSymbolAddress((void**)&wqt,  g_wqt);
    cudaGetSymbolAddress((void**)&wkt,  g_wkt);
    cudaGetSymbolAddress((void**)&wvt,  g_wvt);
    cudaGetSymbolAddress((void**)&wot,  g_wot);

    cudaFuncSetAttribute(gemm_qkv,   cudaFuncAttributeMaxDynamicSharedMemorySize, GEMM_SMEM);
    cudaFuncSetAttribute(gemm_oproj, cudaFuncAttributeMaxDynamicSharedMemorySize, GEMM_SMEM);
    cudaFuncSetAttribute(flash_mma,  cudaFuncAttributeMaxDynamicSharedMemorySize, FLASH_SMEM);

    // tf32 pre-rounding copies (fused into one launch)
    {
        const int total = N4_X + 2 * N4_WQ + 2 * N4_WK;
        round_copy_all<<<(total + 255) / 256, 256>>>(
            (const float4*)x,  (float4*)xt,
            (const float4*)Wq, (float4*)wqt,
            (const float4*)Wk, (float4*)wkt,
            (const float4*)Wv, (float4*)wvt,
            (const float4*)Wo, (float4*)wot);
    }

    // QKV projections (3-stage pipeline)
    gemm_qkv<<<dim3(24, 32), 256, GEMM_SMEM>>>(xt, wqt, wkt, wvt, q, k, v);

    // RoPE (q, k in place, rounded)
    {
        int total = BB * TT * (HH + KVHN) * (DD / 2);
        rope_kernel<<<(total + 255) / 256, 256>>>(q, k, cosb, sinb);
    }

    // V transpose + round
    vt_kernel<<<dim3(TT / 32, DD / 32, BB * KVHN), dim3(32, 8)>>>(v, vT);

    // Flash attention
    flash_mma<<<dim3(TT / FQ, HH, BB), 256, FLASH_SMEM>>>(q, k, vT, attn);

    // Output projection (3-stage pipeline)
    gemm_oproj<<<dim3(16, 32), 256, GEMM_SMEM>>>(attn, wot, out);
}

// round 9
// speedup vs baseline: 3.7923x; 1.0562x over previous
#include <cuda_runtime.h>
#include <math.h>
#include <stdint.h>

#define BB   2
#define TT   2048
#define CC   2048
#define HH   32
#define KVHN 8
#define DD   64
#define KDIM 2048

// GEMM tile config
#define GBM  128
#define GBN  128
#define GBK  32
#define NCHUNK (KDIM / GBK)       // 64
#define SSTRIDE 36
#define TILE_W (128 * SSTRIDE)
#define GEMM_SMEM (3 * 2 * TILE_W * 4)  // 3-stage: 110592 B

// Scratch (allocation-free rule: __device__ globals)
__device__ float g_q[(size_t)BB * TT * CC];
__device__ float g_k[(size_t)BB * TT * KVHN * DD];
__device__ float g_v[(size_t)BB * TT * KVHN * DD];
__device__ float g_vT[(size_t)BB * KVHN * DD * TT];
__device__ float g_attn[(size_t)BB * TT * CC];
// tf32-pre-rounded operand copies
__device__ float g_xt [(size_t)BB * TT * CC];
__device__ float g_wqt[(size_t)CC * CC];
__device__ float g_wkt[(size_t)KVHN * DD * CC];
__device__ float g_wvt[(size_t)KVHN * DD * CC];
__device__ float g_wot[(size_t)CC * CC];

// ---------------------------------------------------------------------------
// helpers
// ---------------------------------------------------------------------------
__device__ __forceinline__ uint32_t smem_u32(const void* p) {
    uint32_t r;
    asm("{ .reg .u64 t; cvta.to.shared.u64 t, %1; cvt.u32.u64 %0, t; }" : "=r"(r) : "l"(p));
    return r;
}
__device__ __forceinline__ uint32_t f2tf(float f) {
    uint32_t r;
    asm("cvt.rna.tf32.f32 %0, %1;" : "=r"(r) : "f"(f));
    return r;
}
#define CP16(dst, src) \
    asm volatile("cp.async.cg.shared.global [%0], [%1], 16;" :: "r"(dst), "l"(src))
#define CP_COMMIT() asm volatile("cp.async.commit_group;" ::: "memory")
#define CP_WAITG1() asm volatile("cp.async.wait_group 1;" ::: "memory")
#define CP_WAIT0()  asm volatile("cp.async.wait_group 0;" ::: "memory")

#define LDMX4(r0, r1, r2, r3, addr) \
    asm volatile("ldmatrix.sync.aligned.m8n8.x4.shared.b16 {%0,%1,%2,%3}, [%4];" \
        : "=r"(r0), "=r"(r1), "=r"(r2), "=r"(r3) : "r"(addr))

__device__ __forceinline__ void mma_tf32(float* d, const uint32_t* a, const uint32_t* b) {
    asm volatile(
        "mma.sync.aligned.m16n8k8.row.col.f32.tf32.tf32.f32 "
        "{%0,%1,%2,%3}, {%4,%5,%6,%7}, {%8,%9}, {%0,%1,%2,%3};"
        : "+f"(d[0]), "+f"(d[1]), "+f"(d[2]), "+f"(d[3])
        : "r"(a[0]), "r"(a[1]), "r"(a[2]), "r"(a[3]), "r"(b[0]), "r"(b[1]));
}

// ---------------------------------------------------------------------------
// Fused tf32 pre-rounding copy (x, Wq, Wk, Wv, Wo in one launch)
// ---------------------------------------------------------------------------
#define N4_X  (BB * TT * CC / 4)
#define N4_WQ (CC * CC / 4)
#define N4_WK (KVHN * DD * CC / 4)

__global__ void round_copy_all(const float4* __restrict__ x,  float4* __restrict__ xt,
                               const float4* __restrict__ wq, float4* __restrict__ wqt,
                               const float4* __restrict__ wk, float4* __restrict__ wkt,
                               const float4* __restrict__ wv, float4* __restrict__ wvt,
                               const float4* __restrict__ wo, float4* __restrict__ wot)
{
    int i = blockIdx.x * blockDim.x + threadIdx.x;
    const float4* in; float4* out; int j = i;
    if (j < N4_X)                      { in = x;  out = xt; }
    else if ((j -= N4_X) < N4_WQ)      { in = wq; out = wqt; }
    else if ((j -= N4_WQ) < N4_WK)     { in = wk; out = wkt; }
    else if ((j -= N4_WK) < N4_WK)     { in = wv; out = wvt; }
    else if ((j -= N4_WK) < N4_WQ)     { in = wo; out = wot; }
    else return;
    float4 v = in[j];
    float4 w;
    w.x = __uint_as_float(f2tf(v.x));
    w.y = __uint_as_float(f2tf(v.y));
    w.z = __uint_as_float(f2tf(v.z));
    w.w = __uint_as_float(f2tf(v.w));
    out[j] = w;
}

// ---------------------------------------------------------------------------
// V transpose + tf32 round
// ---------------------------------------------------------------------------
__global__ void vt_kernel(const float* __restrict__ v, float* __restrict__ vt)
{
    __shared__ float tile[32][33];
    const int bk = blockIdx.z;
    const int b  = bk >> 3, kvh = bk & 7;
    const int t0 = blockIdx.x * 32, d0 = blockIdx.y * 32;
    const int tx = threadIdx.x, ty = threadIdx.y;
#pragma unroll
    for (int i = 0; i < 4; ++i)
        tile[ty + i * 8][tx] =
            v[((size_t)(b * TT + t0 + ty + i * 8)) * (KVHN * DD) + kvh * DD + d0 + tx];
    __syncthreads();
#pragma unroll
    for (int i = 0; i < 4; ++i)
        vt[((size_t)(bk * DD + d0 + ty + i * 8)) * TT + t0 + tx] =
            __uint_as_float(f2tf(tile[tx][ty + i * 8]));
}

// ---------------------------------------------------------------------------
// mma.sync tf32 NT GEMM tile: 3-stage cp.async pipeline, ldmatrix loads.
// ---------------------------------------------------------------------------
__device__ __forceinline__ void gemm_mma_tile(const float* __restrict__ A,
                                              const float* __restrict__ W,
                                              float* __restrict__ Cp, int ldc)
{
    extern __shared__ float smf[];
    const uint32_t sbase = smem_u32(smf);

    const int tid  = threadIdx.x;
    const int wid  = tid >> 5, lane = tid & 31;
    const int wm   = wid & 1,  wn   = wid >> 1;
    const int g    = lane >> 2, tig = lane & 3;

    const int lrowA = lane & 15;
    const int lcolA = (lane >> 4) * 4;
    const int lrowB = (lane & 7) + ((lane >> 4) << 3);
    const int lcolB = (lane & 8) ? 4 : 0;

    float acc[4][4][4];
#pragma unroll
    for (int i = 0; i < 4; ++i)
#pragma unroll
        for (int j = 0; j < 4; ++j)
#pragma unroll
            for (int e = 0; e < 4; ++e) acc[i][j][e] = 0.f;

    auto load_chunk = [&](int c, int buf) {
        const float* Ab = A + c * GBK;
        const float* Wb = W + c * GBK;
        const uint32_t da = sbase + (uint32_t)buf * 2u * TILE_W * 4u;
        const uint32_t db = da + TILE_W * 4u;
#pragma unroll
        for (int i = 0; i < 4; ++i) {
            int lin = tid + i * 256;
            int r = lin >> 3, c4 = lin & 7;
            CP16(da + (uint32_t)(r * SSTRIDE + c4 * 4) * 4u,
                 Ab + (size_t)r * KDIM + c4 * 4);
        }
#pragma unroll
        for (int i = 0; i < 4; ++i) {
            int lin = tid + i * 256;
            int r = lin >> 3, c4 = lin & 7;
            CP16(db + (uint32_t)(r * SSTRIDE + c4 * 4) * 4u,
                 Wb + (size_t)r * KDIM + c4 * 4);
        }
        CP_COMMIT();
    };

    auto compute = [&](int buf) {
        const uint32_t abase = sbase + (uint32_t)buf * 2u * TILE_W * 4u;
        const uint32_t bbase = abase + TILE_W * 4u;
        uint32_t aaddr[4], baddr[2];
#pragma unroll
        for (int mf = 0; mf < 4; ++mf)
            aaddr[mf] = abase + (uint32_t)((wm * 64 + mf * 16 + lrowA) * SSTRIDE + lcolA) * 4u;
#pragma unroll
        for (int np = 0; np < 2; ++np)
            baddr[np] = bbase + (uint32_t)((wn * 32 + np * 16 + lrowB) * SSTRIDE + lcolB) * 4u;

#pragma unroll
        for (int ks = 0; ks < 4; ++ks) {
            uint32_t a[4][4], b2[2][4];
#pragma unroll
            for (int mf = 0; mf < 4; ++mf)
                LDMX4(a[mf][0], a[mf][1], a[mf][2], a[mf][3], aaddr[mf] + ks * 32);
#pragma unroll
            for (int np = 0; np < 2; ++np)
                LDMX4(b2[np][0], b2[np][1], b2[np][2], b2[np][3], baddr[np] + ks * 32);
#pragma unroll
            for (int mf = 0; mf < 4; ++mf)
#pragma unroll
                for (int nf = 0; nf < 4; ++nf)
                    mma_tf32(acc[mf][nf], a[mf], &b2[nf >> 1][(nf & 1) * 2]);
        }
    };

    load_chunk(0, 0);
    load_chunk(1, 1);
    int buf = 0;
    for (int c = 0; c < NCHUNK; ++c) {
        if (c + 1 < NCHUNK) CP_WAITG1();
        else                CP_WAIT0();
        __syncthreads();
        if (c + 2 < NCHUNK) load_chunk(c + 2, (buf + 2) % 3);
        compute(buf);
        buf = (buf + 1) % 3;
    }

#pragma unroll
    for (int mf = 0; mf < 4; ++mf) {
        const int r0 = wm * 64 + mf * 16 + g;
#pragma unroll
        for (int nf = 0; nf < 4; ++nf) {
            const int c0 = wn * 32 + nf * 8 + tig * 2;
            *(float2*)(Cp + (size_t)r0 * ldc + c0)       = make_float2(acc[mf][nf][0], acc[mf][nf][1]);
            *(float2*)(Cp + (size_t)(r0 + 8) * ldc + c0) = make_float2(acc[mf][nf][2], acc[mf][nf][3]);
        }
    }
}

__global__ void __launch_bounds__(256, 2)
gemm_qkv(const float* __restrict__ x,
         const float* __restrict__ Wq, const float* __restrict__ Wk, const float* __restrict__ Wv,
         float* __restrict__ q, float* __restrict__ k, float* __restrict__ v)
{
    const int nt = blockIdx.x;
    const int bm = blockIdx.y * GBM;
    const float* W; float* C; int ldc, cn;
    if (nt < 16)      { W = Wq; C = q; ldc = CC;        cn = nt * GBN; }
    else if (nt < 20) { W = Wk; C = k; ldc = KVHN * DD; cn = (nt - 16) * GBN; }
    else              { W = Wv; C = v; ldc = KVHN * DD; cn = (nt - 20) * GBN; }
    gemm_mma_tile(x + (size_t)bm * KDIM, W + (size_t)cn * KDIM,
                  C + (size_t)bm * ldc + cn, ldc);
}

__global__ void __launch_bounds__(256, 2)
gemm_oproj(const float* __restrict__ A, const float* __restrict__ W, float* __restrict__ C)
{
    const int bm = blockIdx.y * GBM;
    const int bn = blockIdx.x * GBN;
    gemm_mma_tile(A + (size_t)bm * KDIM, W + (size_t)bn * KDIM,
                  C + (size_t)bm * CC + bn, CC);
}

// ---------------------------------------------------------------------------
// RoPE in place on q, k (outputs tf32-rounded).
// ---------------------------------------------------------------------------
__global__ void rope_kernel(float* __restrict__ q, float* __restrict__ k,
                            const float* __restrict__ cosb, const float* __restrict__ sinb)
{
    const int halfs_q = BB * TT * HH * (DD / 2);
    const int halfs_k = BB * TT * KVHN * (DD / 2);
    int idx = blockIdx.x * blockDim.x + threadIdx.x;
    if (idx < halfs_q) {
        int d   = idx & 31;
        int h   = (idx >> 5) & (HH - 1);
        int row = idx >> 10;
        int t   = row & (TT - 1);
        float* p = q + (size_t)row * CC + h * DD;
        float c1 = cosb[t * DD + d],      s1 = sinb[t * DD + d];
        float c2 = cosb[t * DD + d + 32], s2 = sinb[t * DD + d + 32];
        float a = p[d], b2 = p[d + 32];
        p[d]      = __uint_as_float(f2tf(a * c1 - b2 * s1));
        p[d + 32] = __uint_as_float(f2tf(b2 * c2 + a * s2));
    } else if (idx < halfs_q + halfs_k) {
        int j   = idx - halfs_q;
        int d   = j & 31;
        int h   = (j >> 5) & (KVHN - 1);
        int row = j >> 8;
        int t   = row & (TT - 1);
        float* p = k + (size_t)row * (KVHN * DD) + h * DD;
        float c1 = cosb[t * DD + d],      s1 = sinb[t * DD + d];
        float c2 = cosb[t * DD + d + 32], s2 = sinb[t * DD + d + 32];
        float a = p[d], b2 = p[d + 32];
        p[d]      = __uint_as_float(f2tf(a * c1 - b2 * s1));
        p[d + 32] = __uint_as_float(f2tf(b2 * c2 + a * s2));
    }
}

// ---------------------------------------------------------------------------
// Tensor-core flash attention with ldmatrix loads. Causal, GQA G=4, D=64.
// __launch_bounds__(256, 2): cap 128 regs -> 2 CTAs/SM (16 warps).
// Heavy-first block order: qt = nQT-1 - blockIdx.x.
// ---------------------------------------------------------------------------
#define FQ 128
#define FK 64
#define FST 68
#define FW_K0  0
#define FW_K1  (64 * FST)
#define FW_V0  (2 * 64 * FST)
#define FW_V1  (3 * 64 * FST)
#define FW_P   (4 * 64 * FST)
#define FLASH_SMEM ((4 * 64 * FST + 128 * FST) * 4)   // 104448 B

__global__ void __launch_bounds__(256, 2)
flash_mma(const float* __restrict__ Qg, const float* __restrict__ Kg,
          const float* __restrict__ VTg, float* __restrict__ Og)
{
    extern __shared__ float sf[];
    const uint32_t sbase = smem_u32(sf);

    const int qt  = (TT / FQ - 1) - blockIdx.x;   // largest-work blocks first
    const int h   = blockIdx.y;
    const int b   = blockIdx.z;
    const int kvh = h >> 2;
    const int tid = threadIdx.x;
    const int w   = tid >> 5, lane = tid & 31;
    const int g   = lane >> 2, tig = lane & 3;

    const int lrowA = lane & 15;
    const int lcolA = (lane >> 4) * 4;
    const int lrowB = (lane & 7) + ((lane >> 4) << 3);
    const int lcolB = (lane & 8) ? 4 : 0;

    uint32_t qf[8][4];
    {
        const float* Qb = Qg + ((size_t)(b * TT + qt * FQ + w * 16)) * CC + h * DD;
#pragma unroll
        for (int ks = 0; ks < 8; ++ks) {
            qf[ks][0] = __float_as_uint(Qb[(size_t)g * CC + ks * 8 + tig] * 0.125f);
            qf[ks][1] = __float_as_uint(Qb[(size_t)(g + 8) * CC + ks * 8 + tig] * 0.125f);
            qf[ks][2] = __float_as_uint(Qb[(size_t)g * CC + ks * 8 + tig + 4] * 0.125f);
            qf[ks][3] = __float_as_uint(Qb[(size_t)(g + 8) * CC + ks * 8 + tig + 4] * 0.125f);
        }
    }

    float oacc[8][4];
#pragma unroll
    for (int nf = 0; nf < 8; ++nf)
#pragma unroll
        for (int e = 0; e < 4; ++e) oacc[nf][e] = 0.f;
    float m0 = -1e30f, m1 = -1e30f, l0 = 0.f, l1 = 0.f;

    const int ktmax = 2 * qt + 1;
    const float* VTb = VTg + ((size_t)(b * KVHN + kvh)) * DD * TT;

    auto prefetch = [&](int kt, int buf) {
        const float* Kb = Kg + ((size_t)(b * TT + kt * FK)) * (KVHN * DD) + kvh * DD;
        const uint32_t kd = sbase + (buf ? FW_K1 : FW_K0) * 4u;
        const uint32_t vd = sbase + (buf ? FW_V1 : FW_V0) * 4u;
#pragma unroll
        for (int i = 0; i < 4; ++i) {
            int lin = tid + i * 256;
            int r = lin >> 4, c4 = lin & 15;
            CP16(kd + (uint32_t)(r * FST + c4 * 4) * 4u, Kb + (size_t)r * (KVHN * DD) + c4 * 4);
            CP16(vd + (uint32_t)(r * FST + c4 * 4) * 4u, VTb + (size_t)r * TT + kt * FK + c4 * 4);
        }
        CP_COMMIT();
    };

    prefetch(0, 0);
    const uint32_t pw_base = sbase + (FW_P + w * 16 * FST) * 4u;
    float* Pw = sf + FW_P + w * 16 * FST;
    const uint32_t paddr = pw_base + (uint32_t)(lrowA * FST + lcolA) * 4u;

    for (int kt = 0; kt <= ktmax; ++kt) {
        const int buf = kt & 1;
        CP_WAIT0();
        __syncthreads();
        if (kt < ktmax) prefetch(kt + 1, buf ^ 1);

        const uint32_t kbase = sbase + (buf ? FW_K1 : FW_K0) * 4u;
        const uint32_t vbase = sbase + (buf ? FW_V1 : FW_V0) * 4u;

        // ---- S = Q @ K^T ----
        float sacc[8][4];
#pragma unroll
        for (int nf = 0; nf < 8; ++nf)
#pragma unroll
            for (int e = 0; e < 4; ++e) sacc[nf][e] = 0.f;

#pragma unroll
        for (int ks = 0; ks < 8; ++ks) {
            uint32_t b2[4][4];
#pragma unroll
            for (int np = 0; np < 4; ++np)
                LDMX4(b2[np][0], b2[np][1], b2[np][2], b2[np][3],
                      kbase + (uint32_t)((np * 16 + lrowB) * FST + lcolB) * 4u + ks * 32);
#pragma unroll
            for (int nf = 0; nf < 8; ++nf)
                mma_tf32(sacc[nf], qf[ks], &b2[nf >> 1][(nf & 1) * 2]);
        }

        if (kt >= 2 * qt) {
            const int q0 = qt * FQ + w * 16 + g;
            const int q1 = q0 + 8;
#pragma unroll
            for (int nf = 0; nf < 8; ++nf) {
                const int key = kt * FK + nf * 8 + tig * 2;
                if (key     > q0) sacc[nf][0] = -1e30f;
                if (key + 1 > q0) sacc[nf][1] = -1e30f;
                if (key     > q1) sacc[nf][2] = -1e30f;
                if (key + 1 > q1) sacc[nf][3] = -1e30f;
            }
        }

        // ---- online softmax ----
        float mx0 = -1e30f, mx1 = -1e30f;
#pragma unroll
        for (int nf = 0; nf < 8; ++nf) {
            mx0 = fmaxf(mx0, fmaxf(sacc[nf][0], sacc[nf][1]));
            mx1 = fmaxf(mx1, fmaxf(sacc[nf][2], sacc[nf][3]));
        }
        mx0 = fmaxf(mx0, __shfl_xor_sync(0xffffffffu, mx0, 1));
        mx0 = fmaxf(mx0, __shfl_xor_sync(0xffffffffu, mx0, 2));
        mx1 = fmaxf(mx1, __shfl_xor_sync(0xffffffffu, mx1, 1));
        mx1 = fmaxf(mx1, __shfl_xor_sync(0xffffffffu, mx1, 2));

        const float mn0 = fmaxf(m0, mx0), mn1 = fmaxf(m1, mx1);
        const float c0 = __expf(m0 - mn0), c1 = __expf(m1 - mn1);
        float s0 = 0.f, s1 = 0.f;
#pragma unroll
        for (int nf = 0; nf < 8; ++nf) {
            sacc[nf][0] = __expf(sacc[nf][0] - mn0);
            sacc[nf][1] = __expf(sacc[nf][1] - mn0);
            sacc[nf][2] = __expf(sacc[nf][2] - mn1);
            sacc[nf][3] = __expf(sacc[nf][3] - mn1);
            s0 += sacc[nf][0] + sacc[nf][1];
            s1 += sacc[nf][2] + sacc[nf][3];
        }
        s0 += __shfl_xor_sync(0xffffffffu, s0, 1);
        s0 += __shfl_xor_sync(0xffffffffu, s0, 2);
        s1 += __shfl_xor_sync(0xffffffffu, s1, 1);
        s1 += __shfl_xor_sync(0xffffffffu, s1, 2);

        l0 = l0 * c0 + s0;  l1 = l1 * c1 + s1;
        m0 = mn0;           m1 = mn1;
#pragma unroll
        for (int nf = 0; nf < 8; ++nf) {
            oacc[nf][0] *= c0; oacc[nf][1] *= c0;
            oacc[nf][2] *= c1; oacc[nf][3] *= c1;
        }

        // ---- P -> warp-private smem ----
#pragma unroll
        for (int nf = 0; nf < 8; ++nf) {
            *(float2*)(Pw + g * FST + nf * 8 + tig * 2) =
                make_float2(__uint_as_float(f2tf(sacc[nf][0])), __uint_as_float(f2tf(sacc[nf][1])));
            *(float2*)(Pw + (g + 8) * FST + nf * 8 + tig * 2) =
                make_float2(__uint_as_float(f2tf(sacc[nf][2])), __uint_as_float(f2tf(sacc[nf][3])));
        }
        __syncwarp();

        // ---- O += P @ V ----
#pragma unroll
        for (int ks = 0; ks < 8; ++ks) {
            uint32_t pa[4];
            LDMX4(pa[0], pa[1], pa[2], pa[3], paddr + ks * 32);
            uint32_t b2[4][4];
#pragma unroll
            for (int np = 0; np < 4; ++np)
                LDMX4(b2[np][0], b2[np][1], b2[np][2], b2[np][3],
                      vbase + (uint32_t)((np * 16 + lrowB) * FST + lcolB) * 4u + ks * 32);
#pragma unroll
            for (int nf = 0; nf < 8; ++nf)
                mma_tf32(oacc[nf], pa, &b2[nf >> 1][(nf & 1) * 2]);
        }
        __syncwarp();
    }

    // ---- epilogue ----
    float* Ob = Og + ((size_t)(b * TT + qt * FQ + w * 16)) * CC + h * DD;
    const float i0 = 1.0f / l0, i1 = 1.0f / l1;
#pragma unroll
    for (int nf = 0; nf < 8; ++nf) {
        *(float2*)(Ob + (size_t)g * CC + nf * 8 + tig * 2) =
            make_float2(__uint_as_float(f2tf(oacc[nf][0] * i0)),
                        __uint_as_float(f2tf(oacc[nf][1] * i0)));
        *(float2*)(Ob + (size_t)(g + 8) * CC + nf * 8 + tig * 2) =
            make_float2(__uint_as_float(f2tf(oacc[nf][2] * i1)),
                        __uint_as_float(f2tf(oacc[nf][3] * i1)));
    }
}

// ---------------------------------------------------------------------------
extern "C" void kernel_launch(void* const* d_in, const int* in_sizes, int n_in,
                              void* d_out, int out_size)
{
    const float* x    = (const float*)d_in[0];
    const float* Wq   = (const float*)d_in[1];
    const float* Wk   = (const float*)d_in[2];
    const float* Wv   = (const float*)d_in[3];
    const float* Wo   = (const float*)d_in[4];
    const float* cosb = (const float*)d_in[5];
    const float* sinb = (const float*)d_in[6];
    float* out = (float*)d_out;

    float *q, *k, *v, *vT, *attn, *xt, *wqt, *wkt, *wvt, *wot;
    cudaGetSymbolAddress((void**)&q,    g_q);
    cudaGetSymbolAddress((void**)&k,    g_k);
    cudaGetSymbolAddress((void**)&v,    g_v);
    cudaGetSymbolAddress((void**)&vT,   g_vT);
    cudaGetSymbolAddress((void**)&attn, g_attn);
    cudaGetSymbolAddress((void**)&xt,   g_xt);
    cudaGetSymbolAddress((void**)&wqt,  g_wqt);
    cudaGetSymbolAddress((void**)&wkt,  g_wkt);
    cudaGetSymbolAddress((void**)&wvt,  g_wvt);
    cudaGetSymbolAddress((void**)&wot,  g_wot);

    cudaFuncSetAttribute(gemm_qkv,   cudaFuncAttributeMaxDynamicSharedMemorySize, GEMM_SMEM);
    cudaFuncSetAttribute(gemm_oproj, cudaFuncAttributeMaxDynamicSharedMemorySize, GEMM_SMEM);
    cudaFuncSetAttribute(flash_mma,  cudaFuncAttributeMaxDynamicSharedMemorySize, FLASH_SMEM);

    // tf32 pre-rounding copies (fused into one launch)
    {
        const int total = N4_X + 2 * N4_WQ + 2 * N4_WK;
        round_copy_all<<<(total + 255) / 256, 256>>>(
            (const float4*)x,  (float4*)xt,
            (const float4*)Wq, (float4*)wqt,
            (const float4*)Wk, (float4*)wkt,
            (const float4*)Wv, (float4*)wvt,
            (const float4*)Wo, (float4*)wot);
    }

    // QKV projections
    gemm_qkv<<<dim3(24, 32), 256, GEMM_SMEM>>>(xt, wqt, wkt, wvt, q, k, v);

    // RoPE (q, k in place, rounded)
    {
        int total = BB * TT * (HH + KVHN) * (DD / 2);
        rope_kernel<<<(total + 255) / 256, 256>>>(q, k, cosb, sinb);
    }

    // V transpose + round
    vt_kernel<<<dim3(TT / 32, DD / 32, BB * KVHN), dim3(32, 8)>>>(v, vT);

    // Flash attention (2 CTAs/SM, heavy-first order)
    flash_mma<<<dim3(TT / FQ, HH, BB), 256, FLASH_SMEM>>>(q, k, vT, attn);

    // Output projection
    gemm_oproj<<<dim3(16, 32), 256, GEMM_SMEM>>>(attn, wot, out);
}

// round 10
// speedup vs baseline: 6.3380x; 1.6713x over previous
#include <cuda_runtime.h>
#include <cuda_fp16.h>
#include <math.h>
#include <stdint.h>

#define BB   2
#define TT   2048
#define CC   2048
#define HH   32
#define KVHN 8
#define DD   64
#define KDIM 2048

// GEMM tile config (fp16)
#define GBM  128
#define GBN  128
#define GBK  32
#define NCHUNK (KDIM / GBK)       // 64
#define HSTR 40                   // smem row stride in halves (80 B, ldmatrix conflict-free)
#define TILE_B (128 * HSTR * 2)   // 10240 B per tile
#define GEMM_SMEM (3 * 2 * TILE_B)  // 3-stage: 61440 B

// Scratch (allocation-free rule: __device__ globals)
__device__ __half g_q[(size_t)BB * TT * CC];
__device__ __half g_k[(size_t)BB * TT * KVHN * DD];
__device__ __half g_v[(size_t)BB * TT * KVHN * DD];
__device__ __half g_vT[(size_t)BB * KVHN * DD * TT];
__device__ __half g_attn[(size_t)BB * TT * CC];
// fp16 pre-rounded operand copies
__device__ __half g_xt [(size_t)BB * TT * CC];
__device__ __half g_wqt[(size_t)CC * CC];
__device__ __half g_wkt[(size_t)KVHN * DD * CC];
__device__ __half g_wvt[(size_t)KVHN * DD * CC];
__device__ __half g_wot[(size_t)CC * CC];

// ---------------------------------------------------------------------------
// helpers
// ---------------------------------------------------------------------------
__device__ __forceinline__ uint32_t smem_u32(const void* p) {
    uint32_t r;
    asm("{ .reg .u64 t; cvta.to.shared.u64 t, %1; cvt.u32.u64 %0, t; }" : "=r"(r) : "l"(p));
    return r;
}
__device__ __forceinline__ uint32_t pack_h2(float a, float b) {
    __half2 h = __floats2half2_rn(a, b);
    return *reinterpret_cast<uint32_t*>(&h);
}
#define CP16(dst, src) \
    asm volatile("cp.async.cg.shared.global [%0], [%1], 16;" :: "r"(dst), "l"(src))
#define CP_COMMIT() asm volatile("cp.async.commit_group;" ::: "memory")
#define CP_WAITG1() asm volatile("cp.async.wait_group 1;" ::: "memory")
#define CP_WAIT0()  asm volatile("cp.async.wait_group 0;" ::: "memory")

#define LDMX4(r0, r1, r2, r3, addr) \
    asm volatile("ldmatrix.sync.aligned.m8n8.x4.shared.b16 {%0,%1,%2,%3}, [%4];" \
        : "=r"(r0), "=r"(r1), "=r"(r2), "=r"(r3) : "r"(addr))

__device__ __forceinline__ void mma_f16(float* d, const uint32_t* a, const uint32_t* b) {
    asm volatile(
        "mma.sync.aligned.m16n8k16.row.col.f32.f16.f16.f32 "
        "{%0,%1,%2,%3}, {%4,%5,%6,%7}, {%8,%9}, {%0,%1,%2,%3};"
        : "+f"(d[0]), "+f"(d[1]), "+f"(d[2]), "+f"(d[3])
        : "r"(a[0]), "r"(a[1]), "r"(a[2]), "r"(a[3]), "r"(b[0]), "r"(b[1]));
}

// ---------------------------------------------------------------------------
// Fused fp16 pre-rounding copy (x, Wq, Wk, Wv, Wo in one launch)
// ---------------------------------------------------------------------------
#define N4_X  (BB * TT * CC / 4)
#define N4_WQ (CC * CC / 4)
#define N4_WK (KVHN * DD * CC / 4)

__global__ void round_copy_all(const float4* __restrict__ x,  uint2* __restrict__ xt,
                               const float4* __restrict__ wq, uint2* __restrict__ wqt,
                               const float4* __restrict__ wk, uint2* __restrict__ wkt,
                               const float4* __restrict__ wv, uint2* __restrict__ wvt,
                               const float4* __restrict__ wo, uint2* __restrict__ wot)
{
    int i = blockIdx.x * blockDim.x + threadIdx.x;
    const float4* in; uint2* out; int j = i;
    if (j < N4_X)                      { in = x;  out = xt; }
    else if ((j -= N4_X) < N4_WQ)      { in = wq; out = wqt; }
    else if ((j -= N4_WQ) < N4_WK)     { in = wk; out = wkt; }
    else if ((j -= N4_WK) < N4_WK)     { in = wv; out = wvt; }
    else if ((j -= N4_WK) < N4_WQ)     { in = wo; out = wot; }
    else return;
    float4 v = in[j];
    uint2 o;
    o.x = pack_h2(v.x, v.y);
    o.y = pack_h2(v.z, v.w);
    out[j] = o;
}

// ---------------------------------------------------------------------------
// V transpose (fp16): v[(b*TT+t)*512 + kvh*64 + d] -> vT[((b*8+kvh)*64+d)*TT + t]
// ---------------------------------------------------------------------------
__global__ void vt_kernel(const __half* __restrict__ v, __half* __restrict__ vt)
{
    __shared__ __half tile[32][34];
    const int bk = blockIdx.z;
    const int b  = bk >> 3, kvh = bk & 7;
    const int t0 = blockIdx.x * 32, d0 = blockIdx.y * 32;
    const int tx = threadIdx.x, ty = threadIdx.y;
#pragma unroll
    for (int i = 0; i < 4; ++i)
        tile[ty + i * 8][tx] =
            v[((size_t)(b * TT + t0 + ty + i * 8)) * (KVHN * DD) + kvh * DD + d0 + tx];
    __syncthreads();
#pragma unroll
    for (int i = 0; i < 4; ++i)
        vt[((size_t)(bk * DD + d0 + ty + i * 8)) * TT + t0 + tx] = tile[tx][ty + i * 8];
}

// ---------------------------------------------------------------------------
// fp16 mma.sync NT GEMM tile: 3-stage cp.async pipeline, ldmatrix loads.
// C[128,128] = A[128,K] @ W[128,K]^T, fp32 accumulate.
// ---------------------------------------------------------------------------
template<bool HalfOut>
__device__ __forceinline__ void gemm_mma_tile(const __half* __restrict__ A,
                                              const __half* __restrict__ W,
                                              void* __restrict__ Cp, int ldc)
{
    extern __shared__ float smf[];
    const uint32_t sbase = smem_u32(smf);

    const int tid  = threadIdx.x;
    const int wid  = tid >> 5, lane = tid & 31;
    const int wm   = wid & 1,  wn   = wid >> 1;
    const int g    = lane >> 2, tig = lane & 3;

    const int lrowA  = lane & 15;
    const int lcolA  = (lane >> 4) * 16;                      // bytes
    const int lrowB  = (lane & 7) + ((lane >> 4) << 3);
    const int lcolB  = (lane & 8) ? 16 : 0;                   // bytes

    float acc[4][4][4];
#pragma unroll
    for (int i = 0; i < 4; ++i)
#pragma unroll
        for (int j = 0; j < 4; ++j)
#pragma unroll
            for (int e = 0; e < 4; ++e) acc[i][j][e] = 0.f;

    auto load_chunk = [&](int c, int buf) {
        const __half* Ab = A + c * GBK;
        const __half* Wb = W + c * GBK;
        const uint32_t da = sbase + (uint32_t)buf * 2u * TILE_B;
        const uint32_t db = da + TILE_B;
#pragma unroll
        for (int i = 0; i < 2; ++i) {                         // A: 512 16B chunks
            int lin = tid + i * 256;
            int r = lin >> 2, c4 = lin & 3;
            CP16(da + (uint32_t)(r * HSTR + c4 * 8) * 2u,
                 Ab + (size_t)r * KDIM + c4 * 8);
        }
#pragma unroll
        for (int i = 0; i < 2; ++i) {                         // B: 512 16B chunks
            int lin = tid + i * 256;
            int r = lin >> 2, c4 = lin & 3;
            CP16(db + (uint32_t)(r * HSTR + c4 * 8) * 2u,
                 Wb + (size_t)r * KDIM + c4 * 8);
        }
        CP_COMMIT();
    };

    auto compute = [&](int buf) {
        const uint32_t abase = sbase + (uint32_t)buf * 2u * TILE_B;
        const uint32_t bbase = abase + TILE_B;
        uint32_t aaddr[4], baddr[2];
#pragma unroll
        for (int mf = 0; mf < 4; ++mf)
            aaddr[mf] = abase + (uint32_t)((wm * 64 + mf * 16 + lrowA) * HSTR) * 2u + lcolA;
#pragma unroll
        for (int np = 0; np < 2; ++np)
            baddr[np] = bbase + (uint32_t)((wn * 32 + np * 16 + lrowB) * HSTR) * 2u + lcolB;

#pragma unroll
        for (int ks = 0; ks < 2; ++ks) {                      // 2 k16-steps per BK=32
            uint32_t a[4][4], b2[2][4];
#pragma unroll
            for (int mf = 0; mf < 4; ++mf)
                LDMX4(a[mf][0], a[mf][1], a[mf][2], a[mf][3], aaddr[mf] + ks * 32);
#pragma unroll
            for (int np = 0; np < 2; ++np)
                LDMX4(b2[np][0], b2[np][1], b2[np][2], b2[np][3], baddr[np] + ks * 32);
#pragma unroll
            for (int mf = 0; mf < 4; ++mf)
#pragma unroll
                for (int nf = 0; nf < 4; ++nf)
                    mma_f16(acc[mf][nf], a[mf], &b2[nf >> 1][(nf & 1) * 2]);
        }
    };

    load_chunk(0, 0);
    load_chunk(1, 1);
    int buf = 0;
    for (int c = 0; c < NCHUNK; ++c) {
        if (c + 1 < NCHUNK) CP_WAITG1();
        else                CP_WAIT0();
        __syncthreads();
        if (c + 2 < NCHUNK) load_chunk(c + 2, (buf + 2) % 3);
        compute(buf);
        buf = (buf + 1) % 3;
    }

#pragma unroll
    for (int mf = 0; mf < 4; ++mf) {
        const int r0 = wm * 64 + mf * 16 + g;
#pragma unroll
        for (int nf = 0; nf < 4; ++nf) {
            const int c0 = wn * 32 + nf * 8 + tig * 2;
            if (HalfOut) {
                __half* C = (__half*)Cp;
                *(uint32_t*)(C + (size_t)r0 * ldc + c0)       = pack_h2(acc[mf][nf][0], acc[mf][nf][1]);
                *(uint32_t*)(C + (size_t)(r0 + 8) * ldc + c0) = pack_h2(acc[mf][nf][2], acc[mf][nf][3]);
            } else {
                float* C = (float*)Cp;
                *(float2*)(C + (size_t)r0 * ldc + c0)       = make_float2(acc[mf][nf][0], acc[mf][nf][1]);
                *(float2*)(C + (size_t)(r0 + 8) * ldc + c0) = make_float2(acc[mf][nf][2], acc[mf][nf][3]);
            }
        }
    }
}

__global__ void __launch_bounds__(256, 2)
gemm_qkv(const __half* __restrict__ x,
         const __half* __restrict__ Wq, const __half* __restrict__ Wk, const __half* __restrict__ Wv,
         __half* __restrict__ q, __half* __restrict__ k, __half* __restrict__ v)
{
    const int nt = blockIdx.x;
    const int bm = blockIdx.y * GBM;
    const __half* W; __half* C; int ldc, cn;
    if (nt < 16)      { W = Wq; C = q; ldc = CC;        cn = nt * GBN; }
    else if (nt < 20) { W = Wk; C = k; ldc = KVHN * DD; cn = (nt - 16) * GBN; }
    else              { W = Wv; C = v; ldc = KVHN * DD; cn = (nt - 20) * GBN; }
    gemm_mma_tile<true>(x + (size_t)bm * KDIM, W + (size_t)cn * KDIM,
                        C + (size_t)bm * ldc + cn, ldc);
}

__global__ void __launch_bounds__(256, 2)
gemm_oproj(const __half* __restrict__ A, const __half* __restrict__ W, float* __restrict__ C)
{
    const int bm = blockIdx.y * GBM;
    const int bn = blockIdx.x * GBN;
    gemm_mma_tile<false>(A + (size_t)bm * KDIM, W + (size_t)bn * KDIM,
                         C + (size_t)bm * CC + bn, CC);
}

// ---------------------------------------------------------------------------
// RoPE in place on q, k (fp16 in/out, fp32 math). Q additionally pre-scaled
// by 1/sqrt(D)=0.125 (exact in fp16) so flash loads Q raw.
// ---------------------------------------------------------------------------
__global__ void rope_kernel(__half* __restrict__ q, __half* __restrict__ k,
                            const float* __restrict__ cosb, const float* __restrict__ sinb)
{
    const int halfs_q = BB * TT * HH * (DD / 2);
    const int halfs_k = BB * TT * KVHN * (DD / 2);
    int idx = blockIdx.x * blockDim.x + threadIdx.x;
    if (idx < halfs_q) {
        int d   = idx & 31;
        int h   = (idx >> 5) & (HH - 1);
        int row = idx >> 10;
        int t   = row & (TT - 1);
        __half* p = q + (size_t)row * CC + h * DD;
        float c1 = cosb[t * DD + d],      s1 = sinb[t * DD + d];
        float c2 = cosb[t * DD + d + 32], s2 = sinb[t * DD + d + 32];
        float a = __half2float(p[d]), b2 = __half2float(p[d + 32]);
        p[d]      = __float2half_rn((a * c1 - b2 * s1) * 0.125f);
        p[d + 32] = __float2half_rn((b2 * c2 + a * s2) * 0.125f);
    } else if (idx < halfs_q + halfs_k) {
        int j   = idx - halfs_q;
        int d   = j & 31;
        int h   = (j >> 5) & (KVHN - 1);
        int row = j >> 8;
        int t   = row & (TT - 1);
        __half* p = k + (size_t)row * (KVHN * DD) + h * DD;
        float c1 = cosb[t * DD + d],      s1 = sinb[t * DD + d];
        float c2 = cosb[t * DD + d + 32], s2 = sinb[t * DD + d + 32];
        float a = __half2float(p[d]), b2 = __half2float(p[d + 32]);
        p[d]      = __float2half_rn(a * c1 - b2 * s1);
        p[d + 32] = __float2half_rn(b2 * c2 + a * s2);
    }
}

// ---------------------------------------------------------------------------
// fp16 tensor-core flash attention. Causal, GQA G=4, D=64.
// K smem [key][d], V^T smem [d][key], P smem fp16; strides 72 halves.
// 2 CTAs/SM, heavy-first block order.
// ---------------------------------------------------------------------------
#define FQ 128
#define FK 64
#define FST 72                           // halves
#define FW_K0  0
#define FW_K1  (64 * FST)                // 4608
#define FW_V0  (2 * 64 * FST)            // 9216
#define FW_V1  (3 * 64 * FST)            // 13824
#define FW_P   (4 * 64 * FST)            // 18432
#define FLASH_SMEM ((4 * 64 * FST + 128 * FST) * 2)   // 55296 B

__global__ void __launch_bounds__(256, 2)
flash_mma(const __half* __restrict__ Qg, const __half* __restrict__ Kg,
          const __half* __restrict__ VTg, __half* __restrict__ Og)
{
    extern __shared__ float sfraw[];
    __half* sf = (__half*)sfraw;
    const uint32_t sbase = smem_u32(sf);

    const int qt  = (TT / FQ - 1) - blockIdx.x;   // heavy blocks first
    const int h   = blockIdx.y;
    const int b   = blockIdx.z;
    const int kvh = h >> 2;
    const int tid = threadIdx.x;
    const int w   = tid >> 5, lane = tid & 31;
    const int g   = lane >> 2, tig = lane & 3;

    const int lrowA = lane & 15;
    const int lcolA = (lane >> 4) * 16;           // bytes
    const int lrowB = (lane & 7) + ((lane >> 4) << 3);
    const int lcolB = (lane & 8) ? 16 : 0;        // bytes

    // Q fragments (fp16, pre-scaled in rope): 4 k16-steps
    uint32_t qf[4][4];
    {
        const __half* Qb = Qg + ((size_t)(b * TT + qt * FQ + w * 16)) * CC + h * DD;
#pragma unroll
        for (int ks = 0; ks < 4; ++ks) {
            qf[ks][0] = *(const uint32_t*)(Qb + (size_t)g * CC + ks * 16 + 2 * tig);
            qf[ks][1] = *(const uint32_t*)(Qb + (size_t)(g + 8) * CC + ks * 16 + 2 * tig);
            qf[ks][2] = *(const uint32_t*)(Qb + (size_t)g * CC + ks * 16 + 2 * tig + 8);
            qf[ks][3] = *(const uint32_t*)(Qb + (size_t)(g + 8) * CC + ks * 16 + 2 * tig + 8);
        }
    }

    float oacc[8][4];
#pragma unroll
    for (int nf = 0; nf < 8; ++nf)
#pragma unroll
        for (int e = 0; e < 4; ++e) oacc[nf][e] = 0.f;
    float m0 = -1e30f, m1 = -1e30f, l0 = 0.f, l1 = 0.f;

    const int ktmax = 2 * qt + 1;
    const __half* VTb = VTg + ((size_t)(b * KVHN + kvh)) * DD * TT;

    auto prefetch = [&](int kt, int buf) {
        const __half* Kb = Kg + ((size_t)(b * TT + kt * FK)) * (KVHN * DD) + kvh * DD;
        const uint32_t kd = sbase + (buf ? FW_K1 : FW_K0) * 2u;
        const uint32_t vd = sbase + (buf ? FW_V1 : FW_V0) * 2u;
#pragma unroll
        for (int i = 0; i < 2; ++i) {
            int lin = tid + i * 256;
            int r = lin >> 3, c8 = lin & 7;
            CP16(kd + (uint32_t)(r * FST + c8 * 8) * 2u, Kb + (size_t)r * (KVHN * DD) + c8 * 8);
            CP16(vd + (uint32_t)(r * FST + c8 * 8) * 2u, VTb + (size_t)r * TT + kt * FK + c8 * 8);
        }
        CP_COMMIT();
    };

    prefetch(0, 0);
    __half* Pw = sf + FW_P + w * 16 * FST;
    const uint32_t paddr = sbase + (uint32_t)(FW_P + w * 16 * FST + lrowA * FST) * 2u + lcolA;

    for (int kt = 0; kt <= ktmax; ++kt) {
        const int buf = kt & 1;
        CP_WAIT0();
        __syncthreads();
        if (kt < ktmax) prefetch(kt + 1, buf ^ 1);

        const uint32_t kbase = sbase + (buf ? FW_K1 : FW_K0) * 2u;
        const uint32_t vbase = sbase + (buf ? FW_V1 : FW_V0) * 2u;

        // ---- S = Q @ K^T  (4 k16-steps) ----
        float sacc[8][4];
#pragma unroll
        for (int nf = 0; nf < 8; ++nf)
#pragma unroll
            for (int e = 0; e < 4; ++e) sacc[nf][e] = 0.f;

#pragma unroll
        for (int ks = 0; ks < 4; ++ks) {
            uint32_t b2[4][4];
#pragma unroll
            for (int np = 0; np < 4; ++np)
                LDMX4(b2[np][0], b2[np][1], b2[np][2], b2[np][3],
                      kbase + (uint32_t)((np * 16 + lrowB) * FST) * 2u + lcolB + ks * 32);
#pragma unroll
            for (int nf = 0; nf < 8; ++nf)
                mma_f16(sacc[nf], qf[ks], &b2[nf >> 1][(nf & 1) * 2]);
        }

        // ---- causal mask (only last two key blocks) ----
        if (kt >= 2 * qt) {
            const int q0 = qt * FQ + w * 16 + g;
            const int q1 = q0 + 8;
#pragma unroll
            for (int nf = 0; nf < 8; ++nf) {
                const int key = kt * FK + nf * 8 + tig * 2;
                if (key     > q0) sacc[nf][0] = -1e30f;
                if (key + 1 > q0) sacc[nf][1] = -1e30f;
                if (key     > q1) sacc[nf][2] = -1e30f;
                if (key + 1 > q1) sacc[nf][3] = -1e30f;
            }
        }

        // ---- online softmax (fp32) ----
        float mx0 = -1e30f, mx1 = -1e30f;
#pragma unroll
        for (int nf = 0; nf < 8; ++nf) {
            mx0 = fmaxf(mx0, fmaxf(sacc[nf][0], sacc[nf][1]));
            mx1 = fmaxf(mx1, fmaxf(sacc[nf][2], sacc[nf][3]));
        }
        mx0 = fmaxf(mx0, __shfl_xor_sync(0xffffffffu, mx0, 1));
        mx0 = fmaxf(mx0, __shfl_xor_sync(0xffffffffu, mx0, 2));
        mx1 = fmaxf(mx1, __shfl_xor_sync(0xffffffffu, mx1, 1));
        mx1 = fmaxf(mx1, __shfl_xor_sync(0xffffffffu, mx1, 2));

        const float mn0 = fmaxf(m0, mx0), mn1 = fmaxf(m1, mx1);
        const float c0 = __expf(m0 - mn0), c1 = __expf(m1 - mn1);
        float s0 = 0.f, s1 = 0.f;
#pragma unroll
        for (int nf = 0; nf < 8; ++nf) {
            sacc[nf][0] = __expf(sacc[nf][0] - mn0);
            sacc[nf][1] = __expf(sacc[nf][1] - mn0);
            sacc[nf][2] = __expf(sacc[nf][2] - mn1);
            sacc[nf][3] = __expf(sacc[nf][3] - mn1);
            s0 += sacc[nf][0] + sacc[nf][1];
            s1 += sacc[nf][2] + sacc[nf][3];
        }
        s0 += __shfl_xor_sync(0xffffffffu, s0, 1);
        s0 += __shfl_xor_sync(0xffffffffu, s0, 2);
        s1 += __shfl_xor_sync(0xffffffffu, s1, 1);
        s1 += __shfl_xor_sync(0xffffffffu, s1, 2);

        l0 = l0 * c0 + s0;  l1 = l1 * c1 + s1;
        m0 = mn0;           m1 = mn1;
#pragma unroll
        for (int nf = 0; nf < 8; ++nf) {
            oacc[nf][0] *= c0; oacc[nf][1] *= c0;
            oacc[nf][2] *= c1; oacc[nf][3] *= c1;
        }

        // ---- P -> warp-private smem (fp16) ----
#pragma unroll
        for (int nf = 0; nf < 8; ++nf) {
            *(uint32_t*)(Pw + g * FST + nf * 8 + tig * 2)       = pack_h2(sacc[nf][0], sacc[nf][1]);
            *(uint32_t*)(Pw + (g + 8) * FST + nf * 8 + tig * 2) = pack_h2(sacc[nf][2], sacc[nf][3]);
        }
        __syncwarp();

        // ---- O += P @ V  (4 k16-steps; V^T rows = d) ----
#pragma unroll
        for (int ks = 0; ks < 4; ++ks) {
            uint32_t pa[4];
            LDMX4(pa[0], pa[1], pa[2], pa[3], paddr + ks * 32);
            uint32_t b2[4][4];
#pragma unroll
            for (int np = 0; np < 4; ++np)
                LDMX4(b2[np][0], b2[np][1], b2[np][2], b2[np][3],
                      vbase + (uint32_t)((np * 16 + lrowB) * FST) * 2u + lcolB + ks * 32);
#pragma unroll
            for (int nf = 0; nf < 8; ++nf)
                mma_f16(oacc[nf], pa, &b2[nf >> 1][(nf & 1) * 2]);
        }
        __syncwarp();
    }

    // ---- epilogue: normalize, fp16 store (feeds oproj) ----
    __half* Ob = Og + ((size_t)(b * TT + qt * FQ + w * 16)) * CC + h * DD;
    const float i0 = 1.0f / l0, i1 = 1.0f / l1;
#pragma unroll
    for (int nf = 0; nf < 8; ++nf) {
        *(uint32_t*)(Ob + (size_t)g * CC + nf * 8 + tig * 2) =
            pack_h2(oacc[nf][0] * i0, oacc[nf][1] * i0);
        *(uint32_t*)(Ob + (size_t)(g + 8) * CC + nf * 8 + tig * 2) =
            pack_h2(oacc[nf][2] * i1, oacc[nf][3] * i1);
    }
}

// ---------------------------------------------------------------------------
extern "C" void kernel_launch(void* const* d_in, const int* in_sizes, int n_in,
                              void* d_out, int out_size)
{
    const float* x    = (const float*)d_in[0];
    const float* Wq   = (const float*)d_in[1];
    const float* Wk   = (const float*)d_in[2];
    const float* Wv   = (const float*)d_in[3];
    const float* Wo   = (const float*)d_in[4];
    const float* cosb = (const float*)d_in[5];
    const float* sinb = (const float*)d_in[6];
    float* out = (float*)d_out;

    __half *q, *k, *v, *vT, *attn, *xt, *wqt, *wkt, *wvt, *wot;
    cudaGetSymbolAddress((void**)&q,    g_q);
    cudaGetSymbolAddress((void**)&k,    g_k);
    cudaGetSymbolAddress((void**)&v,    g_v);
    cudaGetSymbolAddress((void**)&vT,   g_vT);
    cudaGetSymbolAddress((void**)&attn, g_attn);
    cudaGetSymbolAddress((void**)&xt,   g_xt);
    cudaGetSymbolAddress((void**)&wqt,  g_wqt);
    cudaGetSymbolAddress((void**)&wkt,  g_wkt);
    cudaGetSymbolAddress((void**)&wvt,  g_wvt);
    cudaGetSymbolAddress((void**)&wot,  g_wot);

    cudaFuncSetAttribute(gemm_qkv,   cudaFuncAttributeMaxDynamicSharedMemorySize, GEMM_SMEM);
    cudaFuncSetAttribute(gemm_oproj, cudaFuncAttributeMaxDynamicSharedMemorySize, GEMM_SMEM);
    cudaFuncSetAttribute(flash_mma,  cudaFuncAttributeMaxDynamicSharedMemorySize, FLASH_SMEM);

    // fp16 pre-rounding copies (one launch)
    {
        const int total = N4_X + 2 * N4_WQ + 2 * N4_WK;
        round_copy_all<<<(total + 255) / 256, 256>>>(
            (const float4*)x,  (uint2*)xt,
            (const float4*)Wq, (uint2*)wqt,
            (const float4*)Wk, (uint2*)wkt,
            (const float4*)Wv, (uint2*)wvt,
            (const float4*)Wo, (uint2*)wot);
    }

    // QKV projections (fp16 mma)
    gemm_qkv<<<dim3(24, 32), 256, GEMM_SMEM>>>(xt, wqt, wkt, wvt, q, k, v);

    // RoPE (q pre-scaled by 0.125; fp16 in/out)
    {
        int total = BB * TT * (HH + KVHN) * (DD / 2);
        rope_kernel<<<(total + 255) / 256, 256>>>(q, k, cosb, sinb);
    }

    // V transpose
    vt_kernel<<<dim3(TT / 32, DD / 32, BB * KVHN), dim3(32, 8)>>>(v, vT);

    // Flash attention (fp16 mma)
    flash_mma<<<dim3(TT / FQ, HH, BB), 256, FLASH_SMEM>>>(q, k, vT, attn);

    // Output projection (fp32 out)
    gemm_oproj<<<dim3(16, 32), 256, GEMM_SMEM>>>(attn, wot, out);
}

// round 11
// speedup vs baseline: 6.7795x; 1.0697x over previous
#include <cuda_runtime.h>
#include <cuda_fp16.h>
#include <math.h>
#include <stdint.h>

#define BB   2
#define TT   2048
#define CC   2048
#define HH   32
#define KVHN 8
#define DD   64
#define KDIM 2048

// GEMM tile config (fp16, BK=64)
#define GBM  128
#define GBN  128
#define GBK  64
#define NCHUNK (KDIM / GBK)       // 32
#define HSTR 72                   // smem row stride in halves (144 B, ldmatrix conflict-free)
#define TILE_B (128 * HSTR * 2)   // 18432 B per operand tile
#define GEMM_SMEM (3 * 2 * TILE_B)  // 3-stage: 110592 B

// Scratch (allocation-free rule: __device__ globals)
__device__ __half g_q[(size_t)BB * TT * CC];
__device__ __half g_k[(size_t)BB * TT * KVHN * DD];
__device__ __half g_v[(size_t)BB * TT * KVHN * DD];
__device__ __half g_vT[(size_t)BB * KVHN * DD * TT];
__device__ __half g_attn[(size_t)BB * TT * CC];
// fp16 pre-rounded operand copies
__device__ __half g_xt [(size_t)BB * TT * CC];
__device__ __half g_wqt[(size_t)CC * CC];
__device__ __half g_wkt[(size_t)KVHN * DD * CC];
__device__ __half g_wvt[(size_t)KVHN * DD * CC];
__device__ __half g_wot[(size_t)CC * CC];

// ---------------------------------------------------------------------------
// helpers
// ---------------------------------------------------------------------------
__device__ __forceinline__ uint32_t smem_u32(const void* p) {
    uint32_t r;
    asm("{ .reg .u64 t; cvta.to.shared.u64 t, %1; cvt.u32.u64 %0, t; }" : "=r"(r) : "l"(p));
    return r;
}
__device__ __forceinline__ uint32_t pack_h2(float a, float b) {
    __half2 h = __floats2half2_rn(a, b);
    return *reinterpret_cast<uint32_t*>(&h);
}
#define CP16(dst, src) \
    asm volatile("cp.async.cg.shared.global [%0], [%1], 16;" :: "r"(dst), "l"(src))
#define CP_COMMIT() asm volatile("cp.async.commit_group;" ::: "memory")
#define CP_WAITG1() asm volatile("cp.async.wait_group 1;" ::: "memory")
#define CP_WAIT0()  asm volatile("cp.async.wait_group 0;" ::: "memory")

#define LDMX4(r0, r1, r2, r3, addr) \
    asm volatile("ldmatrix.sync.aligned.m8n8.x4.shared.b16 {%0,%1,%2,%3}, [%4];" \
        : "=r"(r0), "=r"(r1), "=r"(r2), "=r"(r3) : "r"(addr))

__device__ __forceinline__ void mma_f16(float* d, const uint32_t* a, const uint32_t* b) {
    asm volatile(
        "mma.sync.aligned.m16n8k16.row.col.f32.f16.f16.f32 "
        "{%0,%1,%2,%3}, {%4,%5,%6,%7}, {%8,%9}, {%0,%1,%2,%3};"
        : "+f"(d[0]), "+f"(d[1]), "+f"(d[2]), "+f"(d[3])
        : "r"(a[0]), "r"(a[1]), "r"(a[2]), "r"(a[3]), "r"(b[0]), "r"(b[1]));
}

// ---------------------------------------------------------------------------
// Fused fp16 pre-rounding copy (x, Wq, Wk, Wv, Wo in one launch)
// ---------------------------------------------------------------------------
#define N4_X  (BB * TT * CC / 4)
#define N4_WQ (CC * CC / 4)
#define N4_WK (KVHN * DD * CC / 4)

__global__ void round_copy_all(const float4* __restrict__ x,  uint2* __restrict__ xt,
                               const float4* __restrict__ wq, uint2* __restrict__ wqt,
                               const float4* __restrict__ wk, uint2* __restrict__ wkt,
                               const float4* __restrict__ wv, uint2* __restrict__ wvt,
                               const float4* __restrict__ wo, uint2* __restrict__ wot)
{
    int i = blockIdx.x * blockDim.x + threadIdx.x;
    const float4* in; uint2* out; int j = i;
    if (j < N4_X)                      { in = x;  out = xt; }
    else if ((j -= N4_X) < N4_WQ)      { in = wq; out = wqt; }
    else if ((j -= N4_WQ) < N4_WK)     { in = wk; out = wkt; }
    else if ((j -= N4_WK) < N4_WK)     { in = wv; out = wvt; }
    else if ((j -= N4_WK) < N4_WQ)     { in = wo; out = wot; }
    else return;
    float4 v = in[j];
    uint2 o;
    o.x = pack_h2(v.x, v.y);
    o.y = pack_h2(v.z, v.w);
    out[j] = o;
}

// ---------------------------------------------------------------------------
// V transpose (fp16)
// ---------------------------------------------------------------------------
__global__ void vt_kernel(const __half* __restrict__ v, __half* __restrict__ vt)
{
    __shared__ __half tile[32][34];
    const int bk = blockIdx.z;
    const int b  = bk >> 3, kvh = bk & 7;
    const int t0 = blockIdx.x * 32, d0 = blockIdx.y * 32;
    const int tx = threadIdx.x, ty = threadIdx.y;
#pragma unroll
    for (int i = 0; i < 4; ++i)
        tile[ty + i * 8][tx] =
            v[((size_t)(b * TT + t0 + ty + i * 8)) * (KVHN * DD) + kvh * DD + d0 + tx];
    __syncthreads();
#pragma unroll
    for (int i = 0; i < 4; ++i)
        vt[((size_t)(bk * DD + d0 + ty + i * 8)) * TT + t0 + tx] = tile[tx][ty + i * 8];
}

// ---------------------------------------------------------------------------
// fp16 mma.sync NT GEMM tile: BK=64, 3-stage cp.async, ldmatrix loads.
// C[128,128] = A[128,K] @ W[128,K]^T, fp32 accumulate.
// ---------------------------------------------------------------------------
template<bool HalfOut>
__device__ __forceinline__ void gemm_mma_tile(const __half* __restrict__ A,
                                              const __half* __restrict__ W,
                                              void* __restrict__ Cp, int ldc)
{
    extern __shared__ float smf[];
    const uint32_t sbase = smem_u32(smf);

    const int tid  = threadIdx.x;
    const int wid  = tid >> 5, lane = tid & 31;
    const int wm   = wid & 1,  wn   = wid >> 1;
    const int g    = lane >> 2, tig = lane & 3;

    const int lrowA  = lane & 15;
    const int lcolA  = (lane >> 4) * 16;                      // bytes
    const int lrowB  = (lane & 7) + ((lane >> 4) << 3);
    const int lcolB  = (lane & 8) ? 16 : 0;                   // bytes

    float acc[4][4][4];
#pragma unroll
    for (int i = 0; i < 4; ++i)
#pragma unroll
        for (int j = 0; j < 4; ++j)
#pragma unroll
            for (int e = 0; e < 4; ++e) acc[i][j][e] = 0.f;

    auto load_chunk = [&](int c, int buf) {
        const __half* Ab = A + c * GBK;
        const __half* Wb = W + c * GBK;
        const uint32_t da = sbase + (uint32_t)buf * 2u * TILE_B;
        const uint32_t db = da + TILE_B;
#pragma unroll
        for (int i = 0; i < 4; ++i) {                         // A: 1024 16B chunks
            int lin = tid + i * 256;
            int r = lin >> 3, c8 = lin & 7;
            CP16(da + (uint32_t)(r * HSTR + c8 * 8) * 2u,
                 Ab + (size_t)r * KDIM + c8 * 8);
        }
#pragma unroll
        for (int i = 0; i < 4; ++i) {                         // B: 1024 16B chunks
            int lin = tid + i * 256;
            int r = lin >> 3, c8 = lin & 7;
            CP16(db + (uint32_t)(r * HSTR + c8 * 8) * 2u,
                 Wb + (size_t)r * KDIM + c8 * 8);
        }
        CP_COMMIT();
    };

    auto compute = [&](int buf) {
        const uint32_t abase = sbase + (uint32_t)buf * 2u * TILE_B;
        const uint32_t bbase = abase + TILE_B;
        uint32_t aaddr[4], baddr[2];
#pragma unroll
        for (int mf = 0; mf < 4; ++mf)
            aaddr[mf] = abase + (uint32_t)((wm * 64 + mf * 16 + lrowA) * HSTR) * 2u + lcolA;
#pragma unroll
        for (int np = 0; np < 2; ++np)
            baddr[np] = bbase + (uint32_t)((wn * 32 + np * 16 + lrowB) * HSTR) * 2u + lcolB;

#pragma unroll
        for (int ks = 0; ks < 4; ++ks) {                      // 4 k16-steps per BK=64
            uint32_t a[4][4], b2[2][4];
#pragma unroll
            for (int mf = 0; mf < 4; ++mf)
                LDMX4(a[mf][0], a[mf][1], a[mf][2], a[mf][3], aaddr[mf] + ks * 32);
#pragma unroll
            for (int np = 0; np < 2; ++np)
                LDMX4(b2[np][0], b2[np][1], b2[np][2], b2[np][3], baddr[np] + ks * 32);
#pragma unroll
            for (int mf = 0; mf < 4; ++mf)
#pragma unroll
                for (int nf = 0; nf < 4; ++nf)
                    mma_f16(acc[mf][nf], a[mf], &b2[nf >> 1][(nf & 1) * 2]);
        }
    };

    load_chunk(0, 0);
    load_chunk(1, 1);
    int buf = 0;
    for (int c = 0; c < NCHUNK; ++c) {
        if (c + 1 < NCHUNK) CP_WAITG1();
        else                CP_WAIT0();
        __syncthreads();
        if (c + 2 < NCHUNK) load_chunk(c + 2, (buf + 2) % 3);
        compute(buf);
        buf = (buf + 1) % 3;
    }

#pragma unroll
    for (int mf = 0; mf < 4; ++mf) {
        const int r0 = wm * 64 + mf * 16 + g;
#pragma unroll
        for (int nf = 0; nf < 4; ++nf) {
            const int c0 = wn * 32 + nf * 8 + tig * 2;
            if (HalfOut) {
                __half* C = (__half*)Cp;
                *(uint32_t*)(C + (size_t)r0 * ldc + c0)       = pack_h2(acc[mf][nf][0], acc[mf][nf][1]);
                *(uint32_t*)(C + (size_t)(r0 + 8) * ldc + c0) = pack_h2(acc[mf][nf][2], acc[mf][nf][3]);
            } else {
                float* C = (float*)Cp;
                *(float2*)(C + (size_t)r0 * ldc + c0)       = make_float2(acc[mf][nf][0], acc[mf][nf][1]);
                *(float2*)(C + (size_t)(r0 + 8) * ldc + c0) = make_float2(acc[mf][nf][2], acc[mf][nf][3]);
            }
        }
    }
}

__global__ void __launch_bounds__(256, 2)
gemm_qkv(const __half* __restrict__ x,
         const __half* __restrict__ Wq, const __half* __restrict__ Wk, const __half* __restrict__ Wv,
         __half* __restrict__ q, __half* __restrict__ k, __half* __restrict__ v)
{
    const int nt = blockIdx.x;
    const int bm = blockIdx.y * GBM;
    const __half* W; __half* C; int ldc, cn;
    if (nt < 16)      { W = Wq; C = q; ldc = CC;        cn = nt * GBN; }
    else if (nt < 20) { W = Wk; C = k; ldc = KVHN * DD; cn = (nt - 16) * GBN; }
    else              { W = Wv; C = v; ldc = KVHN * DD; cn = (nt - 20) * GBN; }
    gemm_mma_tile<true>(x + (size_t)bm * KDIM, W + (size_t)cn * KDIM,
                        C + (size_t)bm * ldc + cn, ldc);
}

__global__ void __launch_bounds__(256, 2)
gemm_oproj(const __half* __restrict__ A, const __half* __restrict__ W, float* __restrict__ C)
{
    const int bm = blockIdx.y * GBM;
    const int bn = blockIdx.x * GBN;
    gemm_mma_tile<false>(A + (size_t)bm * KDIM, W + (size_t)bn * KDIM,
                         C + (size_t)bm * CC + bn, CC);
}

// ---------------------------------------------------------------------------
// RoPE in place on q, k (fp16 in/out, fp32 math). Q pre-scaled by 0.125.
// ---------------------------------------------------------------------------
__global__ void rope_kernel(__half* __restrict__ q, __half* __restrict__ k,
                            const float* __restrict__ cosb, const float* __restrict__ sinb)
{
    const int halfs_q = BB * TT * HH * (DD / 2);
    const int halfs_k = BB * TT * KVHN * (DD / 2);
    int idx = blockIdx.x * blockDim.x + threadIdx.x;
    if (idx < halfs_q) {
        int d   = idx & 31;
        int h   = (idx >> 5) & (HH - 1);
        int row = idx >> 10;
        int t   = row & (TT - 1);
        __half* p = q + (size_t)row * CC + h * DD;
        float c1 = cosb[t * DD + d],      s1 = sinb[t * DD + d];
        float c2 = cosb[t * DD + d + 32], s2 = sinb[t * DD + d + 32];
        float a = __half2float(p[d]), b2 = __half2float(p[d + 32]);
        p[d]      = __float2half_rn((a * c1 - b2 * s1) * 0.125f);
        p[d + 32] = __float2half_rn((b2 * c2 + a * s2) * 0.125f);
    } else if (idx < halfs_q + halfs_k) {
        int j   = idx - halfs_q;
        int d   = j & 31;
        int h   = (j >> 5) & (KVHN - 1);
        int row = j >> 8;
        int t   = row & (TT - 1);
        __half* p = k + (size_t)row * (KVHN * DD) + h * DD;
        float c1 = cosb[t * DD + d],      s1 = sinb[t * DD + d];
        float c2 = cosb[t * DD + d + 32], s2 = sinb[t * DD + d + 32];
        float a = __half2float(p[d]), b2 = __half2float(p[d + 32]);
        p[d]      = __float2half_rn(a * c1 - b2 * s1);
        p[d + 32] = __float2half_rn(b2 * c2 + a * s2);
    }
}

// ---------------------------------------------------------------------------
// fp16 tensor-core flash attention (unchanged from R10). Causal, GQA, D=64.
// ---------------------------------------------------------------------------
#define FQ 128
#define FK 64
#define FST 72
#define FW_K0  0
#define FW_K1  (64 * FST)
#define FW_V0  (2 * 64 * FST)
#define FW_V1  (3 * 64 * FST)
#define FW_P   (4 * 64 * FST)
#define FLASH_SMEM ((4 * 64 * FST + 128 * FST) * 2)   // 55296 B

__global__ void __launch_bounds__(256, 2)
flash_mma(const __half* __restrict__ Qg, const __half* __restrict__ Kg,
          const __half* __restrict__ VTg, __half* __restrict__ Og)
{
    extern __shared__ float sfraw[];
    __half* sf = (__half*)sfraw;
    const uint32_t sbase = smem_u32(sf);

    const int qt  = (TT / FQ - 1) - blockIdx.x;
    const int h   = blockIdx.y;
    const int b   = blockIdx.z;
    const int kvh = h >> 2;
    const int tid = threadIdx.x;
    const int w   = tid >> 5, lane = tid & 31;
    const int g   = lane >> 2, tig = lane & 3;

    const int lrowA = lane & 15;
    const int lcolA = (lane >> 4) * 16;
    const int lrowB = (lane & 7) + ((lane >> 4) << 3);
    const int lcolB = (lane & 8) ? 16 : 0;

    uint32_t qf[4][4];
    {
        const __half* Qb = Qg + ((size_t)(b * TT + qt * FQ + w * 16)) * CC + h * DD;
#pragma unroll
        for (int ks = 0; ks < 4; ++ks) {
            qf[ks][0] = *(const uint32_t*)(Qb + (size_t)g * CC + ks * 16 + 2 * tig);
            qf[ks][1] = *(const uint32_t*)(Qb + (size_t)(g + 8) * CC + ks * 16 + 2 * tig);
            qf[ks][2] = *(const uint32_t*)(Qb + (size_t)g * CC + ks * 16 + 2 * tig + 8);
            qf[ks][3] = *(const uint32_t*)(Qb + (size_t)(g + 8) * CC + ks * 16 + 2 * tig + 8);
        }
    }

    float oacc[8][4];
#pragma unroll
    for (int nf = 0; nf < 8; ++nf)
#pragma unroll
        for (int e = 0; e < 4; ++e) oacc[nf][e] = 0.f;
    float m0 = -1e30f, m1 = -1e30f, l0 = 0.f, l1 = 0.f;

    const int ktmax = 2 * qt + 1;
    const __half* VTb = VTg + ((size_t)(b * KVHN + kvh)) * DD * TT;

    auto prefetch = [&](int kt, int buf) {
        const __half* Kb = Kg + ((size_t)(b * TT + kt * FK)) * (KVHN * DD) + kvh * DD;
        const uint32_t kd = sbase + (buf ? FW_K1 : FW_K0) * 2u;
        const uint32_t vd = sbase + (buf ? FW_V1 : FW_V0) * 2u;
#pragma unroll
        for (int i = 0; i < 2; ++i) {
            int lin = tid + i * 256;
            int r = lin >> 3, c8 = lin & 7;
            CP16(kd + (uint32_t)(r * FST + c8 * 8) * 2u, Kb + (size_t)r * (KVHN * DD) + c8 * 8);
            CP16(vd + (uint32_t)(r * FST + c8 * 8) * 2u, VTb + (size_t)r * TT + kt * FK + c8 * 8);
        }
        CP_COMMIT();
    };

    prefetch(0, 0);
    __half* Pw = sf + FW_P + w * 16 * FST;
    const uint32_t paddr = sbase + (uint32_t)(FW_P + w * 16 * FST + lrowA * FST) * 2u + lcolA;

    for (int kt = 0; kt <= ktmax; ++kt) {
        const int buf = kt & 1;
        CP_WAIT0();
        __syncthreads();
        if (kt < ktmax) prefetch(kt + 1, buf ^ 1);

        const uint32_t kbase = sbase + (buf ? FW_K1 : FW_K0) * 2u;
        const uint32_t vbase = sbase + (buf ? FW_V1 : FW_V0) * 2u;

        float sacc[8][4];
#pragma unroll
        for (int nf = 0; nf < 8; ++nf)
#pragma unroll
            for (int e = 0; e < 4; ++e) sacc[nf][e] = 0.f;

#pragma unroll
        for (int ks = 0; ks < 4; ++ks) {
            uint32_t b2[4][4];
#pragma unroll
            for (int np = 0; np < 4; ++np)
                LDMX4(b2[np][0], b2[np][1], b2[np][2], b2[np][3],
                      kbase + (uint32_t)((np * 16 + lrowB) * FST) * 2u + lcolB + ks * 32);
#pragma unroll
            for (int nf = 0; nf < 8; ++nf)
                mma_f16(sacc[nf], qf[ks], &b2[nf >> 1][(nf & 1) * 2]);
        }

        if (kt >= 2 * qt) {
            const int q0 = qt * FQ + w * 16 + g;
            const int q1 = q0 + 8;
#pragma unroll
            for (int nf = 0; nf < 8; ++nf) {
                const int key = kt * FK + nf * 8 + tig * 2;
                if (key     > q0) sacc[nf][0] = -1e30f;
                if (key + 1 > q0) sacc[nf][1] = -1e30f;
                if (key     > q1) sacc[nf][2] = -1e30f;
                if (key + 1 > q1) sacc[nf][3] = -1e30f;
            }
        }

        float mx0 = -1e30f, mx1 = -1e30f;
#pragma unroll
        for (int nf = 0; nf < 8; ++nf) {
            mx0 = fmaxf(mx0, fmaxf(sacc[nf][0], sacc[nf][1]));
            mx1 = fmaxf(mx1, fmaxf(sacc[nf][2], sacc[nf][3]));
        }
        mx0 = fmaxf(mx0, __shfl_xor_sync(0xffffffffu, mx0, 1));
        mx0 = fmaxf(mx0, __shfl_xor_sync(0xffffffffu, mx0, 2));
        mx1 = fmaxf(mx1, __shfl_xor_sync(0xffffffffu, mx1, 1));
        mx1 = fmaxf(mx1, __shfl_xor_sync(0xffffffffu, mx1, 2));

        const float mn0 = fmaxf(m0, mx0), mn1 = fmaxf(m1, mx1);
        const float c0 = __expf(m0 - mn0), c1 = __expf(m1 - mn1);
        float s0 = 0.f, s1 = 0.f;
#pragma unroll
        for (int nf = 0; nf < 8; ++nf) {
            sacc[nf][0] = __expf(sacc[nf][0] - mn0);
            sacc[nf][1] = __expf(sacc[nf][1] - mn0);
            sacc[nf][2] = __expf(sacc[nf][2] - mn1);
            sacc[nf][3] = __expf(sacc[nf][3] - mn1);
            s0 += sacc[nf][0] + sacc[nf][1];
            s1 += sacc[nf][2] + sacc[nf][3];
        }
        s0 += __shfl_xor_sync(0xffffffffu, s0, 1);
        s0 += __shfl_xor_sync(0xffffffffu, s0, 2);
        s1 += __shfl_xor_sync(0xffffffffu, s1, 1);
        s1 += __shfl_xor_sync(0xffffffffu, s1, 2);

        l0 = l0 * c0 + s0;  l1 = l1 * c1 + s1;
        m0 = mn0;           m1 = mn1;
#pragma unroll
        for (int nf = 0; nf < 8; ++nf) {
            oacc[nf][0] *= c0; oacc[nf][1] *= c0;
            oacc[nf][2] *= c1; oacc[nf][3] *= c1;
        }

#pragma unroll
        for (int nf = 0; nf < 8; ++nf) {
            *(uint32_t*)(Pw + g * FST + nf * 8 + tig * 2)       = pack_h2(sacc[nf][0], sacc[nf][1]);
            *(uint32_t*)(Pw + (g + 8) * FST + nf * 8 + tig * 2) = pack_h2(sacc[nf][2], sacc[nf][3]);
        }
        __syncwarp();

#pragma unroll
        for (int ks = 0; ks < 4; ++ks) {
            uint32_t pa[4];
            LDMX4(pa[0], pa[1], pa[2], pa[3], paddr + ks * 32);
            uint32_t b2[4][4];
#pragma unroll
            for (int np = 0; np < 4; ++np)
                LDMX4(b2[np][0], b2[np][1], b2[np][2], b2[np][3],
                      vbase + (uint32_t)((np * 16 + lrowB) * FST) * 2u + lcolB + ks * 32);
#pragma unroll
            for (int nf = 0; nf < 8; ++nf)
                mma_f16(oacc[nf], pa, &b2[nf >> 1][(nf & 1) * 2]);
        }
        __syncwarp();
    }

    __half* Ob = Og + ((size_t)(b * TT + qt * FQ + w * 16)) * CC + h * DD;
    const float i0 = 1.0f / l0, i1 = 1.0f / l1;
#pragma unroll
    for (int nf = 0; nf < 8; ++nf) {
        *(uint32_t*)(Ob + (size_t)g * CC + nf * 8 + tig * 2) =
            pack_h2(oacc[nf][0] * i0, oacc[nf][1] * i0);
        *(uint32_t*)(Ob + (size_t)(g + 8) * CC + nf * 8 + tig * 2) =
            pack_h2(oacc[nf][2] * i1, oacc[nf][3] * i1);
    }
}

// ---------------------------------------------------------------------------
extern "C" void kernel_launch(void* const* d_in, const int* in_sizes, int n_in,
                              void* d_out, int out_size)
{
    const float* x    = (const float*)d_in[0];
    const float* Wq   = (const float*)d_in[1];
    const float* Wk   = (const float*)d_in[2];
    const float* Wv   = (const float*)d_in[3];
    const float* Wo   = (const float*)d_in[4];
    const float* cosb = (const float*)d_in[5];
    const float* sinb = (const float*)d_in[6];
    float* out = (float*)d_out;

    __half *q, *k, *v, *vT, *attn, *xt, *wqt, *wkt, *wvt, *wot;
    cudaGetSymbolAddress((void**)&q,    g_q);
    cudaGetSymbolAddress((void**)&k,    g_k);
    cudaGetSymbolAddress((void**)&v,    g_v);
    cudaGetSymbolAddress((void**)&vT,   g_vT);
    cudaGetSymbolAddress((void**)&attn, g_attn);
    cudaGetSymbolAddress((void**)&xt,   g_xt);
    cudaGetSymbolAddress((void**)&wqt,  g_wqt);
    cudaGetSymbolAddress((void**)&wkt,  g_wkt);
    cudaGetSymbolAddress((void**)&wvt,  g_wvt);
    cudaGetSymbolAddress((void**)&wot,  g_wot);

    cudaFuncSetAttribute(gemm_qkv,   cudaFuncAttributeMaxDynamicSharedMemorySize, GEMM_SMEM);
    cudaFuncSetAttribute(gemm_oproj, cudaFuncAttributeMaxDynamicSharedMemorySize, GEMM_SMEM);
    cudaFuncSetAttribute(flash_mma,  cudaFuncAttributeMaxDynamicSharedMemorySize, FLASH_SMEM);

    // fp16 pre-rounding copies (one launch)
    {
        const int total = N4_X + 2 * N4_WQ + 2 * N4_WK;
        round_copy_all<<<(total + 255) / 256, 256>>>(
            (const float4*)x,  (uint2*)xt,
            (const float4*)Wq, (uint2*)wqt,
            (const float4*)Wk, (uint2*)wkt,
            (const float4*)Wv, (uint2*)wvt,
            (const float4*)Wo, (uint2*)wot);
    }

    // QKV projections (fp16 mma, BK=64)
    gemm_qkv<<<dim3(24, 32), 256, GEMM_SMEM>>>(xt, wqt, wkt, wvt, q, k, v);

    // RoPE
    {
        int total = BB * TT * (HH + KVHN) * (DD / 2);
        rope_kernel<<<(total + 255) / 256, 256>>>(q, k, cosb, sinb);
    }

    // V transpose
    vt_kernel<<<dim3(TT / 32, DD / 32, BB * KVHN), dim3(32, 8)>>>(v, vT);

    // Flash attention
    flash_mma<<<dim3(TT / FQ, HH, BB), 256, FLASH_SMEM>>>(q, k, vT, attn);

    // Output projection (fp32 out)
    gemm_oproj<<<dim3(16, 32), 256, GEMM_SMEM>>>(attn, wot, out);
}